// round 3
// baseline (speedup 1.0000x reference)
#include <cuda_runtime.h>
#include <cuda_bf16.h>
#include <cstdint>

// RetNet parallel retention, fused tf32 mma.sync, Q-fragments in registers.
// B=2, H=16, L=2048, DK=DV=128.
namespace {
constexpr int Lc  = 2048;
constexpr int Hc  = 16;
constexpr int Bc  = 2;
constexpr int DKc = 128;
constexpr int DVc = 128;
constexpr int BM  = 64;
constexpr int BN  = 64;
constexpr int KS_STRIDE = 132;
constexpr int VS_STRIDE = 136;
constexpr int SS_STRIDE = 72;
constexpr int NTHREADS  = 256;

// smem (floats): Ks[64][132] | Vs[64][136] | Ss[64][72] | Cs[64] | RSs[64] | SQs[64]
constexpr int SMEM_FLOATS = BN * KS_STRIDE + BN * VS_STRIDE + BM * SS_STRIDE + 3 * 64;
}

__device__ __forceinline__ float f2tf32f(float x) {
    uint32_t r;
    asm("cvt.rna.tf32.f32 %0, %1;" : "=r"(r) : "f"(x));
    return __uint_as_float(r);
}

__device__ __forceinline__ void mma_tf32(float c[4],
                                         uint32_t a0, uint32_t a1, uint32_t a2, uint32_t a3,
                                         uint32_t b0, uint32_t b1) {
    asm volatile(
        "mma.sync.aligned.m16n8k8.row.col.f32.tf32.tf32.f32 "
        "{%0,%1,%2,%3}, {%4,%5,%6,%7}, {%8,%9}, {%0,%1,%2,%3};\n"
        : "+f"(c[0]), "+f"(c[1]), "+f"(c[2]), "+f"(c[3])
        : "r"(a0), "r"(a1), "r"(a2), "r"(a3), "r"(b0), "r"(b1));
}

#define F2U __float_as_uint

__global__ __launch_bounds__(NTHREADS, 2)
void retnet_mma_kernel(const float* __restrict__ q,
                       const float* __restrict__ k,
                       const float* __restrict__ v,
                       float* __restrict__ out)
{
    extern __shared__ float sm[];
    float* Ks  = sm;                        // [BN][132] tf32, raw K
    float* Vs  = Ks  + BN * KS_STRIDE;      // [BN][136] tf32
    float* Ss  = Vs  + BN * VS_STRIDE;      // [BM][72]  tf32 decayed scores
    float* Cs  = Ss  + BM * SS_STRIDE;      // [64] gamma^{-j_local}
    float* RSs = Cs  + 64;                  // [BM]
    float* SQs = RSs + 64;                  // [BM]

    const int tid  = threadIdx.x;
    const int lane = tid & 31;
    const int warp = tid >> 5;
    const int wm   = warp >> 1;   // 0..3
    const int wn   = warp & 1;    // 0..1
    const int lr   = lane >> 2;   // 0..7
    const int lc   = lane & 3;    // 0..3

    const int bh = blockIdx.y;
    const int b  = bh >> 4;
    const int h  = bh & 15;
    const int m_block = (int)(gridDim.x - 1) - (int)blockIdx.x;  // heavy first
    const int i0 = m_block * BM;

    const float* qb = q + (size_t)bh * Lc * DKc;
    const float* kb = k + (size_t)bh * Lc * DKc;
    const float* vb = v + (size_t)bh * Lc * DVc;

    // log2(gamma_h), gamma = 1 - 2^{-5-h}
    const float lg2 = log1pf(-exp2f(-5.0f - (float)h)) * 1.4426950408889634f;

    // column decay LUT: Cs[j] = gamma^{-j}
    if (tid < 64) Cs[tid] = exp2f(-lg2 * (float)tid);

    const int il0 = wm * 16 + lr;
    const int il1 = il0 + 8;

    // ---- stage Q (tf32) through Vs, then pull mma A-fragments into registers ----
    #pragma unroll
    for (int t = 0; t < (BM * DKc / 4) / NTHREADS; t++) {
        int idx = tid + t * NTHREADS;
        int r   = idx >> 5;
        int c4  = idx & 31;
        float4 g = *(const float4*)(qb + (size_t)(i0 + r) * DKc + c4 * 4);
        float4 o;
        o.x = f2tf32f(g.x); o.y = f2tf32f(g.y);
        o.z = f2tf32f(g.z); o.w = f2tf32f(g.w);
        *(float4*)(Vs + r * VS_STRIDE + c4 * 4) = o;
    }
    __syncthreads();

    uint32_t qa[16][4];
    #pragma unroll
    for (int ks = 0; ks < 16; ks++) {
        const int kk = ks * 8;
        qa[ks][0] = F2U(Vs[il0 * VS_STRIDE + kk + lc]);
        qa[ks][1] = F2U(Vs[il1 * VS_STRIDE + kk + lc]);
        qa[ks][2] = F2U(Vs[il0 * VS_STRIDE + kk + lc + 4]);
        qa[ks][3] = F2U(Vs[il1 * VS_STRIDE + kk + lc + 4]);
    }
    __syncthreads();

    float oc[8][4];
    #pragma unroll
    for (int t = 0; t < 8; t++)
        #pragma unroll
        for (int e = 0; e < 4; e++) oc[t][e] = 0.0f;

    float rs0 = 0.0f, rs1 = 0.0f;

    float R0 = exp2f(lg2 * (float)il0);
    float R1 = exp2f(lg2 * (float)il1);
    const float gstep = exp2f(lg2 * (float)BN);

    for (int j0 = i0; j0 >= 0; j0 -= BN) {
        // ---- stage K (raw) and V, tf32 ----
        #pragma unroll
        for (int t = 0; t < (BN * DKc / 4) / NTHREADS; t++) {
            int idx = tid + t * NTHREADS;
            int r   = idx >> 5;
            int c4  = idx & 31;
            float4 g = *(const float4*)(kb + (size_t)(j0 + r) * DKc + c4 * 4);
            float4 o;
            o.x = f2tf32f(g.x); o.y = f2tf32f(g.y);
            o.z = f2tf32f(g.z); o.w = f2tf32f(g.w);
            *(float4*)(Ks + r * KS_STRIDE + c4 * 4) = o;
        }
        #pragma unroll
        for (int t = 0; t < (BN * DVc / 4) / NTHREADS; t++) {
            int idx = tid + t * NTHREADS;
            int r   = idx >> 5;
            int c4  = idx & 31;
            float4 g = *(const float4*)(vb + (size_t)(j0 + r) * DVc + c4 * 4);
            float4 o;
            o.x = f2tf32f(g.x); o.y = f2tf32f(g.y);
            o.z = f2tf32f(g.z); o.w = f2tf32f(g.w);
            *(float4*)(Vs + r * VS_STRIDE + c4 * 4) = o;
        }
        __syncthreads();

        // ---- GEMM1: S(64x64) = Q K^T (raw scores) ----
        float sc[4][4];
        #pragma unroll
        for (int t = 0; t < 4; t++)
            #pragma unroll
            for (int e = 0; e < 4; e++) sc[t][e] = 0.0f;

        #pragma unroll
        for (int ks = 0; ks < DKc / 8; ks++) {
            const int kk = ks * 8;
            #pragma unroll
            for (int t = 0; t < 4; t++) {
                const int n = wn * 32 + t * 8;
                uint32_t b0 = F2U(Ks[(n + lr) * KS_STRIDE + kk + lc]);
                uint32_t b1 = F2U(Ks[(n + lr) * KS_STRIDE + kk + lc + 4]);
                mma_tf32(sc[t], qa[ks][0], qa[ks][1], qa[ks][2], qa[ks][3], b0, b1);
            }
        }

        // ---- decay (row factor R, column LUT Cs) + causal mask + rowsum, stage S ----
        const bool diag = (j0 == i0);
        #pragma unroll
        for (int t = 0; t < 4; t++) {
            const int jb = wn * 32 + t * 8 + 2 * lc;
            const float c0 = Cs[jb];
            const float c1 = Cs[jb + 1];
            float v0 = sc[t][0] * R0 * c0;
            float v1 = sc[t][1] * R0 * c1;
            float v2 = sc[t][2] * R1 * c0;
            float v3 = sc[t][3] * R1 * c1;
            if (diag) {
                if (jb     > il0) v0 = 0.0f;
                if (jb + 1 > il0) v1 = 0.0f;
                if (jb     > il1) v2 = 0.0f;
                if (jb + 1 > il1) v3 = 0.0f;
            }
            rs0 += v0 + v1;
            rs1 += v2 + v3;
            Ss[il0 * SS_STRIDE + jb]     = f2tf32f(v0);
            Ss[il0 * SS_STRIDE + jb + 1] = f2tf32f(v1);
            Ss[il1 * SS_STRIDE + jb]     = f2tf32f(v2);
            Ss[il1 * SS_STRIDE + jb + 1] = f2tf32f(v3);
        }
        R0 *= gstep;
        R1 *= gstep;
        __syncthreads();

        // ---- GEMM2: O(64x128) += S @ V ----
        #pragma unroll
        for (int ks = 0; ks < BN / 8; ks++) {
            const int kk = ks * 8;
            uint32_t a0 = F2U(Ss[il0 * SS_STRIDE + kk + lc]);
            uint32_t a1 = F2U(Ss[il1 * SS_STRIDE + kk + lc]);
            uint32_t a2 = F2U(Ss[il0 * SS_STRIDE + kk + lc + 4]);
            uint32_t a3 = F2U(Ss[il1 * SS_STRIDE + kk + lc + 4]);
            #pragma unroll
            for (int t = 0; t < 8; t++) {
                const int n = wn * 64 + t * 8;
                uint32_t b0 = F2U(Vs[(kk + lc) * VS_STRIDE + n + lr]);
                uint32_t b1 = F2U(Vs[(kk + lc + 4) * VS_STRIDE + n + lr]);
                mma_tf32(oc[t], a0, a1, a2, a3, b0, b1);
            }
        }
        __syncthreads();   // before next iteration overwrites Ks/Vs/Ss
    }

    // ---- rowsum reduce: lane quad, then across wn halves ----
    rs0 += __shfl_xor_sync(0xffffffffu, rs0, 1);
    rs0 += __shfl_xor_sync(0xffffffffu, rs0, 2);
    rs1 += __shfl_xor_sync(0xffffffffu, rs1, 1);
    rs1 += __shfl_xor_sync(0xffffffffu, rs1, 2);

    if (wn == 0 && lc == 0) { RSs[il0] = rs0; RSs[il1] = rs1; }
    __syncthreads();
    if (wn == 1 && lc == 0) { RSs[il0] += rs0; RSs[il1] += rs1; }
    __syncthreads();

    const float dn0 = 1.0f / fmaxf(fabsf(RSs[il0]), 1.0f);
    const float dn1 = 1.0f / fmaxf(fabsf(RSs[il1]), 1.0f);

    float ssq0 = 0.0f, ssq1 = 0.0f;
    #pragma unroll
    for (int t = 0; t < 8; t++) {
        oc[t][0] *= dn0; oc[t][1] *= dn0;
        oc[t][2] *= dn1; oc[t][3] *= dn1;
        ssq0 += oc[t][0] * oc[t][0] + oc[t][1] * oc[t][1];
        ssq1 += oc[t][2] * oc[t][2] + oc[t][3] * oc[t][3];
    }
    ssq0 += __shfl_xor_sync(0xffffffffu, ssq0, 1);
    ssq0 += __shfl_xor_sync(0xffffffffu, ssq0, 2);
    ssq1 += __shfl_xor_sync(0xffffffffu, ssq1, 1);
    ssq1 += __shfl_xor_sync(0xffffffffu, ssq1, 2);

    if (wn == 0 && lc == 0) { SQs[il0] = ssq0; SQs[il1] = ssq1; }
    __syncthreads();
    if (wn == 1 && lc == 0) { SQs[il0] += ssq0; SQs[il1] += ssq1; }
    __syncthreads();

    const float sc0 = rsqrtf(SQs[il0] * (1.0f / (float)DVc) + 1e-6f);
    const float sc1 = rsqrtf(SQs[il1] * (1.0f / (float)DVc) + 1e-6f);

    const int gi0 = i0 + il0;
    const int gi1 = i0 + il1;
    float* po0 = out + (((size_t)b * Lc + gi0) * Hc + h) * DVc;
    float* po1 = out + (((size_t)b * Lc + gi1) * Hc + h) * DVc;
    #pragma unroll
    for (int t = 0; t < 8; t++) {
        const int d = wn * 64 + t * 8 + 2 * lc;
        float2 w0, w1;
        w0.x = oc[t][0] * sc0; w0.y = oc[t][1] * sc0;
        w1.x = oc[t][2] * sc1; w1.y = oc[t][3] * sc1;
        *(float2*)(po0 + d) = w0;
        *(float2*)(po1 + d) = w1;
    }
}

extern "C" void kernel_launch(void* const* d_in, const int* in_sizes, int n_in,
                              void* d_out, int out_size)
{
    const float* q = (const float*)d_in[0];
    const float* k = (const float*)d_in[1];
    const float* v = (const float*)d_in[2];
    float* out = (float*)d_out;

    const size_t smem_bytes = (size_t)SMEM_FLOATS * sizeof(float);
    cudaFuncSetAttribute(retnet_mma_kernel,
                         cudaFuncAttributeMaxDynamicSharedMemorySize,
                         (int)smem_bytes);

    dim3 grid(Lc / BM, Bc * Hc);   // (32, 32)
    retnet_mma_kernel<<<grid, NTHREADS, smem_bytes>>>(q, k, v, out);
}

// round 4
// speedup vs baseline: 1.1753x; 1.1753x over previous
#include <cuda_runtime.h>
#include <cuda_bf16.h>
#include <cstdint>

// RetNet parallel retention, fused tf32 mma.sync.
// R4: Q fragments in regs, K in pre-swizzled fragment layout (LDS.128),
//     double-buffered pipelined K/V staging, 2 barriers/iter, 1 CTA/SM.
namespace {
constexpr int Lc  = 2048;
constexpr int Hc  = 16;
constexpr int Bc  = 2;
constexpr int DKc = 128;
constexpr int DVc = 128;
constexpr int BM  = 64;
constexpr int BN  = 64;
constexpr int KF_BLK   = 132;            // floats per (n-tile, k-pair) fragment block
constexpr int KF_SIZE  = 64 * KF_BLK;    // 8 n-tiles x 8 k-pairs
constexpr int VS_STRIDE = 136;
constexpr int SS_STRIDE = 72;
constexpr int NTHREADS  = 256;

// smem (floats): KsF[2][KF_SIZE] | Vs[2][64][136] | Ss[64][72] | Cs[64] | RSs[64] | SQs[64]
constexpr int SMEM_FLOATS = 2 * KF_SIZE + 2 * BN * VS_STRIDE + BM * SS_STRIDE + 3 * 64;
}

__device__ __forceinline__ float f2tf32f(float x) {
    uint32_t r;
    asm("cvt.rna.tf32.f32 %0, %1;" : "=r"(r) : "f"(x));
    return __uint_as_float(r);
}

__device__ __forceinline__ void mma_tf32(float c[4],
                                         uint32_t a0, uint32_t a1, uint32_t a2, uint32_t a3,
                                         uint32_t b0, uint32_t b1) {
    asm volatile(
        "mma.sync.aligned.m16n8k8.row.col.f32.tf32.tf32.f32 "
        "{%0,%1,%2,%3}, {%4,%5,%6,%7}, {%8,%9}, {%0,%1,%2,%3};\n"
        : "+f"(c[0]), "+f"(c[1]), "+f"(c[2]), "+f"(c[3])
        : "r"(a0), "r"(a1), "r"(a2), "r"(a3), "r"(b0), "r"(b1));
}

#define F2U __float_as_uint

__global__ __launch_bounds__(NTHREADS, 1)
void retnet_mma_kernel(const float* __restrict__ q,
                       const float* __restrict__ k,
                       const float* __restrict__ v,
                       float* __restrict__ out)
{
    extern __shared__ float sm[];
    float* KsF = sm;                         // [2][KF_SIZE] K in mma-B fragment layout
    float* Vs  = KsF + 2 * KF_SIZE;          // [2][64][136]
    float* Ss  = Vs  + 2 * BN * VS_STRIDE;   // [64][72] decayed scores
    float* Cs  = Ss  + BM * SS_STRIDE;       // [64] gamma^{-j}
    float* RSs = Cs  + 64;
    float* SQs = RSs + 64;

    const int tid  = threadIdx.x;
    const int lane = tid & 31;
    const int warp = tid >> 5;
    const int wm   = warp >> 1;   // 0..3
    const int wn   = warp & 1;    // 0..1
    const int lr   = lane >> 2;   // 0..7
    const int lc   = lane & 3;    // 0..3

    const int bh = blockIdx.y;
    const int b  = bh >> 4;
    const int h  = bh & 15;
    const int m_block = (int)(gridDim.x - 1) - (int)blockIdx.x;  // heavy first
    const int i0 = m_block * BM;

    const float* qb = q + (size_t)bh * Lc * DKc;
    const float* kb = k + (size_t)bh * Lc * DKc;
    const float* vb = v + (size_t)bh * Lc * DVc;

    const float lg2 = log1pf(-exp2f(-5.0f - (float)h)) * 1.4426950408889634f;
    if (tid < 64) Cs[tid] = exp2f(-lg2 * (float)tid);

    const int il0 = wm * 16 + lr;
    const int il1 = il0 + 8;

    // ---- stage Q through Vs[0], pull A-fragments into registers ----
    #pragma unroll
    for (int t = 0; t < 8; t++) {
        int idx = tid + t * NTHREADS;
        int r   = idx >> 5;
        int c4  = idx & 31;
        float4 g = *(const float4*)(qb + (size_t)(i0 + r) * DKc + c4 * 4);
        float4 o;
        o.x = f2tf32f(g.x); o.y = f2tf32f(g.y);
        o.z = f2tf32f(g.z); o.w = f2tf32f(g.w);
        *(float4*)(Vs + r * VS_STRIDE + c4 * 4) = o;
    }
    __syncthreads();

    uint32_t qa[16][4];
    #pragma unroll
    for (int ks = 0; ks < 16; ks++) {
        const int kk = ks * 8;
        qa[ks][0] = F2U(Vs[il0 * VS_STRIDE + kk + lc]);
        qa[ks][1] = F2U(Vs[il1 * VS_STRIDE + kk + lc]);
        qa[ks][2] = F2U(Vs[il0 * VS_STRIDE + kk + lc + 4]);
        qa[ks][3] = F2U(Vs[il1 * VS_STRIDE + kk + lc + 4]);
    }
    __syncthreads();

    // per-thread staging coordinates (fixed)
    const int sn = tid >> 5;        // base row (0..7), +8 per t-step via idx
    const int sc4 = tid & 31;       // col4 index
    (void)sn;

    // ---- stage tile 0 (K fragments + V rows) directly ----
    {
        const int j0 = i0;
        #pragma unroll
        for (int t = 0; t < 8; t++) {
            int idx = tid + t * NTHREADS;
            int n   = idx >> 5;
            int c   = idx & 31;
            float4 g = *(const float4*)(kb + (size_t)(j0 + n) * DKc + c * 4);
            float* dst = KsF + ((n >> 3) * 8 + (c >> 2)) * KF_BLK + (n & 7) * 16 + (c & 3);
            dst[0]  = f2tf32f(g.x);
            dst[4]  = f2tf32f(g.y);
            dst[8]  = f2tf32f(g.z);
            dst[12] = f2tf32f(g.w);
        }
        #pragma unroll
        for (int t = 0; t < 8; t++) {
            int idx = tid + t * NTHREADS;
            int n   = idx >> 5;
            int c   = idx & 31;
            float4 g = *(const float4*)(vb + (size_t)(j0 + n) * DVc + c * 4);
            float4 o;
            o.x = f2tf32f(g.x); o.y = f2tf32f(g.y);
            o.z = f2tf32f(g.z); o.w = f2tf32f(g.w);
            *(float4*)(Vs + n * VS_STRIDE + c * 4) = o;
        }
    }
    __syncthreads();

    float oc[8][4];
    #pragma unroll
    for (int t = 0; t < 8; t++)
        #pragma unroll
        for (int e = 0; e < 4; e++) oc[t][e] = 0.0f;

    float rs0 = 0.0f, rs1 = 0.0f;
    float R0 = exp2f(lg2 * (float)il0);
    float R1 = exp2f(lg2 * (float)il1);
    const float gstep = exp2f(lg2 * (float)BN);

    int buf = 0;
    for (int j0 = i0; j0 >= 0; j0 -= BN) {
        const bool haveNext = (j0 - BN) >= 0;
        const float* KB = KsF + buf * KF_SIZE;
        const float* VB = Vs  + buf * BN * VS_STRIDE;

        // ---- prefetch next tile into registers (LDG overlapped with GEMM1) ----
        float4 kpref[8], vpref[8];
        if (haveNext) {
            const int jn = j0 - BN;
            #pragma unroll
            for (int t = 0; t < 8; t++) {
                int idx = tid + t * NTHREADS;
                int n   = idx >> 5;
                int c   = idx & 31;
                kpref[t] = *(const float4*)(kb + (size_t)(jn + n) * DKc + c * 4);
                vpref[t] = *(const float4*)(vb + (size_t)(jn + n) * DVc + c * 4);
            }
        }

        // ---- GEMM1: S(64x64) = Q K^T, B-fragments via LDS.128 ----
        float scr[4][4];
        #pragma unroll
        for (int t = 0; t < 4; t++)
            #pragma unroll
            for (int e = 0; e < 4; e++) scr[t][e] = 0.0f;

        #pragma unroll
        for (int p = 0; p < 8; p++) {
            #pragma unroll
            for (int t = 0; t < 4; t++) {
                const float4 bf = *(const float4*)(KB + ((wn * 4 + t) * 8 + p) * KF_BLK + lane * 4);
                mma_tf32(scr[t], qa[2*p][0],   qa[2*p][1],   qa[2*p][2],   qa[2*p][3],
                         F2U(bf.x), F2U(bf.y));
                mma_tf32(scr[t], qa[2*p+1][0], qa[2*p+1][1], qa[2*p+1][2], qa[2*p+1][3],
                         F2U(bf.z), F2U(bf.w));
            }
        }

        // ---- store prefetched tile into the other buffer ----
        if (haveNext) {
            float* KN = KsF + (buf ^ 1) * KF_SIZE;
            float* VN = Vs  + (buf ^ 1) * BN * VS_STRIDE;
            #pragma unroll
            for (int t = 0; t < 8; t++) {
                int idx = tid + t * NTHREADS;
                int n   = idx >> 5;
                int c   = idx & 31;
                float* dst = KN + ((n >> 3) * 8 + (c >> 2)) * KF_BLK + (n & 7) * 16 + (c & 3);
                dst[0]  = f2tf32f(kpref[t].x);
                dst[4]  = f2tf32f(kpref[t].y);
                dst[8]  = f2tf32f(kpref[t].z);
                dst[12] = f2tf32f(kpref[t].w);
                float4 o;
                o.x = f2tf32f(vpref[t].x); o.y = f2tf32f(vpref[t].y);
                o.z = f2tf32f(vpref[t].z); o.w = f2tf32f(vpref[t].w);
                *(float4*)(VN + n * VS_STRIDE + c * 4) = o;
            }
        }

        // ---- decay + causal mask + rowsum, stage S ----
        const bool diag = (j0 == i0);
        #pragma unroll
        for (int t = 0; t < 4; t++) {
            const int jb = wn * 32 + t * 8 + 2 * lc;
            const float c0 = Cs[jb];
            const float c1 = Cs[jb + 1];
            float v0 = scr[t][0] * R0 * c0;
            float v1 = scr[t][1] * R0 * c1;
            float v2 = scr[t][2] * R1 * c0;
            float v3 = scr[t][3] * R1 * c1;
            if (diag) {
                if (jb     > il0) v0 = 0.0f;
                if (jb + 1 > il0) v1 = 0.0f;
                if (jb     > il1) v2 = 0.0f;
                if (jb + 1 > il1) v3 = 0.0f;
            }
            rs0 += v0 + v1;
            rs1 += v2 + v3;
            Ss[il0 * SS_STRIDE + jb]     = f2tf32f(v0);
            Ss[il0 * SS_STRIDE + jb + 1] = f2tf32f(v1);
            Ss[il1 * SS_STRIDE + jb]     = f2tf32f(v2);
            Ss[il1 * SS_STRIDE + jb + 1] = f2tf32f(v3);
        }
        R0 *= gstep;
        R1 *= gstep;
        __syncthreads();   // S visible; staged next tile visible

        // ---- GEMM2: O(64x128) += S @ V ----
        #pragma unroll
        for (int ks = 0; ks < BN / 8; ks++) {
            const int kk = ks * 8;
            uint32_t a0 = F2U(Ss[il0 * SS_STRIDE + kk + lc]);
            uint32_t a1 = F2U(Ss[il1 * SS_STRIDE + kk + lc]);
            uint32_t a2 = F2U(Ss[il0 * SS_STRIDE + kk + lc + 4]);
            uint32_t a3 = F2U(Ss[il1 * SS_STRIDE + kk + lc + 4]);
            #pragma unroll
            for (int t = 0; t < 8; t++) {
                const int n = wn * 64 + t * 8;
                uint32_t b0 = F2U(VB[(kk + lc) * VS_STRIDE + n + lr]);
                uint32_t b1 = F2U(VB[(kk + lc + 4) * VS_STRIDE + n + lr]);
                mma_tf32(oc[t], a0, a1, a2, a3, b0, b1);
            }
        }
        __syncthreads();   // all reads of current buffers + Ss done

        buf ^= 1;
    }

    // ---- rowsum reduce ----
    rs0 += __shfl_xor_sync(0xffffffffu, rs0, 1);
    rs0 += __shfl_xor_sync(0xffffffffu, rs0, 2);
    rs1 += __shfl_xor_sync(0xffffffffu, rs1, 1);
    rs1 += __shfl_xor_sync(0xffffffffu, rs1, 2);

    if (wn == 0 && lc == 0) { RSs[il0] = rs0; RSs[il1] = rs1; }
    __syncthreads();
    if (wn == 1 && lc == 0) { RSs[il0] += rs0; RSs[il1] += rs1; }
    __syncthreads();

    const float dn0 = 1.0f / fmaxf(fabsf(RSs[il0]), 1.0f);
    const float dn1 = 1.0f / fmaxf(fabsf(RSs[il1]), 1.0f);

    float ssq0 = 0.0f, ssq1 = 0.0f;
    #pragma unroll
    for (int t = 0; t < 8; t++) {
        oc[t][0] *= dn0; oc[t][1] *= dn0;
        oc[t][2] *= dn1; oc[t][3] *= dn1;
        ssq0 += oc[t][0] * oc[t][0] + oc[t][1] * oc[t][1];
        ssq1 += oc[t][2] * oc[t][2] + oc[t][3] * oc[t][3];
    }
    ssq0 += __shfl_xor_sync(0xffffffffu, ssq0, 1);
    ssq0 += __shfl_xor_sync(0xffffffffu, ssq0, 2);
    ssq1 += __shfl_xor_sync(0xffffffffu, ssq1, 1);
    ssq1 += __shfl_xor_sync(0xffffffffu, ssq1, 2);

    if (wn == 0 && lc == 0) { SQs[il0] = ssq0; SQs[il1] = ssq1; }
    __syncthreads();
    if (wn == 1 && lc == 0) { SQs[il0] += ssq0; SQs[il1] += ssq1; }
    __syncthreads();

    const float sc0 = rsqrtf(SQs[il0] * (1.0f / (float)DVc) + 1e-6f);
    const float sc1 = rsqrtf(SQs[il1] * (1.0f / (float)DVc) + 1e-6f);

    const int gi0 = i0 + il0;
    const int gi1 = i0 + il1;
    float* po0 = out + (((size_t)b * Lc + gi0) * Hc + h) * DVc;
    float* po1 = out + (((size_t)b * Lc + gi1) * Hc + h) * DVc;
    #pragma unroll
    for (int t = 0; t < 8; t++) {
        const int d = wn * 64 + t * 8 + 2 * lc;
        float2 w0, w1;
        w0.x = oc[t][0] * sc0; w0.y = oc[t][1] * sc0;
        w1.x = oc[t][2] * sc1; w1.y = oc[t][3] * sc1;
        *(float2*)(po0 + d) = w0;
        *(float2*)(po1 + d) = w1;
    }
}

extern "C" void kernel_launch(void* const* d_in, const int* in_sizes, int n_in,
                              void* d_out, int out_size)
{
    const float* q = (const float*)d_in[0];
    const float* k = (const float*)d_in[1];
    const float* v = (const float*)d_in[2];
    float* out = (float*)d_out;

    const size_t smem_bytes = (size_t)SMEM_FLOATS * sizeof(float);
    cudaFuncSetAttribute(retnet_mma_kernel,
                         cudaFuncAttributeMaxDynamicSharedMemorySize,
                         (int)smem_bytes);

    dim3 grid(Lc / BM, Bc * Hc);   // (32, 32)
    retnet_mma_kernel<<<grid, NTHREADS, smem_bytes>>>(q, k, v, out);
}

// round 5
// speedup vs baseline: 1.9646x; 1.6716x over previous
#include <cuda_runtime.h>
#include <cuda_fp16.h>
#include <cstdint>

// RetNet parallel retention, fused fp16 mma.sync m16n8k16 + ldmatrix.
// R5: tf32 -> fp16 (same 10-bit mantissa), halves LDS bytes and tensor cycles.
// B=2, H=16, L=2048, DK=DV=128.
namespace {
constexpr int Lc  = 2048;
constexpr int Hc  = 16;
constexpr int Bc  = 2;
constexpr int DKc = 128;
constexpr int DVc = 128;
constexpr int BM  = 64;
constexpr int BN  = 64;
constexpr int KV_STRIDE = 136;   // halves per row (272B, +4 banks/row -> ldsm conflict-free)
constexpr int S_STRIDE  = 72;    // halves per row (144B)
constexpr int NTHREADS  = 256;
constexpr int KV_TILE_H = 64 * KV_STRIDE;   // halves per K or V tile buffer

// smem: KsH[2][tile] VsH[2][tile] SsH[64][72] (half) + Cs/RSs/SQs (float)
constexpr size_t SMEM_BYTES =
    (size_t)(4 * KV_TILE_H + 64 * S_STRIDE) * 2 + 3 * 64 * 4;
}

__device__ __forceinline__ void ldsm4(uint32_t& r0, uint32_t& r1, uint32_t& r2, uint32_t& r3,
                                      uint32_t addr) {
    asm volatile("ldmatrix.sync.aligned.m8n8.x4.shared.b16 {%0,%1,%2,%3}, [%4];"
                 : "=r"(r0), "=r"(r1), "=r"(r2), "=r"(r3) : "r"(addr));
}
__device__ __forceinline__ void ldsm4t(uint32_t& r0, uint32_t& r1, uint32_t& r2, uint32_t& r3,
                                       uint32_t addr) {
    asm volatile("ldmatrix.sync.aligned.m8n8.x4.trans.shared.b16 {%0,%1,%2,%3}, [%4];"
                 : "=r"(r0), "=r"(r1), "=r"(r2), "=r"(r3) : "r"(addr));
}
__device__ __forceinline__ void mma_f16(float c[4],
                                        uint32_t a0, uint32_t a1, uint32_t a2, uint32_t a3,
                                        uint32_t b0, uint32_t b1) {
    asm volatile(
        "mma.sync.aligned.m16n8k16.row.col.f32.f16.f16.f32 "
        "{%0,%1,%2,%3}, {%4,%5,%6,%7}, {%8,%9}, {%0,%1,%2,%3};\n"
        : "+f"(c[0]), "+f"(c[1]), "+f"(c[2]), "+f"(c[3])
        : "r"(a0), "r"(a1), "r"(a2), "r"(a3), "r"(b0), "r"(b1));
}

__device__ __forceinline__ uint32_t h2bits(__half2 h) {
    return *reinterpret_cast<uint32_t*>(&h);
}

__global__ __launch_bounds__(NTHREADS, 1)
void retnet_f16_kernel(const float* __restrict__ q,
                       const float* __restrict__ k,
                       const float* __restrict__ v,
                       float* __restrict__ out)
{
    extern __shared__ __align__(16) char smraw[];
    __half* KsH = reinterpret_cast<__half*>(smraw);          // [2][64][136]
    __half* VsH = KsH + 2 * KV_TILE_H;                       // [2][64][136]
    __half* SsH = VsH + 2 * KV_TILE_H;                       // [64][72]
    float*  Cs  = reinterpret_cast<float*>(SsH + 64 * S_STRIDE);  // [64]
    float*  RSs = Cs + 64;
    float*  SQs = RSs + 64;

    const uint32_t KsU = (uint32_t)__cvta_generic_to_shared(KsH);
    const uint32_t VsU = (uint32_t)__cvta_generic_to_shared(VsH);
    const uint32_t SsU = (uint32_t)__cvta_generic_to_shared(SsH);
    constexpr uint32_t KV_TILE_BYTES = KV_TILE_H * 2;

    const int tid  = threadIdx.x;
    const int lane = tid & 31;
    const int warp = tid >> 5;
    const int wm   = warp >> 1;   // 0..3 row group (16 rows)
    const int wn   = warp & 1;    // 0..1 col half
    const int lr   = lane >> 2;
    const int lc   = lane & 3;

    // ldmatrix per-lane offsets
    const int l7 = lane & 7;
    const int g  = lane >> 3;
    const int a_row  = l7 + (g & 1) * 8;   // A-pattern (Q, S) and V-trans rows
    const int a_col8 = (g >> 1) * 8;
    const int kb_row  = l7 + (g >> 1) * 8; // K B-pattern
    const int kb_col8 = (g & 1) * 8;

    const int bh = blockIdx.y;
    const int b  = bh >> 4;
    const int h  = bh & 15;
    const int m_block = (int)(gridDim.x - 1) - (int)blockIdx.x;  // heavy first
    const int i0 = m_block * BM;

    const float* qb = q + (size_t)bh * Lc * DKc;
    const float* kb = k + (size_t)bh * Lc * DKc;
    const float* vb = v + (size_t)bh * Lc * DVc;

    const float lg2 = log1pf(-exp2f(-5.0f - (float)h)) * 1.4426950408889634f;
    if (tid < 64) Cs[tid] = exp2f(-lg2 * (float)tid);

    const int il0 = wm * 16 + lr;
    const int il1 = il0 + 8;

    // ---- stage Q (half) into K buffer 0, pull A-fragments via ldsm ----
    #pragma unroll
    for (int t = 0; t < 8; t++) {
        int idx = tid + t * NTHREADS;
        int r   = idx >> 5;
        int c   = idx & 31;
        float4 gld = *(const float4*)(qb + (size_t)(i0 + r) * DKc + c * 4);
        __half2 h0 = __floats2half2_rn(gld.x, gld.y);
        __half2 h1 = __floats2half2_rn(gld.z, gld.w);
        uint2 u; u.x = h2bits(h0); u.y = h2bits(h1);
        *(uint2*)(KsH + r * KV_STRIDE + c * 4) = u;
    }
    __syncthreads();

    uint32_t qa[8][4];
    #pragma unroll
    for (int kt = 0; kt < 8; kt++) {
        uint32_t addr = KsU + ((wm * 16 + a_row) * KV_STRIDE + kt * 16 + a_col8) * 2;
        ldsm4(qa[kt][0], qa[kt][1], qa[kt][2], qa[kt][3], addr);
    }
    __syncthreads();

    // ---- stage tile 0 (K + V, half) ----
    #pragma unroll
    for (int t = 0; t < 8; t++) {
        int idx = tid + t * NTHREADS;
        int r   = idx >> 5;
        int c   = idx & 31;
        float4 gk = *(const float4*)(kb + (size_t)(i0 + r) * DKc + c * 4);
        __half2 k0 = __floats2half2_rn(gk.x, gk.y);
        __half2 k1 = __floats2half2_rn(gk.z, gk.w);
        uint2 uk; uk.x = h2bits(k0); uk.y = h2bits(k1);
        *(uint2*)(KsH + r * KV_STRIDE + c * 4) = uk;
        float4 gv = *(const float4*)(vb + (size_t)(i0 + r) * DVc + c * 4);
        __half2 v0 = __floats2half2_rn(gv.x, gv.y);
        __half2 v1 = __floats2half2_rn(gv.z, gv.w);
        uint2 uv; uv.x = h2bits(v0); uv.y = h2bits(v1);
        *(uint2*)(VsH + r * KV_STRIDE + c * 4) = uv;
    }
    __syncthreads();

    float oc[8][4];
    #pragma unroll
    for (int t = 0; t < 8; t++)
        #pragma unroll
        for (int e = 0; e < 4; e++) oc[t][e] = 0.0f;

    float rs0 = 0.0f, rs1 = 0.0f;
    float R0 = exp2f(lg2 * (float)il0);
    float R1 = exp2f(lg2 * (float)il1);
    const float gstep = exp2f(lg2 * (float)BN);

    int buf = 0;
    for (int j0 = i0; j0 >= 0; j0 -= BN) {
        const bool haveNext = (j0 - BN) >= 0;
        const uint32_t KB = KsU + buf * KV_TILE_BYTES;
        const uint32_t VB = VsU + buf * KV_TILE_BYTES;

        // ---- prefetch next tile into registers (overlap LDG with GEMM1) ----
        float4 kpref[8], vpref[8];
        if (haveNext) {
            const int jn = j0 - BN;
            #pragma unroll
            for (int t = 0; t < 8; t++) {
                int idx = tid + t * NTHREADS;
                int n   = idx >> 5;
                int c   = idx & 31;
                kpref[t] = *(const float4*)(kb + (size_t)(jn + n) * DKc + c * 4);
                vpref[t] = *(const float4*)(vb + (size_t)(jn + n) * DVc + c * 4);
            }
        }

        // ---- GEMM1: S(64x64) = Q K^T ----
        float scr[4][4];
        #pragma unroll
        for (int t = 0; t < 4; t++)
            #pragma unroll
            for (int e = 0; e < 4; e++) scr[t][e] = 0.0f;

        #pragma unroll
        for (int kt = 0; kt < 8; kt++) {
            #pragma unroll
            for (int tt = 0; tt < 2; tt++) {
                uint32_t b0, b1, b2, b3;
                uint32_t addr = KB + ((wn * 32 + tt * 16 + kb_row) * KV_STRIDE
                                      + kt * 16 + kb_col8) * 2;
                ldsm4(b0, b1, b2, b3, addr);
                mma_f16(scr[tt * 2],     qa[kt][0], qa[kt][1], qa[kt][2], qa[kt][3], b0, b1);
                mma_f16(scr[tt * 2 + 1], qa[kt][0], qa[kt][1], qa[kt][2], qa[kt][3], b2, b3);
            }
        }

        // ---- store prefetched tile to other buffer ----
        if (haveNext) {
            __half* KN = KsH + (buf ^ 1) * KV_TILE_H;
            __half* VN = VsH + (buf ^ 1) * KV_TILE_H;
            #pragma unroll
            for (int t = 0; t < 8; t++) {
                int idx = tid + t * NTHREADS;
                int n   = idx >> 5;
                int c   = idx & 31;
                __half2 k0 = __floats2half2_rn(kpref[t].x, kpref[t].y);
                __half2 k1 = __floats2half2_rn(kpref[t].z, kpref[t].w);
                uint2 uk; uk.x = h2bits(k0); uk.y = h2bits(k1);
                *(uint2*)(KN + n * KV_STRIDE + c * 4) = uk;
                __half2 v0 = __floats2half2_rn(vpref[t].x, vpref[t].y);
                __half2 v1 = __floats2half2_rn(vpref[t].z, vpref[t].w);
                uint2 uv; uv.x = h2bits(v0); uv.y = h2bits(v1);
                *(uint2*)(VN + n * KV_STRIDE + c * 4) = uv;
            }
        }

        // ---- decay + causal mask + rowsum, stage S (half2) ----
        const bool diag = (j0 == i0);
        #pragma unroll
        for (int t = 0; t < 4; t++) {
            const int jb = wn * 32 + t * 8 + 2 * lc;
            const float c0 = Cs[jb];
            const float c1 = Cs[jb + 1];
            float v0 = scr[t][0] * R0 * c0;
            float v1 = scr[t][1] * R0 * c1;
            float v2 = scr[t][2] * R1 * c0;
            float v3 = scr[t][3] * R1 * c1;
            if (diag) {
                if (jb     > il0) v0 = 0.0f;
                if (jb + 1 > il0) v1 = 0.0f;
                if (jb     > il1) v2 = 0.0f;
                if (jb + 1 > il1) v3 = 0.0f;
            }
            rs0 += v0 + v1;
            rs1 += v2 + v3;
            *(__half2*)(SsH + il0 * S_STRIDE + jb) = __floats2half2_rn(v0, v1);
            *(__half2*)(SsH + il1 * S_STRIDE + jb) = __floats2half2_rn(v2, v3);
        }
        R0 *= gstep;
        R1 *= gstep;
        __syncthreads();   // S + next tile visible

        // ---- GEMM2: O(64x128) += S @ V ----
        #pragma unroll
        for (int kt = 0; kt < 4; kt++) {
            uint32_t sa0, sa1, sa2, sa3;
            uint32_t saddr = SsU + ((wm * 16 + a_row) * S_STRIDE + kt * 16 + a_col8) * 2;
            ldsm4(sa0, sa1, sa2, sa3, saddr);
            #pragma unroll
            for (int dt = 0; dt < 4; dt++) {
                uint32_t b0, b1, b2, b3;
                uint32_t vaddr = VB + ((kt * 16 + a_row) * KV_STRIDE
                                       + wn * 64 + dt * 16 + a_col8) * 2;
                ldsm4t(b0, b1, b2, b3, vaddr);
                mma_f16(oc[dt * 2],     sa0, sa1, sa2, sa3, b0, b1);
                mma_f16(oc[dt * 2 + 1], sa0, sa1, sa2, sa3, b2, b3);
            }
        }
        __syncthreads();   // done reading current buffers + S

        buf ^= 1;
    }

    // ---- rowsum reduce: lane quad, then across wn halves ----
    rs0 += __shfl_xor_sync(0xffffffffu, rs0, 1);
    rs0 += __shfl_xor_sync(0xffffffffu, rs0, 2);
    rs1 += __shfl_xor_sync(0xffffffffu, rs1, 1);
    rs1 += __shfl_xor_sync(0xffffffffu, rs1, 2);

    if (wn == 0 && lc == 0) { RSs[il0] = rs0; RSs[il1] = rs1; }
    __syncthreads();
    if (wn == 1 && lc == 0) { RSs[il0] += rs0; RSs[il1] += rs1; }
    __syncthreads();

    const float dn0 = 1.0f / fmaxf(fabsf(RSs[il0]), 1.0f);
    const float dn1 = 1.0f / fmaxf(fabsf(RSs[il1]), 1.0f);

    float ssq0 = 0.0f, ssq1 = 0.0f;
    #pragma unroll
    for (int t = 0; t < 8; t++) {
        oc[t][0] *= dn0; oc[t][1] *= dn0;
        oc[t][2] *= dn1; oc[t][3] *= dn1;
        ssq0 += oc[t][0] * oc[t][0] + oc[t][1] * oc[t][1];
        ssq1 += oc[t][2] * oc[t][2] + oc[t][3] * oc[t][3];
    }
    ssq0 += __shfl_xor_sync(0xffffffffu, ssq0, 1);
    ssq0 += __shfl_xor_sync(0xffffffffu, ssq0, 2);
    ssq1 += __shfl_xor_sync(0xffffffffu, ssq1, 1);
    ssq1 += __shfl_xor_sync(0xffffffffu, ssq1, 2);

    if (wn == 0 && lc == 0) { SQs[il0] = ssq0; SQs[il1] = ssq1; }
    __syncthreads();
    if (wn == 1 && lc == 0) { SQs[il0] += ssq0; SQs[il1] += ssq1; }
    __syncthreads();

    const float sc0 = rsqrtf(SQs[il0] * (1.0f / (float)DVc) + 1e-6f);
    const float sc1 = rsqrtf(SQs[il1] * (1.0f / (float)DVc) + 1e-6f);

    const int gi0 = i0 + il0;
    const int gi1 = i0 + il1;
    float* po0 = out + (((size_t)b * Lc + gi0) * Hc + h) * DVc;
    float* po1 = out + (((size_t)b * Lc + gi1) * Hc + h) * DVc;
    #pragma unroll
    for (int t = 0; t < 8; t++) {
        const int d = wn * 64 + t * 8 + 2 * lc;
        float2 w0, w1;
        w0.x = oc[t][0] * sc0; w0.y = oc[t][1] * sc0;
        w1.x = oc[t][2] * sc1; w1.y = oc[t][3] * sc1;
        *(float2*)(po0 + d) = w0;
        *(float2*)(po1 + d) = w1;
    }
}

extern "C" void kernel_launch(void* const* d_in, const int* in_sizes, int n_in,
                              void* d_out, int out_size)
{
    const float* q = (const float*)d_in[0];
    const float* k = (const float*)d_in[1];
    const float* v = (const float*)d_in[2];
    float* out = (float*)d_out;

    cudaFuncSetAttribute(retnet_f16_kernel,
                         cudaFuncAttributeMaxDynamicSharedMemorySize,
                         (int)SMEM_BYTES);

    dim3 grid(Lc / BM, Bc * Hc);   // (32, 32)
    retnet_f16_kernel<<<grid, NTHREADS, SMEM_BYTES>>>(q, k, v, out);
}

// round 6
// speedup vs baseline: 2.0526x; 1.0448x over previous
#include <cuda_runtime.h>
#include <cuda_fp16.h>
#include <cstdint>

// RetNet parallel retention, fused fp16 mma.sync m16n8k16 + ldmatrix.
// R6: BM=128 (32-row warp tiles) -> 1.85x fewer LDS bytes per MMA.
// B=2, H=16, L=2048, DK=DV=128.
namespace {
constexpr int Lc  = 2048;
constexpr int Hc  = 16;
constexpr int Bc  = 2;
constexpr int DKc = 128;
constexpr int DVc = 128;
constexpr int BM  = 128;
constexpr int BN  = 64;
constexpr int KV_STRIDE = 136;   // halves per row
constexpr int S_STRIDE  = 72;    // halves per row
constexpr int NTHREADS  = 256;
constexpr int KV_TILE_H = 64 * KV_STRIDE;

// smem: KsH[2][64][136] VsH[2][64][136] SsH[128][72] (half) + Cs[64]/RSs[128]/SQs[128] (float)
constexpr size_t SMEM_BYTES =
    (size_t)(4 * KV_TILE_H + BM * S_STRIDE) * 2 + (64 + 128 + 128) * 4;
}

__device__ __forceinline__ void ldsm4(uint32_t& r0, uint32_t& r1, uint32_t& r2, uint32_t& r3,
                                      uint32_t addr) {
    asm volatile("ldmatrix.sync.aligned.m8n8.x4.shared.b16 {%0,%1,%2,%3}, [%4];"
                 : "=r"(r0), "=r"(r1), "=r"(r2), "=r"(r3) : "r"(addr));
}
__device__ __forceinline__ void ldsm4t(uint32_t& r0, uint32_t& r1, uint32_t& r2, uint32_t& r3,
                                       uint32_t addr) {
    asm volatile("ldmatrix.sync.aligned.m8n8.x4.trans.shared.b16 {%0,%1,%2,%3}, [%4];"
                 : "=r"(r0), "=r"(r1), "=r"(r2), "=r"(r3) : "r"(addr));
}
__device__ __forceinline__ void mma_f16(float c[4],
                                        uint32_t a0, uint32_t a1, uint32_t a2, uint32_t a3,
                                        uint32_t b0, uint32_t b1) {
    asm volatile(
        "mma.sync.aligned.m16n8k16.row.col.f32.f16.f16.f32 "
        "{%0,%1,%2,%3}, {%4,%5,%6,%7}, {%8,%9}, {%0,%1,%2,%3};\n"
        : "+f"(c[0]), "+f"(c[1]), "+f"(c[2]), "+f"(c[3])
        : "r"(a0), "r"(a1), "r"(a2), "r"(a3), "r"(b0), "r"(b1));
}
__device__ __forceinline__ uint32_t h2bits(__half2 h) {
    return *reinterpret_cast<uint32_t*>(&h);
}

__global__ __launch_bounds__(NTHREADS, 1)
void retnet_f16_kernel(const float* __restrict__ q,
                       const float* __restrict__ k,
                       const float* __restrict__ v,
                       float* __restrict__ out)
{
    extern __shared__ __align__(16) char smraw[];
    __half* KsH = reinterpret_cast<__half*>(smraw);          // [2][64][136]
    __half* VsH = KsH + 2 * KV_TILE_H;                       // [2][64][136]
    __half* SsH = VsH + 2 * KV_TILE_H;                       // [128][72]
    float*  Cs  = reinterpret_cast<float*>(SsH + BM * S_STRIDE);  // [64]
    float*  RSs = Cs + 64;                                   // [128]
    float*  SQs = RSs + 128;                                 // [128]

    const uint32_t KsU = (uint32_t)__cvta_generic_to_shared(KsH);
    const uint32_t VsU = (uint32_t)__cvta_generic_to_shared(VsH);
    const uint32_t SsU = (uint32_t)__cvta_generic_to_shared(SsH);
    constexpr uint32_t KV_TILE_BYTES = KV_TILE_H * 2;

    const int tid  = threadIdx.x;
    const int lane = tid & 31;
    const int warp = tid >> 5;
    const int wm   = warp >> 1;   // 0..3 : 32-row group
    const int wn   = warp & 1;    // 0..1 : column half
    const int lr   = lane >> 2;
    const int lc   = lane & 3;

    // ldmatrix lane patterns (validated in R5)
    const int l7 = lane & 7;
    const int g  = lane >> 3;
    const int a_row   = l7 + (g & 1) * 8;   // A-pattern rows / V-trans rows
    const int a_col8  = (g >> 1) * 8;
    const int kb_row  = l7 + (g >> 1) * 8;  // K B-pattern
    const int kb_col8 = (g & 1) * 8;

    const int bh = blockIdx.y;
    const int b  = bh >> 4;
    const int h  = bh & 15;
    const int m_block = (int)(gridDim.x - 1) - (int)blockIdx.x;  // heavy first
    const int i0 = m_block * BM;

    const float* qb = q + (size_t)bh * Lc * DKc;
    const float* kb = k + (size_t)bh * Lc * DKc;
    const float* vb = v + (size_t)bh * Lc * DVc;

    const float lg2 = log1pf(-exp2f(-5.0f - (float)h)) * 1.4426950408889634f;
    if (tid < 64) Cs[tid] = exp2f(-lg2 * (float)tid);

    // per-thread rows (4 of them: mg x {lo,hi})
    const int il[2][2] = {{wm * 32 + lr, wm * 32 + lr + 8},
                          {wm * 32 + 16 + lr, wm * 32 + 16 + lr + 8}};

    // ---- stage Q (128x128 half) across the K double-buffer region, pull A-frags ----
    #pragma unroll
    for (int t = 0; t < 16; t++) {
        int idx = tid + t * NTHREADS;
        int r   = idx >> 5;        // 0..127
        int c   = idx & 31;
        float4 gld = *(const float4*)(qb + (size_t)(i0 + r) * DKc + c * 4);
        uint2 u;
        u.x = h2bits(__floats2half2_rn(gld.x, gld.y));
        u.y = h2bits(__floats2half2_rn(gld.z, gld.w));
        *(uint2*)(KsH + r * KV_STRIDE + c * 4) = u;
    }
    __syncthreads();

    uint32_t qa[2][8][4];
    #pragma unroll
    for (int mg = 0; mg < 2; mg++)
        #pragma unroll
        for (int kt = 0; kt < 8; kt++) {
            uint32_t addr = KsU + ((wm * 32 + mg * 16 + a_row) * KV_STRIDE
                                   + kt * 16 + a_col8) * 2;
            ldsm4(qa[mg][kt][0], qa[mg][kt][1], qa[mg][kt][2], qa[mg][kt][3], addr);
        }
    __syncthreads();

    // ---- stage tile 0 (K + V) at j0start = i0 + 64 ----
    const int j0start = i0 + BM - BN;   // i0 + 64
    #pragma unroll
    for (int t = 0; t < 8; t++) {
        int idx = tid + t * NTHREADS;
        int n   = idx >> 5;
        int c   = idx & 31;
        float4 gk = *(const float4*)(kb + (size_t)(j0start + n) * DKc + c * 4);
        uint2 uk;
        uk.x = h2bits(__floats2half2_rn(gk.x, gk.y));
        uk.y = h2bits(__floats2half2_rn(gk.z, gk.w));
        *(uint2*)(KsH + n * KV_STRIDE + c * 4) = uk;
        float4 gv = *(const float4*)(vb + (size_t)(j0start + n) * DVc + c * 4);
        uint2 uv;
        uv.x = h2bits(__floats2half2_rn(gv.x, gv.y));
        uv.y = h2bits(__floats2half2_rn(gv.z, gv.w));
        *(uint2*)(VsH + n * KV_STRIDE + c * 4) = uv;
    }
    __syncthreads();

    float oc[2][8][4];
    #pragma unroll
    for (int mg = 0; mg < 2; mg++)
        #pragma unroll
        for (int t = 0; t < 8; t++)
            #pragma unroll
            for (int e = 0; e < 4; e++) oc[mg][t][e] = 0.0f;

    float rs[2][2] = {{0.0f, 0.0f}, {0.0f, 0.0f}};

    // row decay factors gamma^{il + doff}, doff = i0 - j0 starts at -64
    float R[2][2];
    #pragma unroll
    for (int mg = 0; mg < 2; mg++) {
        R[mg][0] = exp2f(lg2 * (float)(il[mg][0] - 64));
        R[mg][1] = exp2f(lg2 * (float)(il[mg][1] - 64));
    }
    const float gstep = exp2f(lg2 * (float)BN);

    int buf = 0;
    for (int j0 = j0start; j0 >= 0; j0 -= BN) {
        const bool haveNext = (j0 - BN) >= 0;
        const uint32_t KB = KsU + buf * KV_TILE_BYTES;
        const uint32_t VB = VsU + buf * KV_TILE_BYTES;
        const int jn = j0 - BN;

        // ---- prefetch next K into registers (hidden behind GEMM1) ----
        float4 kpref[8];
        if (haveNext) {
            #pragma unroll
            for (int t = 0; t < 8; t++) {
                int idx = tid + t * NTHREADS;
                int n   = idx >> 5;
                int c   = idx & 31;
                kpref[t] = *(const float4*)(kb + (size_t)(jn + n) * DKc + c * 4);
            }
        }

        // ---- GEMM1: S(128x64) = Q K^T ----
        float scr[2][4][4];
        #pragma unroll
        for (int mg = 0; mg < 2; mg++)
            #pragma unroll
            for (int t = 0; t < 4; t++)
                #pragma unroll
                for (int e = 0; e < 4; e++) scr[mg][t][e] = 0.0f;

        #pragma unroll
        for (int kt = 0; kt < 8; kt++) {
            #pragma unroll
            for (int tt = 0; tt < 2; tt++) {
                uint32_t b0, b1, b2, b3;
                uint32_t addr = KB + ((wn * 32 + tt * 16 + kb_row) * KV_STRIDE
                                      + kt * 16 + kb_col8) * 2;
                ldsm4(b0, b1, b2, b3, addr);
                #pragma unroll
                for (int mg = 0; mg < 2; mg++) {
                    mma_f16(scr[mg][tt * 2],     qa[mg][kt][0], qa[mg][kt][1],
                            qa[mg][kt][2], qa[mg][kt][3], b0, b1);
                    mma_f16(scr[mg][tt * 2 + 1], qa[mg][kt][0], qa[mg][kt][1],
                            qa[mg][kt][2], qa[mg][kt][3], b2, b3);
                }
            }
        }

        // ---- store prefetched K to other buffer ----
        if (haveNext) {
            __half* KN = KsH + (buf ^ 1) * KV_TILE_H;
            #pragma unroll
            for (int t = 0; t < 8; t++) {
                int idx = tid + t * NTHREADS;
                int n   = idx >> 5;
                int c   = idx & 31;
                uint2 uk;
                uk.x = h2bits(__floats2half2_rn(kpref[t].x, kpref[t].y));
                uk.y = h2bits(__floats2half2_rn(kpref[t].z, kpref[t].w));
                *(uint2*)(KN + n * KV_STRIDE + c * 4) = uk;
            }
        }

        // ---- prefetch next V into registers (hidden behind decay + GEMM2) ----
        float4 vpref[8];
        if (haveNext) {
            #pragma unroll
            for (int t = 0; t < 8; t++) {
                int idx = tid + t * NTHREADS;
                int n   = idx >> 5;
                int c   = idx & 31;
                vpref[t] = *(const float4*)(vb + (size_t)(jn + n) * DVc + c * 4);
            }
        }

        // ---- decay + causal mask + rowsum, stage S ----
        const int doff = i0 - j0;          // -64, 0, 64, 128, ...
        const bool diag = (doff < 64);
        #pragma unroll
        for (int mg = 0; mg < 2; mg++) {
            #pragma unroll
            for (int t = 0; t < 4; t++) {
                const int jb = wn * 32 + t * 8 + 2 * lc;
                const float c0 = Cs[jb];
                const float c1 = Cs[jb + 1];
                float v0 = scr[mg][t][0] * R[mg][0] * c0;
                float v1 = scr[mg][t][1] * R[mg][0] * c1;
                float v2 = scr[mg][t][2] * R[mg][1] * c0;
                float v3 = scr[mg][t][3] * R[mg][1] * c1;
                if (diag) {
                    const int th0 = il[mg][0] + doff;
                    const int th1 = il[mg][1] + doff;
                    if (jb     > th0) v0 = 0.0f;
                    if (jb + 1 > th0) v1 = 0.0f;
                    if (jb     > th1) v2 = 0.0f;
                    if (jb + 1 > th1) v3 = 0.0f;
                }
                rs[mg][0] += v0 + v1;
                rs[mg][1] += v2 + v3;
                *(__half2*)(SsH + il[mg][0] * S_STRIDE + jb) = __floats2half2_rn(v0, v1);
                *(__half2*)(SsH + il[mg][1] * S_STRIDE + jb) = __floats2half2_rn(v2, v3);
            }
            R[mg][0] *= gstep;
            R[mg][1] *= gstep;
        }
        __syncthreads();   // S visible; K_next visible

        // ---- GEMM2: O(128x128) += S @ V ----
        #pragma unroll
        for (int kt2 = 0; kt2 < 4; kt2++) {
            uint32_t sa[2][4];
            #pragma unroll
            for (int mg = 0; mg < 2; mg++) {
                uint32_t saddr = SsU + ((wm * 32 + mg * 16 + a_row) * S_STRIDE
                                        + kt2 * 16 + a_col8) * 2;
                ldsm4(sa[mg][0], sa[mg][1], sa[mg][2], sa[mg][3], saddr);
            }
            #pragma unroll
            for (int dt = 0; dt < 4; dt++) {
                uint32_t b0, b1, b2, b3;
                uint32_t vaddr = VB + ((kt2 * 16 + a_row) * KV_STRIDE
                                       + wn * 64 + dt * 16 + a_col8) * 2;
                ldsm4t(b0, b1, b2, b3, vaddr);
                #pragma unroll
                for (int mg = 0; mg < 2; mg++) {
                    mma_f16(oc[mg][dt * 2],     sa[mg][0], sa[mg][1], sa[mg][2], sa[mg][3], b0, b1);
                    mma_f16(oc[mg][dt * 2 + 1], sa[mg][0], sa[mg][1], sa[mg][2], sa[mg][3], b2, b3);
                }
            }
        }

        // ---- store prefetched V to other buffer (visible after next mid-sync) ----
        if (haveNext) {
            __half* VN = VsH + (buf ^ 1) * KV_TILE_H;
            #pragma unroll
            for (int t = 0; t < 8; t++) {
                int idx = tid + t * NTHREADS;
                int n   = idx >> 5;
                int c   = idx & 31;
                uint2 uv;
                uv.x = h2bits(__floats2half2_rn(vpref[t].x, vpref[t].y));
                uv.y = h2bits(__floats2half2_rn(vpref[t].z, vpref[t].w));
                *(uint2*)(VN + n * KV_STRIDE + c * 4) = uv;
            }
        }
        __syncthreads();   // reads of current buffers + S done

        buf ^= 1;
    }

    // ---- rowsum reduce: lane quad, then across wn halves via smem ----
    #pragma unroll
    for (int mg = 0; mg < 2; mg++) {
        #pragma unroll
        for (int hh = 0; hh < 2; hh++) {
            rs[mg][hh] += __shfl_xor_sync(0xffffffffu, rs[mg][hh], 1);
            rs[mg][hh] += __shfl_xor_sync(0xffffffffu, rs[mg][hh], 2);
        }
    }
    if (wn == 0 && lc == 0) {
        RSs[il[0][0]] = rs[0][0]; RSs[il[0][1]] = rs[0][1];
        RSs[il[1][0]] = rs[1][0]; RSs[il[1][1]] = rs[1][1];
    }
    __syncthreads();
    if (wn == 1 && lc == 0) {
        RSs[il[0][0]] += rs[0][0]; RSs[il[0][1]] += rs[0][1];
        RSs[il[1][0]] += rs[1][0]; RSs[il[1][1]] += rs[1][1];
    }
    __syncthreads();

    float ssq[2][2] = {{0.0f, 0.0f}, {0.0f, 0.0f}};
    #pragma unroll
    for (int mg = 0; mg < 2; mg++) {
        const float dn0 = 1.0f / fmaxf(fabsf(RSs[il[mg][0]]), 1.0f);
        const float dn1 = 1.0f / fmaxf(fabsf(RSs[il[mg][1]]), 1.0f);
        #pragma unroll
        for (int t = 0; t < 8; t++) {
            oc[mg][t][0] *= dn0; oc[mg][t][1] *= dn0;
            oc[mg][t][2] *= dn1; oc[mg][t][3] *= dn1;
            ssq[mg][0] += oc[mg][t][0] * oc[mg][t][0] + oc[mg][t][1] * oc[mg][t][1];
            ssq[mg][1] += oc[mg][t][2] * oc[mg][t][2] + oc[mg][t][3] * oc[mg][t][3];
        }
        ssq[mg][0] += __shfl_xor_sync(0xffffffffu, ssq[mg][0], 1);
        ssq[mg][0] += __shfl_xor_sync(0xffffffffu, ssq[mg][0], 2);
        ssq[mg][1] += __shfl_xor_sync(0xffffffffu, ssq[mg][1], 1);
        ssq[mg][1] += __shfl_xor_sync(0xffffffffu, ssq[mg][1], 2);
    }
    if (wn == 0 && lc == 0) {
        SQs[il[0][0]] = ssq[0][0]; SQs[il[0][1]] = ssq[0][1];
        SQs[il[1][0]] = ssq[1][0]; SQs[il[1][1]] = ssq[1][1];
    }
    __syncthreads();
    if (wn == 1 && lc == 0) {
        SQs[il[0][0]] += ssq[0][0]; SQs[il[0][1]] += ssq[0][1];
        SQs[il[1][0]] += ssq[1][0]; SQs[il[1][1]] += ssq[1][1];
    }
    __syncthreads();

    // ---- RMS scale + write out[b, i, h, d] ----
    #pragma unroll
    for (int mg = 0; mg < 2; mg++) {
        const float sc0 = rsqrtf(SQs[il[mg][0]] * (1.0f / (float)DVc) + 1e-6f);
        const float sc1 = rsqrtf(SQs[il[mg][1]] * (1.0f / (float)DVc) + 1e-6f);
        float* po0 = out + (((size_t)b * Lc + (i0 + il[mg][0])) * Hc + h) * DVc;
        float* po1 = out + (((size_t)b * Lc + (i0 + il[mg][1])) * Hc + h) * DVc;
        #pragma unroll
        for (int t = 0; t < 8; t++) {
            const int dt = t >> 1, n8 = t & 1;
            const int d = wn * 64 + dt * 16 + n8 * 8 + 2 * lc;
            float2 w0, w1;
            w0.x = oc[mg][t][0] * sc0; w0.y = oc[mg][t][1] * sc0;
            w1.x = oc[mg][t][2] * sc1; w1.y = oc[mg][t][3] * sc1;
            *(float2*)(po0 + d) = w0;
            *(float2*)(po1 + d) = w1;
        }
    }
}

extern "C" void kernel_launch(void* const* d_in, const int* in_sizes, int n_in,
                              void* d_out, int out_size)
{
    const float* q = (const float*)d_in[0];
    const float* k = (const float*)d_in[1];
    const float* v = (const float*)d_in[2];
    float* out = (float*)d_out;

    cudaFuncSetAttribute(retnet_f16_kernel,
                         cudaFuncAttributeMaxDynamicSharedMemorySize,
                         (int)SMEM_BYTES);

    dim3 grid(Lc / BM, Bc * Hc);   // (16, 32)
    retnet_f16_kernel<<<grid, NTHREADS, SMEM_BYTES>>>(q, k, v, out);
}

// round 7
// speedup vs baseline: 2.0928x; 1.0196x over previous
#include <cuda_runtime.h>
#include <cuda_fp16.h>
#include <cstdint>

// RetNet parallel retention, fused fp16 mma.sync m16n8k16 + ldmatrix.
// R7: 512 threads (16 warps/SM), warp grid 8x2, regs<=128, Q frags in regs.
// B=2, H=16, L=2048, DK=DV=128.
namespace {
constexpr int Lc  = 2048;
constexpr int Hc  = 16;
constexpr int Bc  = 2;
constexpr int DKc = 128;
constexpr int DVc = 128;
constexpr int BM  = 128;
constexpr int BN  = 64;
constexpr int KV_STRIDE = 136;   // halves per row
constexpr int S_STRIDE  = 72;    // halves per row
constexpr int NTHREADS  = 512;
constexpr int KV_TILE_H = 64 * KV_STRIDE;

// smem: KsH[2][64][136] VsH[2][64][136] SsH[128][72] (half) + Cs[64]/RSs[128]/SQs[128] (float)
constexpr size_t SMEM_BYTES =
    (size_t)(4 * KV_TILE_H + BM * S_STRIDE) * 2 + (64 + 128 + 128) * 4;
}

__device__ __forceinline__ void ldsm4(uint32_t& r0, uint32_t& r1, uint32_t& r2, uint32_t& r3,
                                      uint32_t addr) {
    asm volatile("ldmatrix.sync.aligned.m8n8.x4.shared.b16 {%0,%1,%2,%3}, [%4];"
                 : "=r"(r0), "=r"(r1), "=r"(r2), "=r"(r3) : "r"(addr));
}
__device__ __forceinline__ void ldsm4t(uint32_t& r0, uint32_t& r1, uint32_t& r2, uint32_t& r3,
                                       uint32_t addr) {
    asm volatile("ldmatrix.sync.aligned.m8n8.x4.trans.shared.b16 {%0,%1,%2,%3}, [%4];"
                 : "=r"(r0), "=r"(r1), "=r"(r2), "=r"(r3) : "r"(addr));
}
__device__ __forceinline__ void mma_f16(float c[4],
                                        uint32_t a0, uint32_t a1, uint32_t a2, uint32_t a3,
                                        uint32_t b0, uint32_t b1) {
    asm volatile(
        "mma.sync.aligned.m16n8k16.row.col.f32.f16.f16.f32 "
        "{%0,%1,%2,%3}, {%4,%5,%6,%7}, {%8,%9}, {%0,%1,%2,%3};\n"
        : "+f"(c[0]), "+f"(c[1]), "+f"(c[2]), "+f"(c[3])
        : "r"(a0), "r"(a1), "r"(a2), "r"(a3), "r"(b0), "r"(b1));
}
__device__ __forceinline__ uint32_t h2bits(__half2 h) {
    return *reinterpret_cast<uint32_t*>(&h);
}

__global__ __launch_bounds__(NTHREADS, 1)
void retnet_f16_kernel(const float* __restrict__ q,
                       const float* __restrict__ k,
                       const float* __restrict__ v,
                       float* __restrict__ out)
{
    extern __shared__ __align__(16) char smraw[];
    __half* KsH = reinterpret_cast<__half*>(smraw);          // [2][64][136]
    __half* VsH = KsH + 2 * KV_TILE_H;                       // [2][64][136]
    __half* SsH = VsH + 2 * KV_TILE_H;                       // [128][72]
    float*  Cs  = reinterpret_cast<float*>(SsH + BM * S_STRIDE);  // [64]
    float*  RSs = Cs + 64;                                   // [128]
    float*  SQs = RSs + 128;                                 // [128]

    const uint32_t KsU = (uint32_t)__cvta_generic_to_shared(KsH);
    const uint32_t VsU = (uint32_t)__cvta_generic_to_shared(VsH);
    const uint32_t SsU = (uint32_t)__cvta_generic_to_shared(SsH);
    constexpr uint32_t KV_TILE_BYTES = KV_TILE_H * 2;

    const int tid  = threadIdx.x;
    const int lane = tid & 31;
    const int warp = tid >> 5;    // 0..15
    const int wm   = warp >> 1;   // 0..7 : 16-row group
    const int wn   = warp & 1;    // 0..1 : column half
    const int lr   = lane >> 2;
    const int lc   = lane & 3;

    // ldmatrix lane patterns (validated R5/R6)
    const int l7 = lane & 7;
    const int g  = lane >> 3;
    const int a_row   = l7 + (g & 1) * 8;   // A-pattern rows / V-trans rows
    const int a_col8  = (g >> 1) * 8;
    const int kb_row  = l7 + (g >> 1) * 8;  // K B-pattern
    const int kb_col8 = (g & 1) * 8;

    const int bh = blockIdx.y;
    const int b  = bh >> 4;
    const int h  = bh & 15;
    const int m_block = (int)(gridDim.x - 1) - (int)blockIdx.x;  // heavy first
    const int i0 = m_block * BM;

    const float* qb = q + (size_t)bh * Lc * DKc;
    const float* kb = k + (size_t)bh * Lc * DKc;
    const float* vb = v + (size_t)bh * Lc * DVc;

    const float lg2 = log1pf(-exp2f(-5.0f - (float)h)) * 1.4426950408889634f;
    if (tid < 64) Cs[tid] = exp2f(-lg2 * (float)tid);

    const int il0 = wm * 16 + lr;   // 0..127
    const int il1 = il0 + 8;

    // ---- stage Q (128x128 half) across K double-buffer region, pull A-frags ----
    #pragma unroll
    for (int t = 0; t < 8; t++) {
        int idx = tid + t * NTHREADS;
        int r   = idx >> 5;        // 0..127
        int c   = idx & 31;
        float4 gld = *(const float4*)(qb + (size_t)(i0 + r) * DKc + c * 4);
        uint2 u;
        u.x = h2bits(__floats2half2_rn(gld.x, gld.y));
        u.y = h2bits(__floats2half2_rn(gld.z, gld.w));
        *(uint2*)(KsH + r * KV_STRIDE + c * 4) = u;
    }
    __syncthreads();

    uint32_t qa[8][4];
    #pragma unroll
    for (int kt = 0; kt < 8; kt++) {
        uint32_t addr = KsU + ((wm * 16 + a_row) * KV_STRIDE + kt * 16 + a_col8) * 2;
        ldsm4(qa[kt][0], qa[kt][1], qa[kt][2], qa[kt][3], addr);
    }
    __syncthreads();

    // ---- stage tile 0 (K + V) at j0start = i0 + 64 ----
    const int j0start = i0 + BM - BN;
    #pragma unroll
    for (int t = 0; t < 4; t++) {
        int idx = tid + t * NTHREADS;
        int n   = idx >> 5;        // 0..63
        int c   = idx & 31;
        float4 gk = *(const float4*)(kb + (size_t)(j0start + n) * DKc + c * 4);
        uint2 uk;
        uk.x = h2bits(__floats2half2_rn(gk.x, gk.y));
        uk.y = h2bits(__floats2half2_rn(gk.z, gk.w));
        *(uint2*)(KsH + n * KV_STRIDE + c * 4) = uk;
        float4 gv = *(const float4*)(vb + (size_t)(j0start + n) * DVc + c * 4);
        uint2 uv;
        uv.x = h2bits(__floats2half2_rn(gv.x, gv.y));
        uv.y = h2bits(__floats2half2_rn(gv.z, gv.w));
        *(uint2*)(VsH + n * KV_STRIDE + c * 4) = uv;
    }
    __syncthreads();

    float oc[8][4];
    #pragma unroll
    for (int t = 0; t < 8; t++)
        #pragma unroll
        for (int e = 0; e < 4; e++) oc[t][e] = 0.0f;

    float rs0 = 0.0f, rs1 = 0.0f;

    // row decay gamma^{il + doff}, doff = i0 - j0 starts at -64
    float R0 = exp2f(lg2 * (float)(il0 - 64));
    float R1 = exp2f(lg2 * (float)(il1 - 64));
    const float gstep = exp2f(lg2 * (float)BN);

    int buf = 0;
    for (int j0 = j0start; j0 >= 0; j0 -= BN) {
        const bool haveNext = (j0 - BN) >= 0;
        const uint32_t KB = KsU + buf * KV_TILE_BYTES;
        const uint32_t VB = VsU + buf * KV_TILE_BYTES;
        const int jn = j0 - BN;

        // ---- prefetch next K into registers (hidden behind GEMM1) ----
        float4 kpref[4];
        if (haveNext) {
            #pragma unroll
            for (int t = 0; t < 4; t++) {
                int idx = tid + t * NTHREADS;
                int n   = idx >> 5;
                int c   = idx & 31;
                kpref[t] = *(const float4*)(kb + (size_t)(jn + n) * DKc + c * 4);
            }
        }

        // ---- GEMM1: S(128x64) = Q K^T, warp tile 16x32 ----
        float scr[4][4];
        #pragma unroll
        for (int t = 0; t < 4; t++)
            #pragma unroll
            for (int e = 0; e < 4; e++) scr[t][e] = 0.0f;

        #pragma unroll
        for (int kt = 0; kt < 8; kt++) {
            #pragma unroll
            for (int tt = 0; tt < 2; tt++) {
                uint32_t b0, b1, b2, b3;
                uint32_t addr = KB + ((wn * 32 + tt * 16 + kb_row) * KV_STRIDE
                                      + kt * 16 + kb_col8) * 2;
                ldsm4(b0, b1, b2, b3, addr);
                mma_f16(scr[tt * 2],     qa[kt][0], qa[kt][1], qa[kt][2], qa[kt][3], b0, b1);
                mma_f16(scr[tt * 2 + 1], qa[kt][0], qa[kt][1], qa[kt][2], qa[kt][3], b2, b3);
            }
        }

        // ---- store prefetched K to other buffer ----
        if (haveNext) {
            __half* KN = KsH + (buf ^ 1) * KV_TILE_H;
            #pragma unroll
            for (int t = 0; t < 4; t++) {
                int idx = tid + t * NTHREADS;
                int n   = idx >> 5;
                int c   = idx & 31;
                uint2 uk;
                uk.x = h2bits(__floats2half2_rn(kpref[t].x, kpref[t].y));
                uk.y = h2bits(__floats2half2_rn(kpref[t].z, kpref[t].w));
                *(uint2*)(KN + n * KV_STRIDE + c * 4) = uk;
            }
        }

        // ---- prefetch next V into registers (hidden behind decay + GEMM2) ----
        float4 vpref[4];
        if (haveNext) {
            #pragma unroll
            for (int t = 0; t < 4; t++) {
                int idx = tid + t * NTHREADS;
                int n   = idx >> 5;
                int c   = idx & 31;
                vpref[t] = *(const float4*)(vb + (size_t)(jn + n) * DVc + c * 4);
            }
        }

        // ---- decay + causal mask + rowsum, stage S ----
        const int doff = i0 - j0;          // -64, 0, 64, ...
        const bool diag = (doff < 64);
        #pragma unroll
        for (int t = 0; t < 4; t++) {
            const int jb = wn * 32 + t * 8 + 2 * lc;
            const float c0 = Cs[jb];
            const float c1 = Cs[jb + 1];
            float v0 = scr[t][0] * R0 * c0;
            float v1 = scr[t][1] * R0 * c1;
            float v2 = scr[t][2] * R1 * c0;
            float v3 = scr[t][3] * R1 * c1;
            if (diag) {
                const int th0 = il0 + doff;
                const int th1 = il1 + doff;
                if (jb     > th0) v0 = 0.0f;
                if (jb + 1 > th0) v1 = 0.0f;
                if (jb     > th1) v2 = 0.0f;
                if (jb + 1 > th1) v3 = 0.0f;
            }
            rs0 += v0 + v1;
            rs1 += v2 + v3;
            *(__half2*)(SsH + il0 * S_STRIDE + jb) = __floats2half2_rn(v0, v1);
            *(__half2*)(SsH + il1 * S_STRIDE + jb) = __floats2half2_rn(v2, v3);
        }
        R0 *= gstep;
        R1 *= gstep;
        __syncthreads();   // S visible; K_next visible

        // ---- GEMM2: O(128x128) += S @ V, warp tile 16x64 ----
        #pragma unroll
        for (int kt2 = 0; kt2 < 4; kt2++) {
            uint32_t sa0, sa1, sa2, sa3;
            uint32_t saddr = SsU + ((wm * 16 + a_row) * S_STRIDE + kt2 * 16 + a_col8) * 2;
            ldsm4(sa0, sa1, sa2, sa3, saddr);
            #pragma unroll
            for (int dt = 0; dt < 4; dt++) {
                uint32_t b0, b1, b2, b3;
                uint32_t vaddr = VB + ((kt2 * 16 + a_row) * KV_STRIDE
                                       + wn * 64 + dt * 16 + a_col8) * 2;
                ldsm4t(b0, b1, b2, b3, vaddr);
                mma_f16(oc[dt * 2],     sa0, sa1, sa2, sa3, b0, b1);
                mma_f16(oc[dt * 2 + 1], sa0, sa1, sa2, sa3, b2, b3);
            }
        }

        // ---- store prefetched V to other buffer ----
        if (haveNext) {
            __half* VN = VsH + (buf ^ 1) * KV_TILE_H;
            #pragma unroll
            for (int t = 0; t < 4; t++) {
                int idx = tid + t * NTHREADS;
                int n   = idx >> 5;
                int c   = idx & 31;
                uint2 uv;
                uv.x = h2bits(__floats2half2_rn(vpref[t].x, vpref[t].y));
                uv.y = h2bits(__floats2half2_rn(vpref[t].z, vpref[t].w));
                *(uint2*)(VN + n * KV_STRIDE + c * 4) = uv;
            }
        }
        __syncthreads();   // reads of current buffers + S done

        buf ^= 1;
    }

    // ---- rowsum reduce: lane quad, then across the 2 wn warps via smem ----
    rs0 += __shfl_xor_sync(0xffffffffu, rs0, 1);
    rs0 += __shfl_xor_sync(0xffffffffu, rs0, 2);
    rs1 += __shfl_xor_sync(0xffffffffu, rs1, 1);
    rs1 += __shfl_xor_sync(0xffffffffu, rs1, 2);

    if (wn == 0 && lc == 0) { RSs[il0] = rs0; RSs[il1] = rs1; }
    __syncthreads();
    if (wn == 1 && lc == 0) { RSs[il0] += rs0; RSs[il1] += rs1; }
    __syncthreads();

    const float dn0 = 1.0f / fmaxf(fabsf(RSs[il0]), 1.0f);
    const float dn1 = 1.0f / fmaxf(fabsf(RSs[il1]), 1.0f);

    float ssq0 = 0.0f, ssq1 = 0.0f;
    #pragma unroll
    for (int t = 0; t < 8; t++) {
        oc[t][0] *= dn0; oc[t][1] *= dn0;
        oc[t][2] *= dn1; oc[t][3] *= dn1;
        ssq0 += oc[t][0] * oc[t][0] + oc[t][1] * oc[t][1];
        ssq1 += oc[t][2] * oc[t][2] + oc[t][3] * oc[t][3];
    }
    ssq0 += __shfl_xor_sync(0xffffffffu, ssq0, 1);
    ssq0 += __shfl_xor_sync(0xffffffffu, ssq0, 2);
    ssq1 += __shfl_xor_sync(0xffffffffu, ssq1, 1);
    ssq1 += __shfl_xor_sync(0xffffffffu, ssq1, 2);

    if (wn == 0 && lc == 0) { SQs[il0] = ssq0; SQs[il1] = ssq1; }
    __syncthreads();
    if (wn == 1 && lc == 0) { SQs[il0] += ssq0; SQs[il1] += ssq1; }
    __syncthreads();

    const float sc0 = rsqrtf(SQs[il0] * (1.0f / (float)DVc) + 1e-6f);
    const float sc1 = rsqrtf(SQs[il1] * (1.0f / (float)DVc) + 1e-6f);

    float* po0 = out + (((size_t)b * Lc + (i0 + il0)) * Hc + h) * DVc;
    float* po1 = out + (((size_t)b * Lc + (i0 + il1)) * Hc + h) * DVc;
    #pragma unroll
    for (int t = 0; t < 8; t++) {
        const int dt = t >> 1, n8 = t & 1;
        const int d = wn * 64 + dt * 16 + n8 * 8 + 2 * lc;
        float2 w0, w1;
        w0.x = oc[t][0] * sc0; w0.y = oc[t][1] * sc0;
        w1.x = oc[t][2] * sc1; w1.y = oc[t][3] * sc1;
        *(float2*)(po0 + d) = w0;
        *(float2*)(po1 + d) = w1;
    }
}

extern "C" void kernel_launch(void* const* d_in, const int* in_sizes, int n_in,
                              void* d_out, int out_size)
{
    const float* q = (const float*)d_in[0];
    const float* k = (const float*)d_in[1];
    const float* v = (const float*)d_in[2];
    float* out = (float*)d_out;

    cudaFuncSetAttribute(retnet_f16_kernel,
                         cudaFuncAttributeMaxDynamicSharedMemorySize,
                         (int)SMEM_BYTES);

    dim3 grid(Lc / BM, Bc * Hc);   // (16, 32)
    retnet_f16_kernel<<<grid, NTHREADS, SMEM_BYTES>>>(q, k, v, out);
}

// round 9
// speedup vs baseline: 2.3598x; 1.1276x over previous
#include <cuda_runtime.h>
#include <cuda_fp16.h>
#include <cstdint>

// RetNet parallel retention, fused fp16 mma.sync m16n8k16 + ldmatrix.
// R9: fp16 pre-conversion of K/V + cp.async tile staging (no RF round-trip).
// B=2, H=16, L=2048, DK=DV=128.
namespace {
constexpr int Lc  = 2048;
constexpr int Hc  = 16;
constexpr int Bc  = 2;
constexpr int DKc = 128;
constexpr int DVc = 128;
constexpr int BM  = 128;
constexpr int BN  = 64;
constexpr int KV_STRIDE = 136;   // halves per row (272B, 16B-aligned)
constexpr int S_STRIDE  = 72;
constexpr int NTHREADS  = 512;
constexpr int KV_TILE_H = 64 * KV_STRIDE;

constexpr size_t SMEM_BYTES =
    (size_t)(4 * KV_TILE_H + BM * S_STRIDE) * 2 + (64 + 128 + 128) * 4;

constexpr size_t KV_ELEMS = (size_t)Bc * Hc * Lc * DKc;   // 8388608
}

// fp16 copies of K and V (device globals: allowed scratch)
__device__ __half g_kh[KV_ELEMS];
__device__ __half g_vh[KV_ELEMS];

__device__ __forceinline__ void ldsm4(uint32_t& r0, uint32_t& r1, uint32_t& r2, uint32_t& r3,
                                      uint32_t addr) {
    asm volatile("ldmatrix.sync.aligned.m8n8.x4.shared.b16 {%0,%1,%2,%3}, [%4];"
                 : "=r"(r0), "=r"(r1), "=r"(r2), "=r"(r3) : "r"(addr));
}
__device__ __forceinline__ void ldsm4t(uint32_t& r0, uint32_t& r1, uint32_t& r2, uint32_t& r3,
                                       uint32_t addr) {
    asm volatile("ldmatrix.sync.aligned.m8n8.x4.trans.shared.b16 {%0,%1,%2,%3}, [%4];"
                 : "=r"(r0), "=r"(r1), "=r"(r2), "=r"(r3) : "r"(addr));
}
__device__ __forceinline__ void mma_f16(float c[4],
                                        uint32_t a0, uint32_t a1, uint32_t a2, uint32_t a3,
                                        uint32_t b0, uint32_t b1) {
    asm volatile(
        "mma.sync.aligned.m16n8k16.row.col.f32.f16.f16.f32 "
        "{%0,%1,%2,%3}, {%4,%5,%6,%7}, {%8,%9}, {%0,%1,%2,%3};\n"
        : "+f"(c[0]), "+f"(c[1]), "+f"(c[2]), "+f"(c[3])
        : "r"(a0), "r"(a1), "r"(a2), "r"(a3), "r"(b0), "r"(b1));
}
__device__ __forceinline__ uint32_t h2bits(__half2 h) {
    return *reinterpret_cast<uint32_t*>(&h);
}

#define CP_ASYNC16(dst, src) \
    asm volatile("cp.async.cg.shared.global [%0], [%1], 16;" :: "r"(dst), "l"(src) : "memory")
#define CP_COMMIT() asm volatile("cp.async.commit_group;" ::: "memory")
#define CP_WAIT0()  asm volatile("cp.async.wait_group 0;"  ::: "memory")

// ---- pre-pass: fp32 K/V -> fp16 device globals ----
__global__ __launch_bounds__(256, 4)
void cvt_kv_kernel(const float* __restrict__ k, const float* __restrict__ v)
{
    size_t i = (size_t)blockIdx.x * blockDim.x + threadIdx.x;   // over float4s
    float4 a = ((const float4*)k)[i];
    uint2 uk;
    uk.x = h2bits(__floats2half2_rn(a.x, a.y));
    uk.y = h2bits(__floats2half2_rn(a.z, a.w));
    ((uint2*)g_kh)[i] = uk;
    float4 bvec = ((const float4*)v)[i];
    uint2 uv;
    uv.x = h2bits(__floats2half2_rn(bvec.x, bvec.y));
    uv.y = h2bits(__floats2half2_rn(bvec.z, bvec.w));
    ((uint2*)g_vh)[i] = uv;
}

__global__ __launch_bounds__(NTHREADS, 1)
void retnet_f16_kernel(const float* __restrict__ q,
                       float* __restrict__ out)
{
    extern __shared__ __align__(16) char smraw[];
    __half* KsH = reinterpret_cast<__half*>(smraw);          // [2][64][136]
    __half* VsH = KsH + 2 * KV_TILE_H;                       // [2][64][136]
    __half* SsH = VsH + 2 * KV_TILE_H;                       // [128][72]
    float*  Cs  = reinterpret_cast<float*>(SsH + BM * S_STRIDE);  // [64]
    float*  RSs = Cs + 64;                                   // [128]
    float*  SQs = RSs + 128;                                 // [128]

    const uint32_t KsU = (uint32_t)__cvta_generic_to_shared(KsH);
    const uint32_t VsU = (uint32_t)__cvta_generic_to_shared(VsH);
    const uint32_t SsU = (uint32_t)__cvta_generic_to_shared(SsH);
    constexpr uint32_t KV_TILE_BYTES = KV_TILE_H * 2;

    const int tid  = threadIdx.x;
    const int lane = tid & 31;
    const int warp = tid >> 5;    // 0..15
    const int wm   = warp >> 1;   // 0..7 : 16-row group
    const int wn   = warp & 1;    // 0..1 : column half
    const int lc   = lane & 3;

    // ldmatrix lane patterns (validated R5-R7)
    const int l7 = lane & 7;
    const int g  = lane >> 3;
    const int a_row   = l7 + (g & 1) * 8;
    const int a_col8  = (g >> 1) * 8;
    const int kb_row  = l7 + (g >> 1) * 8;
    const int kb_col8 = (g & 1) * 8;

    const int bh = blockIdx.y;
    const int b  = bh >> 4;
    const int h  = bh & 15;
    const int m_block = (int)(gridDim.x - 1) - (int)blockIdx.x;  // heavy first
    const int i0 = m_block * BM;

    const float*  qb = q + (size_t)bh * Lc * DKc;
    const __half* kh = g_kh + (size_t)bh * Lc * DKc;
    const __half* vh = g_vh + (size_t)bh * Lc * DVc;

    const float lg2 = log1pf(-exp2f(-5.0f - (float)h)) * 1.4426950408889634f;
    if (tid < 64) Cs[tid] = exp2f(-lg2 * (float)tid);

    const int lr  = lane >> 2;
    const int il0 = wm * 16 + lr;   // 0..127
    const int il1 = il0 + 8;

    // ---- stage Q (128x128 fp32->fp16) across K double-buffer region, pull A-frags ----
    #pragma unroll
    for (int t = 0; t < 8; t++) {
        int idx = tid + t * NTHREADS;
        int r   = idx >> 5;        // 0..127
        int c   = idx & 31;
        float4 gld = *(const float4*)(qb + (size_t)(i0 + r) * DKc + c * 4);
        uint2 u;
        u.x = h2bits(__floats2half2_rn(gld.x, gld.y));
        u.y = h2bits(__floats2half2_rn(gld.z, gld.w));
        *(uint2*)(KsH + r * KV_STRIDE + c * 4) = u;
    }
    __syncthreads();

    uint32_t qa[8][4];
    #pragma unroll
    for (int kt = 0; kt < 8; kt++) {
        uint32_t addr = KsU + ((wm * 16 + a_row) * KV_STRIDE + kt * 16 + a_col8) * 2;
        ldsm4(qa[kt][0], qa[kt][1], qa[kt][2], qa[kt][3], addr);
    }
    __syncthreads();

    // ---- stage tile 0 (K + V) via cp.async at j0start = i0 + 64 ----
    const int j0start = i0 + BM - BN;
    {
        const __half* ksrc = kh + (size_t)j0start * DKc;
        const __half* vsrc = vh + (size_t)j0start * DVc;
        #pragma unroll
        for (int t = 0; t < 2; t++) {
            int idx = tid + t * NTHREADS;
            int n   = idx >> 4;        // 0..63
            int c   = idx & 15;        // 16B chunk
            CP_ASYNC16(KsU + (uint32_t)(n * KV_STRIDE + c * 8) * 2, ksrc + n * DKc + c * 8);
            CP_ASYNC16(VsU + (uint32_t)(n * KV_STRIDE + c * 8) * 2, vsrc + n * DVc + c * 8);
        }
        CP_COMMIT();
        CP_WAIT0();
    }
    __syncthreads();

    float oc[8][4];
    #pragma unroll
    for (int t = 0; t < 8; t++)
        #pragma unroll
        for (int e = 0; e < 4; e++) oc[t][e] = 0.0f;

    float rs0 = 0.0f, rs1 = 0.0f;
    float R0 = exp2f(lg2 * (float)(il0 - 64));
    float R1 = exp2f(lg2 * (float)(il1 - 64));
    const float gstep = exp2f(lg2 * (float)BN);

    int buf = 0;
    for (int j0 = j0start; j0 >= 0; j0 -= BN) {
        const bool haveNext = (j0 - BN) >= 0;
        const uint32_t KB = KsU + buf * KV_TILE_BYTES;
        const uint32_t VB = VsU + buf * KV_TILE_BYTES;
        const int jn = j0 - BN;

        // ---- issue async staging of next tile into the other buffer ----
        if (haveNext) {
            const __half* ksrc = kh + (size_t)jn * DKc;
            const __half* vsrc = vh + (size_t)jn * DVc;
            const uint32_t kdst = KsU + (buf ^ 1) * KV_TILE_BYTES;
            const uint32_t vdst = VsU + (buf ^ 1) * KV_TILE_BYTES;
            #pragma unroll
            for (int t = 0; t < 2; t++) {
                int idx = tid + t * NTHREADS;
                int n   = idx >> 4;
                int c   = idx & 15;
                CP_ASYNC16(kdst + (uint32_t)(n * KV_STRIDE + c * 8) * 2, ksrc + n * DKc + c * 8);
                CP_ASYNC16(vdst + (uint32_t)(n * KV_STRIDE + c * 8) * 2, vsrc + n * DVc + c * 8);
            }
            CP_COMMIT();
        }

        // ---- GEMM1: S(128x64) = Q K^T, warp tile 16x32 ----
        float scr[4][4];
        #pragma unroll
        for (int t = 0; t < 4; t++)
            #pragma unroll
            for (int e = 0; e < 4; e++) scr[t][e] = 0.0f;

        #pragma unroll
        for (int kt = 0; kt < 8; kt++) {
            #pragma unroll
            for (int tt = 0; tt < 2; tt++) {
                uint32_t b0, b1, b2, b3;
                uint32_t addr = KB + ((wn * 32 + tt * 16 + kb_row) * KV_STRIDE
                                      + kt * 16 + kb_col8) * 2;
                ldsm4(b0, b1, b2, b3, addr);
                mma_f16(scr[tt * 2],     qa[kt][0], qa[kt][1], qa[kt][2], qa[kt][3], b0, b1);
                mma_f16(scr[tt * 2 + 1], qa[kt][0], qa[kt][1], qa[kt][2], qa[kt][3], b2, b3);
            }
        }

        // ---- decay + causal mask + rowsum, stage S ----
        const int doff = i0 - j0;          // -64, 0, 64, ...
        const bool diag = (doff < 64);
        #pragma unroll
        for (int t = 0; t < 4; t++) {
            const int jb = wn * 32 + t * 8 + 2 * lc;
            const float c0 = Cs[jb];
            const float c1 = Cs[jb + 1];
            float v0 = scr[t][0] * R0 * c0;
            float v1 = scr[t][1] * R0 * c1;
            float v2 = scr[t][2] * R1 * c0;
            float v3 = scr[t][3] * R1 * c1;
            if (diag) {
                const int th0 = il0 + doff;
                const int th1 = il1 + doff;
                if (jb     > th0) v0 = 0.0f;
                if (jb + 1 > th0) v1 = 0.0f;
                if (jb     > th1) v2 = 0.0f;
                if (jb + 1 > th1) v3 = 0.0f;
            }
            rs0 += v0 + v1;
            rs1 += v2 + v3;
            *(__half2*)(SsH + il0 * S_STRIDE + jb) = __floats2half2_rn(v0, v1);
            *(__half2*)(SsH + il1 * S_STRIDE + jb) = __floats2half2_rn(v2, v3);
        }
        R0 *= gstep;
        R1 *= gstep;
        __syncthreads();   // S visible

        // ---- GEMM2: O(128x128) += S @ V, warp tile 16x64 ----
        #pragma unroll
        for (int kt2 = 0; kt2 < 4; kt2++) {
            uint32_t sa0, sa1, sa2, sa3;
            uint32_t saddr = SsU + ((wm * 16 + a_row) * S_STRIDE + kt2 * 16 + a_col8) * 2;
            ldsm4(sa0, sa1, sa2, sa3, saddr);
            #pragma unroll
            for (int dt = 0; dt < 4; dt++) {
                uint32_t b0, b1, b2, b3;
                uint32_t vaddr = VB + ((kt2 * 16 + a_row) * KV_STRIDE
                                       + wn * 64 + dt * 16 + a_col8) * 2;
                ldsm4t(b0, b1, b2, b3, vaddr);
                mma_f16(oc[dt * 2],     sa0, sa1, sa2, sa3, b0, b1);
                mma_f16(oc[dt * 2 + 1], sa0, sa1, sa2, sa3, b2, b3);
            }
        }

        // ---- drain async staging, then release buffers ----
        if (haveNext) CP_WAIT0();
        __syncthreads();

        buf ^= 1;
    }

    // ---- rowsum reduce: lane quad, then across the 2 wn warps via smem ----
    rs0 += __shfl_xor_sync(0xffffffffu, rs0, 1);
    rs0 += __shfl_xor_sync(0xffffffffu, rs0, 2);
    rs1 += __shfl_xor_sync(0xffffffffu, rs1, 1);
    rs1 += __shfl_xor_sync(0xffffffffu, rs1, 2);

    if (wn == 0 && lc == 0) { RSs[il0] = rs0; RSs[il1] = rs1; }
    __syncthreads();
    if (wn == 1 && lc == 0) { RSs[il0] += rs0; RSs[il1] += rs1; }
    __syncthreads();

    const float dn0 = 1.0f / fmaxf(fabsf(RSs[il0]), 1.0f);
    const float dn1 = 1.0f / fmaxf(fabsf(RSs[il1]), 1.0f);

    float ssq0 = 0.0f, ssq1 = 0.0f;
    #pragma unroll
    for (int t = 0; t < 8; t++) {
        oc[t][0] *= dn0; oc[t][1] *= dn0;
        oc[t][2] *= dn1; oc[t][3] *= dn1;
        ssq0 += oc[t][0] * oc[t][0] + oc[t][1] * oc[t][1];
        ssq1 += oc[t][2] * oc[t][2] + oc[t][3] * oc[t][3];
    }
    ssq0 += __shfl_xor_sync(0xffffffffu, ssq0, 1);
    ssq0 += __shfl_xor_sync(0xffffffffu, ssq0, 2);
    ssq1 += __shfl_xor_sync(0xffffffffu, ssq1, 1);
    ssq1 += __shfl_xor_sync(0xffffffffu, ssq1, 2);

    if (wn == 0 && lc == 0) { SQs[il0] = ssq0; SQs[il1] = ssq1; }
    __syncthreads();
    if (wn == 1 && lc == 0) { SQs[il0] += ssq0; SQs[il1] += ssq1; }
    __syncthreads();

    const float sc0 = rsqrtf(SQs[il0] * (1.0f / (float)DVc) + 1e-6f);
    const float sc1 = rsqrtf(SQs[il1] * (1.0f / (float)DVc) + 1e-6f);

    float* po0 = out + (((size_t)b * Lc + (i0 + il0)) * Hc + h) * DVc;
    float* po1 = out + (((size_t)b * Lc + (i0 + il1)) * Hc + h) * DVc;
    #pragma unroll
    for (int t = 0; t < 8; t++) {
        const int dt = t >> 1, n8 = t & 1;
        const int d = wn * 64 + dt * 16 + n8 * 8 + 2 * lc;
        float2 w0, w1;
        w0.x = oc[t][0] * sc0; w0.y = oc[t][1] * sc0;
        w1.x = oc[t][2] * sc1; w1.y = oc[t][3] * sc1;
        *(float2*)(po0 + d) = w0;
        *(float2*)(po1 + d) = w1;
    }
}

extern "C" void kernel_launch(void* const* d_in, const int* in_sizes, int n_in,
                              void* d_out, int out_size)
{
    const float* q = (const float*)d_in[0];
    const float* k = (const float*)d_in[1];
    const float* v = (const float*)d_in[2];
    float* out = (float*)d_out;

    // pre-pass: K/V fp32 -> fp16 (8388608 elems = 2097152 float4s)
    cvt_kv_kernel<<<(unsigned)(KV_ELEMS / 4 / 256), 256>>>(k, v);

    cudaFuncSetAttribute(retnet_f16_kernel,
                         cudaFuncAttributeMaxDynamicSharedMemorySize,
                         (int)SMEM_BYTES);
    dim3 grid(Lc / BM, Bc * Hc);   // (16, 32)
    retnet_f16_kernel<<<grid, NTHREADS, SMEM_BYTES>>>(q, out);
}

// round 10
// speedup vs baseline: 2.4127x; 1.0224x over previous
#include <cuda_runtime.h>
#include <cuda_fp16.h>
#include <cstdint>

// RetNet parallel retention, fused fp16 mma.sync m16n8k16 + ldmatrix.
// R10: FA2-style S-in-registers (warp tile 16 x full-BN), 1 barrier/iter,
//      no S smem, no cross-warp reductions. fp16 K/V prepass + cp.async staging.
// B=2, H=16, L=2048, DK=DV=128.
namespace {
constexpr int Lc  = 2048;
constexpr int Hc  = 16;
constexpr int Bc  = 2;
constexpr int DKc = 128;
constexpr int DVc = 128;
constexpr int BM  = 128;
constexpr int BN  = 64;
constexpr int KV_STRIDE = 136;   // halves per row (272B)
constexpr int NTHREADS  = 256;   // 8 warps, each: 16 rows x full width
constexpr int KV_TILE_H = 64 * KV_STRIDE;

// smem: KsH[2][64][136] VsH[2][64][136] (half) + Cs[64] (float)
constexpr size_t SMEM_BYTES = (size_t)(4 * KV_TILE_H) * 2 + 64 * 4;

constexpr size_t KV_ELEMS = (size_t)Bc * Hc * Lc * DKc;   // 8388608
}

__device__ __half g_kh[KV_ELEMS];
__device__ __half g_vh[KV_ELEMS];

__device__ __forceinline__ void ldsm4(uint32_t& r0, uint32_t& r1, uint32_t& r2, uint32_t& r3,
                                      uint32_t addr) {
    asm volatile("ldmatrix.sync.aligned.m8n8.x4.shared.b16 {%0,%1,%2,%3}, [%4];"
                 : "=r"(r0), "=r"(r1), "=r"(r2), "=r"(r3) : "r"(addr));
}
__device__ __forceinline__ void ldsm4t(uint32_t& r0, uint32_t& r1, uint32_t& r2, uint32_t& r3,
                                       uint32_t addr) {
    asm volatile("ldmatrix.sync.aligned.m8n8.x4.trans.shared.b16 {%0,%1,%2,%3}, [%4];"
                 : "=r"(r0), "=r"(r1), "=r"(r2), "=r"(r3) : "r"(addr));
}
__device__ __forceinline__ void mma_f16(float c[4],
                                        uint32_t a0, uint32_t a1, uint32_t a2, uint32_t a3,
                                        uint32_t b0, uint32_t b1) {
    asm volatile(
        "mma.sync.aligned.m16n8k16.row.col.f32.f16.f16.f32 "
        "{%0,%1,%2,%3}, {%4,%5,%6,%7}, {%8,%9}, {%0,%1,%2,%3};\n"
        : "+f"(c[0]), "+f"(c[1]), "+f"(c[2]), "+f"(c[3])
        : "r"(a0), "r"(a1), "r"(a2), "r"(a3), "r"(b0), "r"(b1));
}
__device__ __forceinline__ uint32_t h2bits(__half2 h) {
    return *reinterpret_cast<uint32_t*>(&h);
}

#define CP_ASYNC16(dst, src) \
    asm volatile("cp.async.cg.shared.global [%0], [%1], 16;" :: "r"(dst), "l"(src) : "memory")
#define CP_COMMIT() asm volatile("cp.async.commit_group;" ::: "memory")
#define CP_WAIT0()  asm volatile("cp.async.wait_group 0;"  ::: "memory")

// ---- pre-pass: fp32 K/V -> fp16 device globals ----
__global__ __launch_bounds__(256, 4)
void cvt_kv_kernel(const float* __restrict__ k, const float* __restrict__ v)
{
    size_t i = (size_t)blockIdx.x * blockDim.x + threadIdx.x;   // over float4s
    float4 a = ((const float4*)k)[i];
    uint2 uk;
    uk.x = h2bits(__floats2half2_rn(a.x, a.y));
    uk.y = h2bits(__floats2half2_rn(a.z, a.w));
    ((uint2*)g_kh)[i] = uk;
    float4 bvec = ((const float4*)v)[i];
    uint2 uv;
    uv.x = h2bits(__floats2half2_rn(bvec.x, bvec.y));
    uv.y = h2bits(__floats2half2_rn(bvec.z, bvec.w));
    ((uint2*)g_vh)[i] = uv;
}

__global__ __launch_bounds__(NTHREADS, 1)
void retnet_f16_kernel(const float* __restrict__ q,
                       float* __restrict__ out)
{
    extern __shared__ __align__(16) char smraw[];
    __half* KsH = reinterpret_cast<__half*>(smraw);          // [2][64][136]
    __half* VsH = KsH + 2 * KV_TILE_H;                       // [2][64][136]
    float*  Cs  = reinterpret_cast<float*>(VsH + 2 * KV_TILE_H);  // [64]

    const uint32_t KsU = (uint32_t)__cvta_generic_to_shared(KsH);
    const uint32_t VsU = (uint32_t)__cvta_generic_to_shared(VsH);
    constexpr uint32_t KV_TILE_BYTES = KV_TILE_H * 2;

    const int tid  = threadIdx.x;
    const int lane = tid & 31;
    const int warp = tid >> 5;    // 0..7 : 16-row group (full width)
    const int lr   = lane >> 2;
    const int lc   = lane & 3;

    // ldmatrix lane patterns (validated R5-R9)
    const int l7 = lane & 7;
    const int g  = lane >> 3;
    const int a_row   = l7 + (g & 1) * 8;   // A-pattern rows / V-trans rows
    const int a_col8  = (g >> 1) * 8;
    const int kb_row  = l7 + (g >> 1) * 8;  // K B-pattern
    const int kb_col8 = (g & 1) * 8;

    const int bh = blockIdx.y;
    const int b  = bh >> 4;
    const int h  = bh & 15;
    const int m_block = (int)(gridDim.x - 1) - (int)blockIdx.x;  // heavy first
    const int i0 = m_block * BM;

    const float*  qb = q + (size_t)bh * Lc * DKc;
    const __half* kh = g_kh + (size_t)bh * Lc * DKc;
    const __half* vh = g_vh + (size_t)bh * Lc * DVc;

    const float lg2 = log1pf(-exp2f(-5.0f - (float)h)) * 1.4426950408889634f;
    if (tid < 64) Cs[tid] = exp2f(-lg2 * (float)tid);

    const int il0 = warp * 16 + lr;   // 0..127
    const int il1 = il0 + 8;

    // ---- stage Q (128x128 fp32->fp16) across K double-buffer region, pull A-frags ----
    #pragma unroll
    for (int t = 0; t < 16; t++) {
        int idx = tid + t * NTHREADS;
        int r   = idx >> 5;        // 0..127
        int c   = idx & 31;
        float4 gld = *(const float4*)(qb + (size_t)(i0 + r) * DKc + c * 4);
        uint2 u;
        u.x = h2bits(__floats2half2_rn(gld.x, gld.y));
        u.y = h2bits(__floats2half2_rn(gld.z, gld.w));
        *(uint2*)(KsH + r * KV_STRIDE + c * 4) = u;
    }
    __syncthreads();

    uint32_t qa[8][4];
    #pragma unroll
    for (int kt = 0; kt < 8; kt++) {
        uint32_t addr = KsU + ((warp * 16 + a_row) * KV_STRIDE + kt * 16 + a_col8) * 2;
        ldsm4(qa[kt][0], qa[kt][1], qa[kt][2], qa[kt][3], addr);
    }
    __syncthreads();

    // ---- stage tile 0 (K + V) via cp.async at j0start = i0 + 64 ----
    const int j0start = i0 + BM - BN;
    {
        const __half* ksrc = kh + (size_t)j0start * DKc;
        const __half* vsrc = vh + (size_t)j0start * DVc;
        #pragma unroll
        for (int t = 0; t < 4; t++) {
            int idx = tid + t * NTHREADS;
            int n   = idx >> 4;        // 0..63
            int c   = idx & 15;        // 16B chunk
            CP_ASYNC16(KsU + (uint32_t)(n * KV_STRIDE + c * 8) * 2, ksrc + n * DKc + c * 8);
            CP_ASYNC16(VsU + (uint32_t)(n * KV_STRIDE + c * 8) * 2, vsrc + n * DVc + c * 8);
        }
        CP_COMMIT();
        CP_WAIT0();
    }
    __syncthreads();

    float oc[16][4];
    #pragma unroll
    for (int t = 0; t < 16; t++)
        #pragma unroll
        for (int e = 0; e < 4; e++) oc[t][e] = 0.0f;

    float rs0 = 0.0f, rs1 = 0.0f;
    float R0 = exp2f(lg2 * (float)(il0 - 64));
    float R1 = exp2f(lg2 * (float)(il1 - 64));
    const float gstep = exp2f(lg2 * (float)BN);

    int buf = 0;
    for (int j0 = j0start; j0 >= 0; j0 -= BN) {
        const bool haveNext = (j0 - BN) >= 0;
        const uint32_t KB = KsU + buf * KV_TILE_BYTES;
        const uint32_t VB = VsU + buf * KV_TILE_BYTES;
        const int jn = j0 - BN;

        // ---- issue async staging of next tile into the other buffer ----
        if (haveNext) {
            const __half* ksrc = kh + (size_t)jn * DKc;
            const __half* vsrc = vh + (size_t)jn * DVc;
            const uint32_t kdst = KsU + (buf ^ 1) * KV_TILE_BYTES;
            const uint32_t vdst = VsU + (buf ^ 1) * KV_TILE_BYTES;
            #pragma unroll
            for (int t = 0; t < 4; t++) {
                int idx = tid + t * NTHREADS;
                int n   = idx >> 4;
                int c   = idx & 15;
                CP_ASYNC16(kdst + (uint32_t)(n * KV_STRIDE + c * 8) * 2, ksrc + n * DKc + c * 8);
                CP_ASYNC16(vdst + (uint32_t)(n * KV_STRIDE + c * 8) * 2, vsrc + n * DVc + c * 8);
            }
            CP_COMMIT();
        }

        // ---- GEMM1: S(16 x 64 per warp) = Q K^T ----
        float scr[8][4];
        #pragma unroll
        for (int t = 0; t < 8; t++)
            #pragma unroll
            for (int e = 0; e < 4; e++) scr[t][e] = 0.0f;

        #pragma unroll
        for (int kt = 0; kt < 8; kt++) {
            #pragma unroll
            for (int nt = 0; nt < 4; nt++) {
                uint32_t b0, b1, b2, b3;
                uint32_t addr = KB + ((nt * 16 + kb_row) * KV_STRIDE + kt * 16 + kb_col8) * 2;
                ldsm4(b0, b1, b2, b3, addr);
                mma_f16(scr[nt * 2],     qa[kt][0], qa[kt][1], qa[kt][2], qa[kt][3], b0, b1);
                mma_f16(scr[nt * 2 + 1], qa[kt][0], qa[kt][1], qa[kt][2], qa[kt][3], b2, b3);
            }
        }

        // ---- decay + causal mask + rowsum + repack to fp16 A-fragments (registers!) ----
        const int doff = i0 - j0;          // -64, 0, 64, ...
        const bool diag = (doff < 64);
        uint32_t sa[4][4];                 // A-frags for GEMM2, k-blocks of 16
        #pragma unroll
        for (int t = 0; t < 8; t++) {
            const int jb = t * 8 + 2 * lc;
            const float c0 = Cs[jb];
            const float c1 = Cs[jb + 1];
            float v0 = scr[t][0] * R0 * c0;
            float v1 = scr[t][1] * R0 * c1;
            float v2 = scr[t][2] * R1 * c0;
            float v3 = scr[t][3] * R1 * c1;
            if (diag) {
                const int th0 = il0 + doff;
                const int th1 = il1 + doff;
                if (jb     > th0) v0 = 0.0f;
                if (jb + 1 > th0) v1 = 0.0f;
                if (jb     > th1) v2 = 0.0f;
                if (jb + 1 > th1) v3 = 0.0f;
            }
            rs0 += v0 + v1;
            rs1 += v2 + v3;
            // S-tile t (cols 8t..8t+7) -> A-frag k-block u = t/2, halves (t&1)
            const int u  = t >> 1;
            const int hi = (t & 1) * 2;
            sa[u][hi]     = h2bits(__floats2half2_rn(v0, v1));   // row lr
            sa[u][hi + 1] = h2bits(__floats2half2_rn(v2, v3));   // row lr+8
        }
        R0 *= gstep;
        R1 *= gstep;

        // sa[u] currently = {a0(row lr,k lo8), a1(row lr+8,k lo8), a2(row lr,k hi8), a3(...)}?
        // mapping check: t=2u   -> k cols [16u, 16u+8)  = (a0, a1)
        //                t=2u+1 -> k cols [16u+8,16u+16) = (a2, a3)
        // sa[u][0]=t2u row lr -> a0 ; sa[u][1]=t2u row lr+8 -> a1 ;
        // sa[u][2]=t2u+1 row lr -> a2 ; sa[u][3]=t2u+1 row lr+8 -> a3.  OK.

        // ---- GEMM2: O(16 x 128 per warp) += S @ V ----
        #pragma unroll
        for (int kt2 = 0; kt2 < 4; kt2++) {
            #pragma unroll
            for (int dt = 0; dt < 8; dt++) {
                uint32_t b0, b1, b2, b3;
                uint32_t vaddr = VB + ((kt2 * 16 + a_row) * KV_STRIDE
                                       + dt * 16 + a_col8) * 2;
                ldsm4t(b0, b1, b2, b3, vaddr);
                mma_f16(oc[dt * 2],     sa[kt2][0], sa[kt2][1], sa[kt2][2], sa[kt2][3], b0, b1);
                mma_f16(oc[dt * 2 + 1], sa[kt2][0], sa[kt2][1], sa[kt2][2], sa[kt2][3], b2, b3);
            }
        }

        // ---- drain async staging, release buffers (single barrier per iter) ----
        if (haveNext) CP_WAIT0();
        __syncthreads();

        buf ^= 1;
    }

    // ---- rowsum: warp owns all 64 cols of its rows -> 2 shfls, done ----
    rs0 += __shfl_xor_sync(0xffffffffu, rs0, 1);
    rs0 += __shfl_xor_sync(0xffffffffu, rs0, 2);
    rs1 += __shfl_xor_sync(0xffffffffu, rs1, 1);
    rs1 += __shfl_xor_sync(0xffffffffu, rs1, 2);

    const float dn0 = 1.0f / fmaxf(fabsf(rs0), 1.0f);
    const float dn1 = 1.0f / fmaxf(fabsf(rs1), 1.0f);

    float ssq0 = 0.0f, ssq1 = 0.0f;
    #pragma unroll
    for (int t = 0; t < 16; t++) {
        oc[t][0] *= dn0; oc[t][1] *= dn0;
        oc[t][2] *= dn1; oc[t][3] *= dn1;
        ssq0 += oc[t][0] * oc[t][0] + oc[t][1] * oc[t][1];
        ssq1 += oc[t][2] * oc[t][2] + oc[t][3] * oc[t][3];
    }
    ssq0 += __shfl_xor_sync(0xffffffffu, ssq0, 1);
    ssq0 += __shfl_xor_sync(0xffffffffu, ssq0, 2);
    ssq1 += __shfl_xor_sync(0xffffffffu, ssq1, 1);
    ssq1 += __shfl_xor_sync(0xffffffffu, ssq1, 2);

    const float sc0 = rsqrtf(ssq0 * (1.0f / (float)DVc) + 1e-6f);
    const float sc1 = rsqrtf(ssq1 * (1.0f / (float)DVc) + 1e-6f);

    float* po0 = out + (((size_t)b * Lc + (i0 + il0)) * Hc + h) * DVc;
    float* po1 = out + (((size_t)b * Lc + (i0 + il1)) * Hc + h) * DVc;
    #pragma unroll
    for (int t = 0; t < 16; t++) {
        const int d = t * 8 + 2 * lc;
        float2 w0, w1;
        w0.x = oc[t][0] * sc0; w0.y = oc[t][1] * sc0;
        w1.x = oc[t][2] * sc1; w1.y = oc[t][3] * sc1;
        *(float2*)(po0 + d) = w0;
        *(float2*)(po1 + d) = w1;
    }
}

extern "C" void kernel_launch(void* const* d_in, const int* in_sizes, int n_in,
                              void* d_out, int out_size)
{
    const float* q = (const float*)d_in[0];
    const float* k = (const float*)d_in[1];
    const float* v = (const float*)d_in[2];
    float* out = (float*)d_out;

    // pre-pass: K/V fp32 -> fp16
    cvt_kv_kernel<<<(unsigned)(KV_ELEMS / 4 / 256), 256>>>(k, v);

    cudaFuncSetAttribute(retnet_f16_kernel,
                         cudaFuncAttributeMaxDynamicSharedMemorySize,
                         (int)SMEM_BYTES);
    dim3 grid(Lc / BM, Bc * Hc);   // (16, 32)
    retnet_f16_kernel<<<grid, NTHREADS, SMEM_BYTES>>>(q, out);
}

// round 11
// speedup vs baseline: 2.5810x; 1.0698x over previous
#include <cuda_runtime.h>
#include <cuda_fp16.h>
#include <cstdint>

// RetNet parallel retention, fused fp16 mma.sync m16n8k16 + ldmatrix.
// R11: BM=64, 128 threads, 4 warps, 2 CTAs/SM (two independent barrier domains).
//      FA2-style S-in-registers, 1 barrier/iter, fp16 K/V prepass + cp.async.
// B=2, H=16, L=2048, DK=DV=128.
namespace {
constexpr int Lc  = 2048;
constexpr int Hc  = 16;
constexpr int Bc  = 2;
constexpr int DKc = 128;
constexpr int DVc = 128;
constexpr int BM  = 64;
constexpr int BN  = 64;
constexpr int KV_STRIDE = 136;   // halves per row (272B)
constexpr int NTHREADS  = 128;   // 4 warps, each: 16 rows x full width
constexpr int KV_TILE_H = 64 * KV_STRIDE;

// smem: KsH[2][64][136] VsH[2][64][136] (half) + Cs[64] (float)  (~70 KB -> 2 CTAs/SM)
constexpr size_t SMEM_BYTES = (size_t)(4 * KV_TILE_H) * 2 + 64 * 4;

constexpr size_t KV_ELEMS = (size_t)Bc * Hc * Lc * DKc;   // 8388608
}

__device__ __half g_kh[KV_ELEMS];
__device__ __half g_vh[KV_ELEMS];

__device__ __forceinline__ void ldsm4(uint32_t& r0, uint32_t& r1, uint32_t& r2, uint32_t& r3,
                                      uint32_t addr) {
    asm volatile("ldmatrix.sync.aligned.m8n8.x4.shared.b16 {%0,%1,%2,%3}, [%4];"
                 : "=r"(r0), "=r"(r1), "=r"(r2), "=r"(r3) : "r"(addr));
}
__device__ __forceinline__ void ldsm4t(uint32_t& r0, uint32_t& r1, uint32_t& r2, uint32_t& r3,
                                       uint32_t addr) {
    asm volatile("ldmatrix.sync.aligned.m8n8.x4.trans.shared.b16 {%0,%1,%2,%3}, [%4];"
                 : "=r"(r0), "=r"(r1), "=r"(r2), "=r"(r3) : "r"(addr));
}
__device__ __forceinline__ void mma_f16(float c[4],
                                        uint32_t a0, uint32_t a1, uint32_t a2, uint32_t a3,
                                        uint32_t b0, uint32_t b1) {
    asm volatile(
        "mma.sync.aligned.m16n8k16.row.col.f32.f16.f16.f32 "
        "{%0,%1,%2,%3}, {%4,%5,%6,%7}, {%8,%9}, {%0,%1,%2,%3};\n"
        : "+f"(c[0]), "+f"(c[1]), "+f"(c[2]), "+f"(c[3])
        : "r"(a0), "r"(a1), "r"(a2), "r"(a3), "r"(b0), "r"(b1));
}
__device__ __forceinline__ uint32_t h2bits(__half2 h) {
    return *reinterpret_cast<uint32_t*>(&h);
}

#define CP_ASYNC16(dst, src) \
    asm volatile("cp.async.cg.shared.global [%0], [%1], 16;" :: "r"(dst), "l"(src) : "memory")
#define CP_COMMIT() asm volatile("cp.async.commit_group;" ::: "memory")
#define CP_WAIT0()  asm volatile("cp.async.wait_group 0;"  ::: "memory")

// ---- pre-pass: fp32 K/V -> fp16 device globals ----
__global__ __launch_bounds__(256, 4)
void cvt_kv_kernel(const float* __restrict__ k, const float* __restrict__ v)
{
    size_t i = (size_t)blockIdx.x * blockDim.x + threadIdx.x;   // over float4s
    float4 a = ((const float4*)k)[i];
    uint2 uk;
    uk.x = h2bits(__floats2half2_rn(a.x, a.y));
    uk.y = h2bits(__floats2half2_rn(a.z, a.w));
    ((uint2*)g_kh)[i] = uk;
    float4 bvec = ((const float4*)v)[i];
    uint2 uv;
    uv.x = h2bits(__floats2half2_rn(bvec.x, bvec.y));
    uv.y = h2bits(__floats2half2_rn(bvec.z, bvec.w));
    ((uint2*)g_vh)[i] = uv;
}

__global__ __launch_bounds__(NTHREADS)
void retnet_f16_kernel(const float* __restrict__ q,
                       float* __restrict__ out)
{
    extern __shared__ __align__(16) char smraw[];
    __half* KsH = reinterpret_cast<__half*>(smraw);          // [2][64][136]
    __half* VsH = KsH + 2 * KV_TILE_H;                       // [2][64][136]
    float*  Cs  = reinterpret_cast<float*>(VsH + 2 * KV_TILE_H);  // [64]

    const uint32_t KsU = (uint32_t)__cvta_generic_to_shared(KsH);
    const uint32_t VsU = (uint32_t)__cvta_generic_to_shared(VsH);
    constexpr uint32_t KV_TILE_BYTES = KV_TILE_H * 2;

    const int tid  = threadIdx.x;
    const int lane = tid & 31;
    const int warp = tid >> 5;    // 0..3 : 16-row group (full width)
    const int lr   = lane >> 2;
    const int lc   = lane & 3;

    // ldmatrix lane patterns (validated R5-R10)
    const int l7 = lane & 7;
    const int g  = lane >> 3;
    const int a_row   = l7 + (g & 1) * 8;   // A-pattern rows / V-trans rows
    const int a_col8  = (g >> 1) * 8;
    const int kb_row  = l7 + (g >> 1) * 8;  // K B-pattern
    const int kb_col8 = (g & 1) * 8;

    const int bh = blockIdx.y;
    const int b  = bh >> 4;
    const int h  = bh & 15;
    const int m_block = (int)(gridDim.x - 1) - (int)blockIdx.x;  // heavy first
    const int i0 = m_block * BM;

    const float*  qb = q + (size_t)bh * Lc * DKc;
    const __half* kh = g_kh + (size_t)bh * Lc * DKc;
    const __half* vh = g_vh + (size_t)bh * Lc * DVc;

    const float lg2 = log1pf(-exp2f(-5.0f - (float)h)) * 1.4426950408889634f;
    if (tid < 64) Cs[tid] = exp2f(-lg2 * (float)tid);

    const int il0 = warp * 16 + lr;   // 0..63
    const int il1 = il0 + 8;

    // ---- stage Q (64x128 fp32->fp16) into K buffer 0, pull A-frags ----
    #pragma unroll
    for (int t = 0; t < 16; t++) {
        int idx = tid + t * NTHREADS;
        int r   = idx >> 5;        // 0..63
        int c   = idx & 31;
        float4 gld = *(const float4*)(qb + (size_t)(i0 + r) * DKc + c * 4);
        uint2 u;
        u.x = h2bits(__floats2half2_rn(gld.x, gld.y));
        u.y = h2bits(__floats2half2_rn(gld.z, gld.w));
        *(uint2*)(KsH + r * KV_STRIDE + c * 4) = u;
    }
    __syncthreads();

    uint32_t qa[8][4];
    #pragma unroll
    for (int kt = 0; kt < 8; kt++) {
        uint32_t addr = KsU + ((warp * 16 + a_row) * KV_STRIDE + kt * 16 + a_col8) * 2;
        ldsm4(qa[kt][0], qa[kt][1], qa[kt][2], qa[kt][3], addr);
    }
    __syncthreads();

    // ---- stage tile 0 (K + V) via cp.async at j0start = i0 (BM == BN) ----
    const int j0start = i0;
    {
        const __half* ksrc = kh + (size_t)j0start * DKc;
        const __half* vsrc = vh + (size_t)j0start * DVc;
        #pragma unroll
        for (int t = 0; t < 8; t++) {
            int idx = tid + t * NTHREADS;
            int n   = idx >> 4;        // 0..63
            int c   = idx & 15;        // 16B chunk
            CP_ASYNC16(KsU + (uint32_t)(n * KV_STRIDE + c * 8) * 2, ksrc + n * DKc + c * 8);
            CP_ASYNC16(VsU + (uint32_t)(n * KV_STRIDE + c * 8) * 2, vsrc + n * DVc + c * 8);
        }
        CP_COMMIT();
        CP_WAIT0();
    }
    __syncthreads();

    float oc[16][4];
    #pragma unroll
    for (int t = 0; t < 16; t++)
        #pragma unroll
        for (int e = 0; e < 4; e++) oc[t][e] = 0.0f;

    float rs0 = 0.0f, rs1 = 0.0f;
    float R0 = exp2f(lg2 * (float)il0);
    float R1 = exp2f(lg2 * (float)il1);
    const float gstep = exp2f(lg2 * (float)BN);

    int buf = 0;
    for (int j0 = j0start; j0 >= 0; j0 -= BN) {
        const bool haveNext = (j0 - BN) >= 0;
        const uint32_t KB = KsU + buf * KV_TILE_BYTES;
        const uint32_t VB = VsU + buf * KV_TILE_BYTES;
        const int jn = j0 - BN;

        // ---- issue async staging of next tile into the other buffer ----
        if (haveNext) {
            const __half* ksrc = kh + (size_t)jn * DKc;
            const __half* vsrc = vh + (size_t)jn * DVc;
            const uint32_t kdst = KsU + (buf ^ 1) * KV_TILE_BYTES;
            const uint32_t vdst = VsU + (buf ^ 1) * KV_TILE_BYTES;
            #pragma unroll
            for (int t = 0; t < 8; t++) {
                int idx = tid + t * NTHREADS;
                int n   = idx >> 4;
                int c   = idx & 15;
                CP_ASYNC16(kdst + (uint32_t)(n * KV_STRIDE + c * 8) * 2, ksrc + n * DKc + c * 8);
                CP_ASYNC16(vdst + (uint32_t)(n * KV_STRIDE + c * 8) * 2, vsrc + n * DVc + c * 8);
            }
            CP_COMMIT();
        }

        // ---- GEMM1: S(16 x 64 per warp) = Q K^T ----
        float scr[8][4];
        #pragma unroll
        for (int t = 0; t < 8; t++)
            #pragma unroll
            for (int e = 0; e < 4; e++) scr[t][e] = 0.0f;

        #pragma unroll
        for (int kt = 0; kt < 8; kt++) {
            #pragma unroll
            for (int nt = 0; nt < 4; nt++) {
                uint32_t b0, b1, b2, b3;
                uint32_t addr = KB + ((nt * 16 + kb_row) * KV_STRIDE + kt * 16 + kb_col8) * 2;
                ldsm4(b0, b1, b2, b3, addr);
                mma_f16(scr[nt * 2],     qa[kt][0], qa[kt][1], qa[kt][2], qa[kt][3], b0, b1);
                mma_f16(scr[nt * 2 + 1], qa[kt][0], qa[kt][1], qa[kt][2], qa[kt][3], b2, b3);
            }
        }

        // ---- decay + causal mask + rowsum + repack to fp16 A-fragments (registers) ----
        const int doff = i0 - j0;          // 0, 64, 128, ...
        const bool diag = (doff < 64);     // first iteration only
        uint32_t sa[4][4];                 // A-frags for GEMM2, k-blocks of 16
        #pragma unroll
        for (int t = 0; t < 8; t++) {
            const int jb = t * 8 + 2 * lc;
            const float c0 = Cs[jb];
            const float c1 = Cs[jb + 1];
            float v0 = scr[t][0] * R0 * c0;
            float v1 = scr[t][1] * R0 * c1;
            float v2 = scr[t][2] * R1 * c0;
            float v3 = scr[t][3] * R1 * c1;
            if (diag) {
                const int th0 = il0 + doff;
                const int th1 = il1 + doff;
                if (jb     > th0) v0 = 0.0f;
                if (jb + 1 > th0) v1 = 0.0f;
                if (jb     > th1) v2 = 0.0f;
                if (jb + 1 > th1) v3 = 0.0f;
            }
            rs0 += v0 + v1;
            rs1 += v2 + v3;
            // S-tile t (cols 8t..8t+7) -> A-frag k-block u = t/2, halves (t&1)
            const int u  = t >> 1;
            const int hi = (t & 1) * 2;
            sa[u][hi]     = h2bits(__floats2half2_rn(v0, v1));   // row lr
            sa[u][hi + 1] = h2bits(__floats2half2_rn(v2, v3));   // row lr+8
        }
        R0 *= gstep;
        R1 *= gstep;

        // ---- GEMM2: O(16 x 128 per warp) += S @ V ----
        #pragma unroll
        for (int kt2 = 0; kt2 < 4; kt2++) {
            #pragma unroll
            for (int dt = 0; dt < 8; dt++) {
                uint32_t b0, b1, b2, b3;
                uint32_t vaddr = VB + ((kt2 * 16 + a_row) * KV_STRIDE
                                       + dt * 16 + a_col8) * 2;
                ldsm4t(b0, b1, b2, b3, vaddr);
                mma_f16(oc[dt * 2],     sa[kt2][0], sa[kt2][1], sa[kt2][2], sa[kt2][3], b0, b1);
                mma_f16(oc[dt * 2 + 1], sa[kt2][0], sa[kt2][1], sa[kt2][2], sa[kt2][3], b2, b3);
            }
        }

        // ---- drain async staging, release buffers (single barrier per iter) ----
        if (haveNext) CP_WAIT0();
        __syncthreads();

        buf ^= 1;
    }

    // ---- rowsum: warp owns all 64 cols of its rows -> 2 shfls, done ----
    rs0 += __shfl_xor_sync(0xffffffffu, rs0, 1);
    rs0 += __shfl_xor_sync(0xffffffffu, rs0, 2);
    rs1 += __shfl_xor_sync(0xffffffffu, rs1, 1);
    rs1 += __shfl_xor_sync(0xffffffffu, rs1, 2);

    const float dn0 = 1.0f / fmaxf(fabsf(rs0), 1.0f);
    const float dn1 = 1.0f / fmaxf(fabsf(rs1), 1.0f);

    float ssq0 = 0.0f, ssq1 = 0.0f;
    #pragma unroll
    for (int t = 0; t < 16; t++) {
        oc[t][0] *= dn0; oc[t][1] *= dn0;
        oc[t][2] *= dn1; oc[t][3] *= dn1;
        ssq0 += oc[t][0] * oc[t][0] + oc[t][1] * oc[t][1];
        ssq1 += oc[t][2] * oc[t][2] + oc[t][3] * oc[t][3];
    }
    ssq0 += __shfl_xor_sync(0xffffffffu, ssq0, 1);
    ssq0 += __shfl_xor_sync(0xffffffffu, ssq0, 2);
    ssq1 += __shfl_xor_sync(0xffffffffu, ssq1, 1);
    ssq1 += __shfl_xor_sync(0xffffffffu, ssq1, 2);

    const float sc0 = rsqrtf(ssq0 * (1.0f / (float)DVc) + 1e-6f);
    const float sc1 = rsqrtf(ssq1 * (1.0f / (float)DVc) + 1e-6f);

    float* po0 = out + (((size_t)b * Lc + (i0 + il0)) * Hc + h) * DVc;
    float* po1 = out + (((size_t)b * Lc + (i0 + il1)) * Hc + h) * DVc;
    #pragma unroll
    for (int t = 0; t < 16; t++) {
        const int d = t * 8 + 2 * lc;
        float2 w0, w1;
        w0.x = oc[t][0] * sc0; w0.y = oc[t][1] * sc0;
        w1.x = oc[t][2] * sc1; w1.y = oc[t][3] * sc1;
        *(float2*)(po0 + d) = w0;
        *(float2*)(po1 + d) = w1;
    }
}

extern "C" void kernel_launch(void* const* d_in, const int* in_sizes, int n_in,
                              void* d_out, int out_size)
{
    const float* q = (const float*)d_in[0];
    const float* k = (const float*)d_in[1];
    const float* v = (const float*)d_in[2];
    float* out = (float*)d_out;

    // pre-pass: K/V fp32 -> fp16
    cvt_kv_kernel<<<(unsigned)(KV_ELEMS / 4 / 256), 256>>>(k, v);

    cudaFuncSetAttribute(retnet_f16_kernel,
                         cudaFuncAttributeMaxDynamicSharedMemorySize,
                         (int)SMEM_BYTES);
    dim3 grid(Lc / BM, Bc * Hc);   // (32, 32)
    retnet_f16_kernel<<<grid, NTHREADS, SMEM_BYTES>>>(q, out);
}

// round 12
// speedup vs baseline: 2.5980x; 1.0066x over previous
#include <cuda_runtime.h>
#include <cuda_fp16.h>
#include <cstdint>

// RetNet parallel retention, fused fp16 mma.sync m16n8k16 + ldmatrix.
// R12: 3 CTAs/SM (launch_bounds(128,3), regs capped at 170).
//      BM=64, 4 warps, FA2-style S-in-registers, 1 barrier/iter,
//      fp16 K/V prepass + cp.async double-buffered staging.
// B=2, H=16, L=2048, DK=DV=128.
namespace {
constexpr int Lc  = 2048;
constexpr int Hc  = 16;
constexpr int Bc  = 2;
constexpr int DKc = 128;
constexpr int DVc = 128;
constexpr int BM  = 64;
constexpr int BN  = 64;
constexpr int KV_STRIDE = 136;   // halves per row (272B)
constexpr int NTHREADS  = 128;   // 4 warps, each: 16 rows x full width
constexpr int KV_TILE_H = 64 * KV_STRIDE;

// smem: KsH[2][64][136] VsH[2][64][136] (half) + Cs[64] (float)  (~68.2 KB -> 3 CTAs/SM)
constexpr size_t SMEM_BYTES = (size_t)(4 * KV_TILE_H) * 2 + 64 * 4;

constexpr size_t KV_ELEMS = (size_t)Bc * Hc * Lc * DKc;   // 8388608
}

__device__ __half g_kh[KV_ELEMS];
__device__ __half g_vh[KV_ELEMS];

__device__ __forceinline__ void ldsm4(uint32_t& r0, uint32_t& r1, uint32_t& r2, uint32_t& r3,
                                      uint32_t addr) {
    asm volatile("ldmatrix.sync.aligned.m8n8.x4.shared.b16 {%0,%1,%2,%3}, [%4];"
                 : "=r"(r0), "=r"(r1), "=r"(r2), "=r"(r3) : "r"(addr));
}
__device__ __forceinline__ void ldsm4t(uint32_t& r0, uint32_t& r1, uint32_t& r2, uint32_t& r3,
                                       uint32_t addr) {
    asm volatile("ldmatrix.sync.aligned.m8n8.x4.trans.shared.b16 {%0,%1,%2,%3}, [%4];"
                 : "=r"(r0), "=r"(r1), "=r"(r2), "=r"(r3) : "r"(addr));
}
__device__ __forceinline__ void mma_f16(float c[4],
                                        uint32_t a0, uint32_t a1, uint32_t a2, uint32_t a3,
                                        uint32_t b0, uint32_t b1) {
    asm volatile(
        "mma.sync.aligned.m16n8k16.row.col.f32.f16.f16.f32 "
        "{%0,%1,%2,%3}, {%4,%5,%6,%7}, {%8,%9}, {%0,%1,%2,%3};\n"
        : "+f"(c[0]), "+f"(c[1]), "+f"(c[2]), "+f"(c[3])
        : "r"(a0), "r"(a1), "r"(a2), "r"(a3), "r"(b0), "r"(b1));
}
__device__ __forceinline__ uint32_t h2bits(__half2 h) {
    return *reinterpret_cast<uint32_t*>(&h);
}

#define CP_ASYNC16(dst, src) \
    asm volatile("cp.async.cg.shared.global [%0], [%1], 16;" :: "r"(dst), "l"(src) : "memory")
#define CP_COMMIT() asm volatile("cp.async.commit_group;" ::: "memory")
#define CP_WAIT0()  asm volatile("cp.async.wait_group 0;"  ::: "memory")

// ---- pre-pass: fp32 K/V -> fp16 device globals ----
__global__ __launch_bounds__(256, 4)
void cvt_kv_kernel(const float* __restrict__ k, const float* __restrict__ v)
{
    size_t i = (size_t)blockIdx.x * blockDim.x + threadIdx.x;   // over float4s
    float4 a = ((const float4*)k)[i];
    uint2 uk;
    uk.x = h2bits(__floats2half2_rn(a.x, a.y));
    uk.y = h2bits(__floats2half2_rn(a.z, a.w));
    ((uint2*)g_kh)[i] = uk;
    float4 bvec = ((const float4*)v)[i];
    uint2 uv;
    uv.x = h2bits(__floats2half2_rn(bvec.x, bvec.y));
    uv.y = h2bits(__floats2half2_rn(bvec.z, bvec.w));
    ((uint2*)g_vh)[i] = uv;
}

__global__ __launch_bounds__(NTHREADS, 3)
void retnet_f16_kernel(const float* __restrict__ q,
                       float* __restrict__ out)
{
    extern __shared__ __align__(16) char smraw[];
    __half* KsH = reinterpret_cast<__half*>(smraw);          // [2][64][136]
    __half* VsH = KsH + 2 * KV_TILE_H;                       // [2][64][136]
    float*  Cs  = reinterpret_cast<float*>(VsH + 2 * KV_TILE_H);  // [64]

    const uint32_t KsU = (uint32_t)__cvta_generic_to_shared(KsH);
    const uint32_t VsU = (uint32_t)__cvta_generic_to_shared(VsH);
    constexpr uint32_t KV_TILE_BYTES = KV_TILE_H * 2;

    const int tid  = threadIdx.x;
    const int lane = tid & 31;
    const int warp = tid >> 5;    // 0..3 : 16-row group (full width)
    const int lr   = lane >> 2;
    const int lc   = lane & 3;

    // ldmatrix lane patterns (validated R5-R11)
    const int l7 = lane & 7;
    const int g  = lane >> 3;
    const int a_row   = l7 + (g & 1) * 8;   // A-pattern rows / V-trans rows
    const int a_col8  = (g >> 1) * 8;
    const int kb_row  = l7 + (g >> 1) * 8;  // K B-pattern
    const int kb_col8 = (g & 1) * 8;

    const int bh = blockIdx.y;
    const int b  = bh >> 4;
    const int h  = bh & 15;
    const int m_block = (int)(gridDim.x - 1) - (int)blockIdx.x;  // heavy first
    const int i0 = m_block * BM;

    const float*  qb = q + (size_t)bh * Lc * DKc;
    const __half* kh = g_kh + (size_t)bh * Lc * DKc;
    const __half* vh = g_vh + (size_t)bh * Lc * DVc;

    const float lg2 = log1pf(-exp2f(-5.0f - (float)h)) * 1.4426950408889634f;
    if (tid < 64) Cs[tid] = exp2f(-lg2 * (float)tid);

    const int il0 = warp * 16 + lr;   // 0..63
    const int il1 = il0 + 8;

    // ---- stage Q (64x128 fp32->fp16) into K buffer 0, pull A-frags ----
    #pragma unroll
    for (int t = 0; t < 16; t++) {
        int idx = tid + t * NTHREADS;
        int r   = idx >> 5;        // 0..63
        int c   = idx & 31;
        float4 gld = *(const float4*)(qb + (size_t)(i0 + r) * DKc + c * 4);
        uint2 u;
        u.x = h2bits(__floats2half2_rn(gld.x, gld.y));
        u.y = h2bits(__floats2half2_rn(gld.z, gld.w));
        *(uint2*)(KsH + r * KV_STRIDE + c * 4) = u;
    }
    __syncthreads();

    uint32_t qa[8][4];
    #pragma unroll
    for (int kt = 0; kt < 8; kt++) {
        uint32_t addr = KsU + ((warp * 16 + a_row) * KV_STRIDE + kt * 16 + a_col8) * 2;
        ldsm4(qa[kt][0], qa[kt][1], qa[kt][2], qa[kt][3], addr);
    }
    __syncthreads();

    // ---- stage tile 0 (K + V) via cp.async at j0start = i0 (BM == BN) ----
    const int j0start = i0;
    {
        const __half* ksrc = kh + (size_t)j0start * DKc;
        const __half* vsrc = vh + (size_t)j0start * DVc;
        #pragma unroll
        for (int t = 0; t < 8; t++) {
            int idx = tid + t * NTHREADS;
            int n   = idx >> 4;        // 0..63
            int c   = idx & 15;        // 16B chunk
            CP_ASYNC16(KsU + (uint32_t)(n * KV_STRIDE + c * 8) * 2, ksrc + n * DKc + c * 8);
            CP_ASYNC16(VsU + (uint32_t)(n * KV_STRIDE + c * 8) * 2, vsrc + n * DVc + c * 8);
        }
        CP_COMMIT();
        CP_WAIT0();
    }
    __syncthreads();

    float oc[16][4];
    #pragma unroll
    for (int t = 0; t < 16; t++)
        #pragma unroll
        for (int e = 0; e < 4; e++) oc[t][e] = 0.0f;

    float rs0 = 0.0f, rs1 = 0.0f;
    float R0 = exp2f(lg2 * (float)il0);
    float R1 = exp2f(lg2 * (float)il1);
    const float gstep = exp2f(lg2 * (float)BN);

    int buf = 0;
    for (int j0 = j0start; j0 >= 0; j0 -= BN) {
        const bool haveNext = (j0 - BN) >= 0;
        const uint32_t KB = KsU + buf * KV_TILE_BYTES;
        const uint32_t VB = VsU + buf * KV_TILE_BYTES;
        const int jn = j0 - BN;

        // ---- issue async staging of next tile into the other buffer ----
        if (haveNext) {
            const __half* ksrc = kh + (size_t)jn * DKc;
            const __half* vsrc = vh + (size_t)jn * DVc;
            const uint32_t kdst = KsU + (buf ^ 1) * KV_TILE_BYTES;
            const uint32_t vdst = VsU + (buf ^ 1) * KV_TILE_BYTES;
            #pragma unroll
            for (int t = 0; t < 8; t++) {
                int idx = tid + t * NTHREADS;
                int n   = idx >> 4;
                int c   = idx & 15;
                CP_ASYNC16(kdst + (uint32_t)(n * KV_STRIDE + c * 8) * 2, ksrc + n * DKc + c * 8);
                CP_ASYNC16(vdst + (uint32_t)(n * KV_STRIDE + c * 8) * 2, vsrc + n * DVc + c * 8);
            }
            CP_COMMIT();
        }

        // ---- GEMM1: S(16 x 64 per warp) = Q K^T ----
        float scr[8][4];
        #pragma unroll
        for (int t = 0; t < 8; t++)
            #pragma unroll
            for (int e = 0; e < 4; e++) scr[t][e] = 0.0f;

        #pragma unroll
        for (int kt = 0; kt < 8; kt++) {
            #pragma unroll
            for (int nt = 0; nt < 4; nt++) {
                uint32_t b0, b1, b2, b3;
                uint32_t addr = KB + ((nt * 16 + kb_row) * KV_STRIDE + kt * 16 + kb_col8) * 2;
                ldsm4(b0, b1, b2, b3, addr);
                mma_f16(scr[nt * 2],     qa[kt][0], qa[kt][1], qa[kt][2], qa[kt][3], b0, b1);
                mma_f16(scr[nt * 2 + 1], qa[kt][0], qa[kt][1], qa[kt][2], qa[kt][3], b2, b3);
            }
        }

        // ---- decay + causal mask + rowsum + repack to fp16 A-fragments (registers) ----
        const int doff = i0 - j0;          // 0, 64, 128, ...
        const bool diag = (doff < 64);     // first iteration only
        uint32_t sa[4][4];                 // A-frags for GEMM2, k-blocks of 16
        #pragma unroll
        for (int t = 0; t < 8; t++) {
            const int jb = t * 8 + 2 * lc;
            const float c0 = Cs[jb];
            const float c1 = Cs[jb + 1];
            float v0 = scr[t][0] * R0 * c0;
            float v1 = scr[t][1] * R0 * c1;
            float v2 = scr[t][2] * R1 * c0;
            float v3 = scr[t][3] * R1 * c1;
            if (diag) {
                const int th0 = il0 + doff;
                const int th1 = il1 + doff;
                if (jb     > th0) v0 = 0.0f;
                if (jb + 1 > th0) v1 = 0.0f;
                if (jb     > th1) v2 = 0.0f;
                if (jb + 1 > th1) v3 = 0.0f;
            }
            rs0 += v0 + v1;
            rs1 += v2 + v3;
            const int u  = t >> 1;
            const int hi = (t & 1) * 2;
            sa[u][hi]     = h2bits(__floats2half2_rn(v0, v1));   // row lr
            sa[u][hi + 1] = h2bits(__floats2half2_rn(v2, v3));   // row lr+8
        }
        R0 *= gstep;
        R1 *= gstep;

        // ---- GEMM2: O(16 x 128 per warp) += S @ V ----
        #pragma unroll
        for (int kt2 = 0; kt2 < 4; kt2++) {
            #pragma unroll
            for (int dt = 0; dt < 8; dt++) {
                uint32_t b0, b1, b2, b3;
                uint32_t vaddr = VB + ((kt2 * 16 + a_row) * KV_STRIDE
                                       + dt * 16 + a_col8) * 2;
                ldsm4t(b0, b1, b2, b3, vaddr);
                mma_f16(oc[dt * 2],     sa[kt2][0], sa[kt2][1], sa[kt2][2], sa[kt2][3], b0, b1);
                mma_f16(oc[dt * 2 + 1], sa[kt2][0], sa[kt2][1], sa[kt2][2], sa[kt2][3], b2, b3);
            }
        }

        // ---- drain async staging, release buffers (single barrier per iter) ----
        if (haveNext) CP_WAIT0();
        __syncthreads();

        buf ^= 1;
    }

    // ---- rowsum: warp owns all 64 cols of its rows -> 2 shfls, done ----
    rs0 += __shfl_xor_sync(0xffffffffu, rs0, 1);
    rs0 += __shfl_xor_sync(0xffffffffu, rs0, 2);
    rs1 += __shfl_xor_sync(0xffffffffu, rs1, 1);
    rs1 += __shfl_xor_sync(0xffffffffu, rs1, 2);

    const float dn0 = 1.0f / fmaxf(fabsf(rs0), 1.0f);
    const float dn1 = 1.0f / fmaxf(fabsf(rs1), 1.0f);

    float ssq0 = 0.0f, ssq1 = 0.0f;
    #pragma unroll
    for (int t = 0; t < 16; t++) {
        oc[t][0] *= dn0; oc[t][1] *= dn0;
        oc[t][2] *= dn1; oc[t][3] *= dn1;
        ssq0 += oc[t][0] * oc[t][0] + oc[t][1] * oc[t][1];
        ssq1 += oc[t][2] * oc[t][2] + oc[t][3] * oc[t][3];
    }
    ssq0 += __shfl_xor_sync(0xffffffffu, ssq0, 1);
    ssq0 += __shfl_xor_sync(0xffffffffu, ssq0, 2);
    ssq1 += __shfl_xor_sync(0xffffffffu, ssq1, 1);
    ssq1 += __shfl_xor_sync(0xffffffffu, ssq1, 2);

    const float sc0 = rsqrtf(ssq0 * (1.0f / (float)DVc) + 1e-6f);
    const float sc1 = rsqrtf(ssq1 * (1.0f / (float)DVc) + 1e-6f);

    float* po0 = out + (((size_t)b * Lc + (i0 + il0)) * Hc + h) * DVc;
    float* po1 = out + (((size_t)b * Lc + (i0 + il1)) * Hc + h) * DVc;
    #pragma unroll
    for (int t = 0; t < 16; t++) {
        const int d = t * 8 + 2 * lc;
        float2 w0, w1;
        w0.x = oc[t][0] * sc0; w0.y = oc[t][1] * sc0;
        w1.x = oc[t][2] * sc1; w1.y = oc[t][3] * sc1;
        *(float2*)(po0 + d) = w0;
        *(float2*)(po1 + d) = w1;
    }
}

extern "C" void kernel_launch(void* const* d_in, const int* in_sizes, int n_in,
                              void* d_out, int out_size)
{
    const float* q = (const float*)d_in[0];
    const float* k = (const float*)d_in[1];
    const float* v = (const float*)d_in[2];
    float* out = (float*)d_out;

    // pre-pass: K/V fp32 -> fp16
    cvt_kv_kernel<<<(unsigned)(KV_ELEMS / 4 / 256), 256>>>(k, v);

    cudaFuncSetAttribute(retnet_f16_kernel,
                         cudaFuncAttributeMaxDynamicSharedMemorySize,
                         (int)SMEM_BYTES);
    dim3 grid(Lc / BM, Bc * Hc);   // (32, 32)
    retnet_f16_kernel<<<grid, NTHREADS, SMEM_BYTES>>>(q, out);
}

// round 13
// speedup vs baseline: 2.6773x; 1.0305x over previous
#include <cuda_runtime.h>
#include <cuda_fp16.h>
#include <cstdint>

// RetNet parallel retention, fused fp16 mma.sync m16n8k16 + ldmatrix.
// R13: column decay folded into K at prepass (no Cs loads), uniform diag branch,
//      epilogue/GEMM2 interleaved per k-block. 3 CTAs/SM, 1 barrier/iter.
// B=2, H=16, L=2048, DK=DV=128.
namespace {
constexpr int Lc  = 2048;
constexpr int Hc  = 16;
constexpr int Bc  = 2;
constexpr int DKc = 128;
constexpr int DVc = 128;
constexpr int BM  = 64;
constexpr int BN  = 64;
constexpr int KV_STRIDE = 136;   // halves per row (272B)
constexpr int NTHREADS  = 128;   // 4 warps, each: 16 rows x full width
constexpr int KV_TILE_H = 64 * KV_STRIDE;

// smem: KsH[2][64][136] VsH[2][64][136] (half)  (~69.6 KB -> 3 CTAs/SM)
constexpr size_t SMEM_BYTES = (size_t)(4 * KV_TILE_H) * 2;

constexpr size_t KV_ELEMS = (size_t)Bc * Hc * Lc * DKc;   // 8388608
}

__device__ __half g_kh[KV_ELEMS];   // K pre-scaled by gamma^{-(j mod 64)}
__device__ __half g_vh[KV_ELEMS];

__device__ __forceinline__ void ldsm4(uint32_t& r0, uint32_t& r1, uint32_t& r2, uint32_t& r3,
                                      uint32_t addr) {
    asm volatile("ldmatrix.sync.aligned.m8n8.x4.shared.b16 {%0,%1,%2,%3}, [%4];"
                 : "=r"(r0), "=r"(r1), "=r"(r2), "=r"(r3) : "r"(addr));
}
__device__ __forceinline__ void ldsm4t(uint32_t& r0, uint32_t& r1, uint32_t& r2, uint32_t& r3,
                                       uint32_t addr) {
    asm volatile("ldmatrix.sync.aligned.m8n8.x4.trans.shared.b16 {%0,%1,%2,%3}, [%4];"
                 : "=r"(r0), "=r"(r1), "=r"(r2), "=r"(r3) : "r"(addr));
}
__device__ __forceinline__ void mma_f16(float c[4],
                                        uint32_t a0, uint32_t a1, uint32_t a2, uint32_t a3,
                                        uint32_t b0, uint32_t b1) {
    asm volatile(
        "mma.sync.aligned.m16n8k16.row.col.f32.f16.f16.f32 "
        "{%0,%1,%2,%3}, {%4,%5,%6,%7}, {%8,%9}, {%0,%1,%2,%3};\n"
        : "+f"(c[0]), "+f"(c[1]), "+f"(c[2]), "+f"(c[3])
        : "r"(a0), "r"(a1), "r"(a2), "r"(a3), "r"(b0), "r"(b1));
}
__device__ __forceinline__ uint32_t h2bits(__half2 h) {
    return *reinterpret_cast<uint32_t*>(&h);
}

#define CP_ASYNC16(dst, src) \
    asm volatile("cp.async.cg.shared.global [%0], [%1], 16;" :: "r"(dst), "l"(src) : "memory")
#define CP_COMMIT() asm volatile("cp.async.commit_group;" ::: "memory")
#define CP_WAIT0()  asm volatile("cp.async.wait_group 0;"  ::: "memory")

// ---- pre-pass: fp32 K/V -> fp16; K scaled by gamma^{-(row mod 64)} ----
__global__ __launch_bounds__(256, 4)
void cvt_kv_kernel(const float* __restrict__ k, const float* __restrict__ v)
{
    size_t i = (size_t)blockIdx.x * blockDim.x + threadIdx.x;   // over float4s
    // elem = 4*i ; layout [b][h][L][128]
    const int h    = (int)((i >> 16) & 15);          // (4i >> 18) & 15
    const int jloc = (int)((i >> 5) & 63);           // ((4i >> 7) mod 2048) mod 64
    const float lg2 = log1pf(-exp2f(-5.0f - (float)h)) * 1.4426950408889634f;
    const float cj  = exp2f(-lg2 * (float)jloc);

    float4 a = ((const float4*)k)[i];
    uint2 uk;
    uk.x = h2bits(__floats2half2_rn(a.x * cj, a.y * cj));
    uk.y = h2bits(__floats2half2_rn(a.z * cj, a.w * cj));
    ((uint2*)g_kh)[i] = uk;
    float4 bvec = ((const float4*)v)[i];
    uint2 uv;
    uv.x = h2bits(__floats2half2_rn(bvec.x, bvec.y));
    uv.y = h2bits(__floats2half2_rn(bvec.z, bvec.w));
    ((uint2*)g_vh)[i] = uv;
}

__global__ __launch_bounds__(NTHREADS, 3)
void retnet_f16_kernel(const float* __restrict__ q,
                       float* __restrict__ out)
{
    extern __shared__ __align__(16) char smraw[];
    __half* KsH = reinterpret_cast<__half*>(smraw);          // [2][64][136]
    __half* VsH = KsH + 2 * KV_TILE_H;                       // [2][64][136]

    const uint32_t KsU = (uint32_t)__cvta_generic_to_shared(KsH);
    const uint32_t VsU = (uint32_t)__cvta_generic_to_shared(VsH);
    constexpr uint32_t KV_TILE_BYTES = KV_TILE_H * 2;

    const int tid  = threadIdx.x;
    const int lane = tid & 31;
    const int warp = tid >> 5;    // 0..3 : 16-row group (full width)
    const int lr   = lane >> 2;
    const int lc   = lane & 3;

    // ldmatrix lane patterns (validated R5-R12)
    const int l7 = lane & 7;
    const int g  = lane >> 3;
    const int a_row   = l7 + (g & 1) * 8;   // A-pattern rows / V-trans rows
    const int a_col8  = (g >> 1) * 8;
    const int kb_row  = l7 + (g >> 1) * 8;  // K B-pattern
    const int kb_col8 = (g & 1) * 8;

    const int bh = blockIdx.y;
    const int b  = bh >> 4;
    const int h  = bh & 15;
    const int m_block = (int)(gridDim.x - 1) - (int)blockIdx.x;  // heavy first
    const int i0 = m_block * BM;

    const float*  qb = q + (size_t)bh * Lc * DKc;
    const __half* kh = g_kh + (size_t)bh * Lc * DKc;
    const __half* vh = g_vh + (size_t)bh * Lc * DVc;

    const float lg2 = log1pf(-exp2f(-5.0f - (float)h)) * 1.4426950408889634f;

    const int il0 = warp * 16 + lr;   // 0..63
    const int il1 = il0 + 8;

    // ---- stage Q (64x128 fp32->fp16) into K buffer 0, pull A-frags ----
    #pragma unroll
    for (int t = 0; t < 16; t++) {
        int idx = tid + t * NTHREADS;
        int r   = idx >> 5;        // 0..63
        int c   = idx & 31;
        float4 gld = *(const float4*)(qb + (size_t)(i0 + r) * DKc + c * 4);
        uint2 u;
        u.x = h2bits(__floats2half2_rn(gld.x, gld.y));
        u.y = h2bits(__floats2half2_rn(gld.z, gld.w));
        *(uint2*)(KsH + r * KV_STRIDE + c * 4) = u;
    }
    __syncthreads();

    uint32_t qa[8][4];
    #pragma unroll
    for (int kt = 0; kt < 8; kt++) {
        uint32_t addr = KsU + ((warp * 16 + a_row) * KV_STRIDE + kt * 16 + a_col8) * 2;
        ldsm4(qa[kt][0], qa[kt][1], qa[kt][2], qa[kt][3], addr);
    }
    __syncthreads();

    // ---- stage tile 0 (K + V) via cp.async at j0start = i0 (BM == BN) ----
    const int j0start = i0;
    {
        const __half* ksrc = kh + (size_t)j0start * DKc;
        const __half* vsrc = vh + (size_t)j0start * DVc;
        #pragma unroll
        for (int t = 0; t < 8; t++) {
            int idx = tid + t * NTHREADS;
            int n   = idx >> 4;        // 0..63
            int c   = idx & 15;        // 16B chunk
            CP_ASYNC16(KsU + (uint32_t)(n * KV_STRIDE + c * 8) * 2, ksrc + n * DKc + c * 8);
            CP_ASYNC16(VsU + (uint32_t)(n * KV_STRIDE + c * 8) * 2, vsrc + n * DVc + c * 8);
        }
        CP_COMMIT();
        CP_WAIT0();
    }
    __syncthreads();

    float oc[16][4];
    #pragma unroll
    for (int t = 0; t < 16; t++)
        #pragma unroll
        for (int e = 0; e < 4; e++) oc[t][e] = 0.0f;

    float rs0 = 0.0f, rs1 = 0.0f;
    float R0 = exp2f(lg2 * (float)il0);
    float R1 = exp2f(lg2 * (float)il1);
    const float gstep = exp2f(lg2 * (float)BN);

    // epilogue (t=2u, 2u+1) + GEMM2 k-block u, interleaved.
    // MASKED is a compile-time constant inside each branch.
#define EPI_GEMM2_U(u, MASKED)                                                   \
    {                                                                            \
        const int t0 = 2 * (u), t1 = 2 * (u) + 1;                                \
        float v0 = scr[t0][0] * R0;                                              \
        float v1 = scr[t0][1] * R0;                                              \
        float v2 = scr[t0][2] * R1;                                              \
        float v3 = scr[t0][3] * R1;                                              \
        float w0 = scr[t1][0] * R0;                                              \
        float w1 = scr[t1][1] * R0;                                              \
        float w2 = scr[t1][2] * R1;                                              \
        float w3 = scr[t1][3] * R1;                                              \
        if (MASKED) {                                                            \
            const int jb0 = t0 * 8 + 2 * lc;                                     \
            const int jb1 = t1 * 8 + 2 * lc;                                     \
            if (jb0     > il0) v0 = 0.0f;                                        \
            if (jb0 + 1 > il0) v1 = 0.0f;                                        \
            if (jb0     > il1) v2 = 0.0f;                                        \
            if (jb0 + 1 > il1) v3 = 0.0f;                                        \
            if (jb1     > il0) w0 = 0.0f;                                        \
            if (jb1 + 1 > il0) w1 = 0.0f;                                        \
            if (jb1     > il1) w2 = 0.0f;                                        \
            if (jb1 + 1 > il1) w3 = 0.0f;                                        \
        }                                                                        \
        rs0 += (v0 + v1) + (w0 + w1);                                            \
        rs1 += (v2 + v3) + (w2 + w3);                                            \
        const uint32_t sa0 = h2bits(__floats2half2_rn(v0, v1));                  \
        const uint32_t sa1 = h2bits(__floats2half2_rn(v2, v3));                  \
        const uint32_t sa2 = h2bits(__floats2half2_rn(w0, w1));                  \
        const uint32_t sa3 = h2bits(__floats2half2_rn(w2, w3));                  \
        _Pragma("unroll")                                                        \
        for (int dt = 0; dt < 8; dt++) {                                         \
            uint32_t b0, b1, b2, b3;                                             \
            uint32_t vaddr = VB + (((u) * 16 + a_row) * KV_STRIDE                \
                                   + dt * 16 + a_col8) * 2;                      \
            ldsm4t(b0, b1, b2, b3, vaddr);                                       \
            mma_f16(oc[dt * 2],     sa0, sa1, sa2, sa3, b0, b1);                 \
            mma_f16(oc[dt * 2 + 1], sa0, sa1, sa2, sa3, b2, b3);                 \
        }                                                                        \
    }

    int buf = 0;
    for (int j0 = j0start; j0 >= 0; j0 -= BN) {
        const bool haveNext = (j0 - BN) >= 0;
        const uint32_t KB = KsU + buf * KV_TILE_BYTES;
        const uint32_t VB = VsU + buf * KV_TILE_BYTES;
        const int jn = j0 - BN;

        // ---- issue async staging of next tile into the other buffer ----
        if (haveNext) {
            const __half* ksrc = kh + (size_t)jn * DKc;
            const __half* vsrc = vh + (size_t)jn * DVc;
            const uint32_t kdst = KsU + (buf ^ 1) * KV_TILE_BYTES;
            const uint32_t vdst = VsU + (buf ^ 1) * KV_TILE_BYTES;
            #pragma unroll
            for (int t = 0; t < 8; t++) {
                int idx = tid + t * NTHREADS;
                int n   = idx >> 4;
                int c   = idx & 15;
                CP_ASYNC16(kdst + (uint32_t)(n * KV_STRIDE + c * 8) * 2, ksrc + n * DKc + c * 8);
                CP_ASYNC16(vdst + (uint32_t)(n * KV_STRIDE + c * 8) * 2, vsrc + n * DVc + c * 8);
            }
            CP_COMMIT();
        }

        // ---- GEMM1: S(16 x 64 per warp) = Q K'^T (K' carries gamma^{-jloc}) ----
        float scr[8][4];
        #pragma unroll
        for (int t = 0; t < 8; t++)
            #pragma unroll
            for (int e = 0; e < 4; e++) scr[t][e] = 0.0f;

        #pragma unroll
        for (int kt = 0; kt < 8; kt++) {
            #pragma unroll
            for (int nt = 0; nt < 4; nt++) {
                uint32_t b0, b1, b2, b3;
                uint32_t addr = KB + ((nt * 16 + kb_row) * KV_STRIDE + kt * 16 + kb_col8) * 2;
                ldsm4(b0, b1, b2, b3, addr);
                mma_f16(scr[nt * 2],     qa[kt][0], qa[kt][1], qa[kt][2], qa[kt][3], b0, b1);
                mma_f16(scr[nt * 2 + 1], qa[kt][0], qa[kt][1], qa[kt][2], qa[kt][3], b2, b3);
            }
        }

        // ---- epilogue + GEMM2, interleaved per k-block; uniform diag branch ----
        if (j0 == i0) {
            #pragma unroll
            for (int u = 0; u < 4; u++) EPI_GEMM2_U(u, true)
        } else {
            #pragma unroll
            for (int u = 0; u < 4; u++) EPI_GEMM2_U(u, false)
        }
        R0 *= gstep;
        R1 *= gstep;

        // ---- drain async staging, release buffers (single barrier per iter) ----
        if (haveNext) CP_WAIT0();
        __syncthreads();

        buf ^= 1;
    }
#undef EPI_GEMM2_U

    // ---- rowsum: warp owns all 64 cols of its rows -> 2 shfls, done ----
    rs0 += __shfl_xor_sync(0xffffffffu, rs0, 1);
    rs0 += __shfl_xor_sync(0xffffffffu, rs0, 2);
    rs1 += __shfl_xor_sync(0xffffffffu, rs1, 1);
    rs1 += __shfl_xor_sync(0xffffffffu, rs1, 2);

    const float dn0 = 1.0f / fmaxf(fabsf(rs0), 1.0f);
    const float dn1 = 1.0f / fmaxf(fabsf(rs1), 1.0f);

    float ssq0 = 0.0f, ssq1 = 0.0f;
    #pragma unroll
    for (int t = 0; t < 16; t++) {
        oc[t][0] *= dn0; oc[t][1] *= dn0;
        oc[t][2] *= dn1; oc[t][3] *= dn1;
        ssq0 += oc[t][0] * oc[t][0] + oc[t][1] * oc[t][1];
        ssq1 += oc[t][2] * oc[t][2] + oc[t][3] * oc[t][3];
    }
    ssq0 += __shfl_xor_sync(0xffffffffu, ssq0, 1);
    ssq0 += __shfl_xor_sync(0xffffffffu, ssq0, 2);
    ssq1 += __shfl_xor_sync(0xffffffffu, ssq1, 1);
    ssq1 += __shfl_xor_sync(0xffffffffu, ssq1, 2);

    const float sc0 = rsqrtf(ssq0 * (1.0f / (float)DVc) + 1e-6f);
    const float sc1 = rsqrtf(ssq1 * (1.0f / (float)DVc) + 1e-6f);

    float* po0 = out + (((size_t)b * Lc + (i0 + il0)) * Hc + h) * DVc;
    float* po1 = out + (((size_t)b * Lc + (i0 + il1)) * Hc + h) * DVc;
    #pragma unroll
    for (int t = 0; t < 16; t++) {
        const int d = t * 8 + 2 * lc;
        float2 w0, w1;
        w0.x = oc[t][0] * sc0; w0.y = oc[t][1] * sc0;
        w1.x = oc[t][2] * sc1; w1.y = oc[t][3] * sc1;
        *(float2*)(po0 + d) = w0;
        *(float2*)(po1 + d) = w1;
    }
}

extern "C" void kernel_launch(void* const* d_in, const int* in_sizes, int n_in,
                              void* d_out, int out_size)
{
    const float* q = (const float*)d_in[0];
    const float* k = (const float*)d_in[1];
    const float* v = (const float*)d_in[2];
    float* out = (float*)d_out;

    // pre-pass: K/V fp32 -> fp16 (K pre-scaled by gamma^{-(j mod 64)})
    cvt_kv_kernel<<<(unsigned)(KV_ELEMS / 4 / 256), 256>>>(k, v);

    cudaFuncSetAttribute(retnet_f16_kernel,
                         cudaFuncAttributeMaxDynamicSharedMemorySize,
                         (int)SMEM_BYTES);
    dim3 grid(Lc / BM, Bc * Hc);   // (32, 32)
    retnet_f16_kernel<<<grid, NTHREADS, SMEM_BYTES>>>(q, out);
}

// round 14
// speedup vs baseline: 4.2661x; 1.5934x over previous
#include <cuda_runtime.h>
#include <cuda_fp16.h>
#include <cstdint>

// RetNet retention via exact chunked linear-attention form.
//   P_c = K'^T [V | 1]          (per-chunk partial, 128x136, MMA)
//   T_{c+1} = g^64 (T_c + P_c)  (prefix scan, fp32, stored fp16)
//   O = g^{iloc} Q T_c + intra-chunk (masked decayed S)  ; denom via z col of T
// B=2, H=16, L=2048, DK=DV=128, chunk C=64.
namespace {
constexpr int Lc  = 2048;
constexpr int Hc  = 16;
constexpr int Bc  = 2;
constexpr int DKc = 128;
constexpr int CH  = 64;                 // chunk size
constexpr int NC  = Lc / CH;            // 32 chunks
constexpr int NBH = Bc * Hc;            // 32
constexpr int PCOLS = 136;              // 128 dv + z col + 7 pad
constexpr int KV_STRIDE = 136;          // smem stride (halves) for K/V tiles
constexpr int TS_STRIDE = 152;          // smem stride (halves) for T/Q/V_aug tiles

constexpr size_t KV_ELEMS = (size_t)NBH * Lc * DKc;          // 8388608
constexpr size_t PT_ELEMS = (size_t)NBH * NC * DKc * PCOLS;  // 17825792
}

__device__ __half g_kh[KV_ELEMS];   // K * gamma^{-(j mod 64)}  (fp16)
__device__ __half g_vh[KV_ELEMS];   // V (fp16)
__device__ float  g_P[PT_ELEMS];    // chunk partials (fp32)
__device__ __half g_T[PT_ELEMS];    // prefix states (fp16)

__device__ __forceinline__ void ldsm4(uint32_t& r0, uint32_t& r1, uint32_t& r2, uint32_t& r3,
                                      uint32_t addr) {
    asm volatile("ldmatrix.sync.aligned.m8n8.x4.shared.b16 {%0,%1,%2,%3}, [%4];"
                 : "=r"(r0), "=r"(r1), "=r"(r2), "=r"(r3) : "r"(addr));
}
__device__ __forceinline__ void ldsm4t(uint32_t& r0, uint32_t& r1, uint32_t& r2, uint32_t& r3,
                                       uint32_t addr) {
    asm volatile("ldmatrix.sync.aligned.m8n8.x4.trans.shared.b16 {%0,%1,%2,%3}, [%4];"
                 : "=r"(r0), "=r"(r1), "=r"(r2), "=r"(r3) : "r"(addr));
}
__device__ __forceinline__ void mma_f16(float c[4],
                                        uint32_t a0, uint32_t a1, uint32_t a2, uint32_t a3,
                                        uint32_t b0, uint32_t b1) {
    asm volatile(
        "mma.sync.aligned.m16n8k16.row.col.f32.f16.f16.f32 "
        "{%0,%1,%2,%3}, {%4,%5,%6,%7}, {%8,%9}, {%0,%1,%2,%3};\n"
        : "+f"(c[0]), "+f"(c[1]), "+f"(c[2]), "+f"(c[3])
        : "r"(a0), "r"(a1), "r"(a2), "r"(a3), "r"(b0), "r"(b1));
}
__device__ __forceinline__ uint32_t h2bits(__half2 h) {
    return *reinterpret_cast<uint32_t*>(&h);
}

#define CP_ASYNC16(dst, src) \
    asm volatile("cp.async.cg.shared.global [%0], [%1], 16;" :: "r"(dst), "l"(src) : "memory")
#define CP_COMMIT() asm volatile("cp.async.commit_group;" ::: "memory")
#define CP_WAIT0()  asm volatile("cp.async.wait_group 0;"  ::: "memory")

__device__ __forceinline__ float head_lg2(int h) {
    return log1pf(-exp2f(-5.0f - (float)h)) * 1.4426950408889634f;
}

// ============ kernel 0: prepass fp32 K/V -> fp16, K scaled by gamma^{-jloc} ============
__global__ __launch_bounds__(256, 4)
void cvt_kv_kernel(const float* __restrict__ k, const float* __restrict__ v)
{
    size_t i = (size_t)blockIdx.x * blockDim.x + threadIdx.x;   // over float4s
    const int h    = (int)((i >> 16) & 15);
    const int jloc = (int)((i >> 5) & 63);
    const float lg2 = head_lg2(h);
    const float cj  = exp2f(-lg2 * (float)jloc);

    float4 a = ((const float4*)k)[i];
    uint2 uk;
    uk.x = h2bits(__floats2half2_rn(a.x * cj, a.y * cj));
    uk.y = h2bits(__floats2half2_rn(a.z * cj, a.w * cj));
    ((uint2*)g_kh)[i] = uk;
    float4 bvec = ((const float4*)v)[i];
    uint2 uv;
    uv.x = h2bits(__floats2half2_rn(bvec.x, bvec.y));
    uv.y = h2bits(__floats2half2_rn(bvec.z, bvec.w));
    ((uint2*)g_vh)[i] = uv;
}

// ============ kernel 1: chunk partials P = K'^T [V | 1] ============
// grid (NC, NBH), 128 threads (4 warps, each owns 32 dk rows).
__global__ __launch_bounds__(128)
void chunk_partial_kernel()
{
    extern __shared__ __align__(16) char smraw[];
    __half* Ka = reinterpret_cast<__half*>(smraw);            // [64][136]
    __half* Va = Ka + CH * KV_STRIDE;                         // [64][152] augmented
    const uint32_t KaU = (uint32_t)__cvta_generic_to_shared(Ka);
    const uint32_t VaU = (uint32_t)__cvta_generic_to_shared(Va);

    const int tid  = threadIdx.x;
    const int lane = tid & 31;
    const int warp = tid >> 5;
    const int lr   = lane >> 2;
    const int lc   = lane & 3;
    const int l7 = lane & 7;
    const int g  = lane >> 3;
    const int a_row  = l7 + (g & 1) * 8;
    const int a_col8 = (g >> 1) * 8;

    const int c  = blockIdx.x;
    const int bh = blockIdx.y;
    const int j0 = c * CH;

    const __half* kh = g_kh + (size_t)bh * Lc * DKc + (size_t)j0 * DKc;
    const __half* vh = g_vh + (size_t)bh * Lc * DKc + (size_t)j0 * DKc;

    // cp.async K', V tiles (16-chunk rows)
    #pragma unroll
    for (int t = 0; t < 8; t++) {
        int idx = tid + t * 128;
        int n   = idx >> 4;
        int ch  = idx & 15;
        CP_ASYNC16(KaU + (uint32_t)(n * KV_STRIDE + ch * 8) * 2, kh + n * DKc + ch * 8);
        CP_ASYNC16(VaU + (uint32_t)(n * TS_STRIDE + ch * 8) * 2, vh + n * DKc + ch * 8);
    }
    CP_COMMIT();
    // augmentation: col 128 = 1.0, cols 129..151 = 0
    if (tid < 64) {
        __half* row = Va + tid * TS_STRIDE;
        row[128] = __float2half_rn(1.0f);
        #pragma unroll
        for (int cc = 129; cc < 152; cc++) row[cc] = __float2half_rn(0.0f);
    }
    CP_WAIT0();
    __syncthreads();

    // A-fragments of K'^T via ldsm trans; mapping a0=r0, a1=r2, a2=r1, a3=r3.
    uint32_t afr[2][4][4];
    #pragma unroll
    for (int mt = 0; mt < 2; mt++)
        #pragma unroll
        for (int kt = 0; kt < 4; kt++) {
            uint32_t r0, r1, r2, r3;
            uint32_t addr = KaU + ((uint32_t)((kt * 16 + a_row) * KV_STRIDE
                                              + warp * 32 + mt * 16 + a_col8)) * 2;
            ldsm4t(r0, r1, r2, r3, addr);
            afr[mt][kt][0] = r0; afr[mt][kt][1] = r2;
            afr[mt][kt][2] = r1; afr[mt][kt][3] = r3;
        }

    float* Pout = g_P + (size_t)(bh * NC + c) * DKc * PCOLS;

    #pragma unroll
    for (int ntb = 0; ntb < 9; ntb++) {
        uint32_t bfr[4][4];
        #pragma unroll
        for (int kt = 0; kt < 4; kt++) {
            ldsm4t(bfr[kt][0], bfr[kt][1], bfr[kt][2], bfr[kt][3],
                   VaU + ((uint32_t)((kt * 16 + a_row) * TS_STRIDE + ntb * 16 + a_col8)) * 2);
        }
        #pragma unroll
        for (int mt = 0; mt < 2; mt++) {
            #pragma unroll
            for (int nh = 0; nh < 2; nh++) {
                if (ntb == 8 && nh == 1) continue;   // cols >=136 discarded
                float acc[4] = {0.0f, 0.0f, 0.0f, 0.0f};
                #pragma unroll
                for (int kt = 0; kt < 4; kt++)
                    mma_f16(acc, afr[mt][kt][0], afr[mt][kt][1], afr[mt][kt][2], afr[mt][kt][3],
                            bfr[kt][nh * 2], bfr[kt][nh * 2 + 1]);
                const int dk0 = warp * 32 + mt * 16 + lr;
                const int col = ntb * 16 + nh * 8 + 2 * lc;
                *(float2*)(Pout + (size_t)dk0 * PCOLS + col)       = make_float2(acc[0], acc[1]);
                *(float2*)(Pout + (size_t)(dk0 + 8) * PCOLS + col) = make_float2(acc[2], acc[3]);
            }
        }
    }
}

// ============ kernel 2: prefix scan T_{c+1} = g^64 (T_c + P_c) ============
// grid (17 col-slabs of 8, NBH), 128 threads (thread = dk row).
__global__ __launch_bounds__(128)
void scan_kernel()
{
    const int s  = blockIdx.x;           // slab: cols 8s..8s+7
    const int bh = blockIdx.y;
    const int t  = threadIdx.x;          // dk row
    const float lg2  = head_lg2(bh & 15);
    const float g64  = exp2f(lg2 * 64.0f);

    const float* P = g_P + (size_t)bh * NC * DKc * PCOLS;
    __half*      T = g_T + (size_t)bh * NC * DKc * PCOLS;
    const size_t offs = (size_t)t * PCOLS + s * 8;
    const size_t cstride = (size_t)DKc * PCOLS;

    float acc[8] = {0, 0, 0, 0, 0, 0, 0, 0};
    // T_0 = 0
    {
        uint2 z2 = make_uint2(0, 0);
        *(uint2*)(T + offs)     = z2;
        *(uint2*)(T + offs + 4) = z2;
    }
    for (int c = 0; c < NC - 1; c++) {
        float4 p0 = *(const float4*)(P + c * cstride + offs);
        float4 p1 = *(const float4*)(P + c * cstride + offs + 4);
        acc[0] = g64 * (acc[0] + p0.x); acc[1] = g64 * (acc[1] + p0.y);
        acc[2] = g64 * (acc[2] + p0.z); acc[3] = g64 * (acc[3] + p0.w);
        acc[4] = g64 * (acc[4] + p1.x); acc[5] = g64 * (acc[5] + p1.y);
        acc[6] = g64 * (acc[6] + p1.z); acc[7] = g64 * (acc[7] + p1.w);
        uint2 o0, o1;
        o0.x = h2bits(__floats2half2_rn(acc[0], acc[1]));
        o0.y = h2bits(__floats2half2_rn(acc[2], acc[3]));
        o1.x = h2bits(__floats2half2_rn(acc[4], acc[5]));
        o1.y = h2bits(__floats2half2_rn(acc[6], acc[7]));
        *(uint2*)(T + (c + 1) * cstride + offs)     = o0;
        *(uint2*)(T + (c + 1) * cstride + offs + 4) = o1;
    }
}

// ============ kernel 3: output = intra(chunk) + g^{iloc} Q T_c ; denom ; RMS ============
// grid (NC, NBH), 128 threads (4 warps, warp = 16 Q rows, full width).
__global__ __launch_bounds__(128)
void retnet_out_kernel(const float* __restrict__ q, float* __restrict__ out)
{
    extern __shared__ __align__(16) char smraw[];
    __half* Ks = reinterpret_cast<__half*>(smraw);            // [64][136]
    __half* Vs = Ks + CH * KV_STRIDE;                         // [64][136]
    __half* Ts = Vs + CH * KV_STRIDE;                         // [128][152] (Q staged here first)
    const uint32_t KsU = (uint32_t)__cvta_generic_to_shared(Ks);
    const uint32_t VsU = (uint32_t)__cvta_generic_to_shared(Vs);
    const uint32_t TsU = (uint32_t)__cvta_generic_to_shared(Ts);

    const int tid  = threadIdx.x;
    const int lane = tid & 31;
    const int warp = tid >> 5;
    const int lr   = lane >> 2;
    const int lc   = lane & 3;
    const int l7 = lane & 7;
    const int g  = lane >> 3;
    const int a_row  = l7 + (g & 1) * 8;
    const int a_col8 = (g >> 1) * 8;
    const int kb_row  = l7 + (g >> 1) * 8;
    const int kb_col8 = (g & 1) * 8;

    const int c  = blockIdx.x;
    const int bh = blockIdx.y;
    const int b  = bh >> 4;
    const int h  = bh & 15;
    const int i0 = c * CH;

    const float*  qb = q    + (size_t)bh * Lc * DKc + (size_t)i0 * DKc;
    const __half* kh = g_kh + (size_t)bh * Lc * DKc + (size_t)i0 * DKc;
    const __half* vh = g_vh + (size_t)bh * Lc * DKc + (size_t)i0 * DKc;
    const __half* th = g_T  + (size_t)(bh * NC + c) * DKc * PCOLS;

    const float lg2 = head_lg2(h);
    const int il0 = warp * 16 + lr;
    const int il1 = il0 + 8;
    const float R0 = exp2f(lg2 * (float)il0);   // gamma^{iloc}
    const float R1 = exp2f(lg2 * (float)il1);

    // (1) cp.async K', V
    #pragma unroll
    for (int t = 0; t < 8; t++) {
        int idx = tid + t * 128;
        int n   = idx >> 4;
        int ch  = idx & 15;
        CP_ASYNC16(KsU + (uint32_t)(n * KV_STRIDE + ch * 8) * 2, kh + n * DKc + ch * 8);
        CP_ASYNC16(VsU + (uint32_t)(n * KV_STRIDE + ch * 8) * 2, vh + n * DKc + ch * 8);
    }
    CP_COMMIT();

    // (2) stage Q fp32->fp16 into Ts region, pull qa fragments
    #pragma unroll
    for (int t = 0; t < 16; t++) {
        int idx = tid + t * 128;
        int r   = idx >> 5;
        int c4  = idx & 31;
        float4 gld = *(const float4*)(qb + (size_t)r * DKc + c4 * 4);
        uint2 u;
        u.x = h2bits(__floats2half2_rn(gld.x, gld.y));
        u.y = h2bits(__floats2half2_rn(gld.z, gld.w));
        *(uint2*)(Ts + r * TS_STRIDE + c4 * 4) = u;
    }
    __syncthreads();
    uint32_t qa[8][4];
    #pragma unroll
    for (int kt = 0; kt < 8; kt++) {
        ldsm4(qa[kt][0], qa[kt][1], qa[kt][2], qa[kt][3],
              TsU + (uint32_t)((warp * 16 + a_row) * TS_STRIDE + kt * 16 + a_col8) * 2);
    }
    __syncthreads();

    // (3) cp.async T into Ts (fp16, 17 chunks/row)
    #pragma unroll
    for (int t = 0; t < 17; t++) {
        int idx = tid + t * 128;
        int r   = idx / 17;
        int ch  = idx % 17;
        CP_ASYNC16(TsU + (uint32_t)(r * TS_STRIDE + ch * 8) * 2, th + (size_t)r * PCOLS + ch * 8);
    }
    CP_COMMIT();
    CP_WAIT0();
    __syncthreads();

    // (4) intra GEMM1: S = Q K'^T
    float scr[8][4];
    #pragma unroll
    for (int t = 0; t < 8; t++)
        #pragma unroll
        for (int e = 0; e < 4; e++) scr[t][e] = 0.0f;
    #pragma unroll
    for (int kt = 0; kt < 8; kt++) {
        #pragma unroll
        for (int nt = 0; nt < 4; nt++) {
            uint32_t b0, b1, b2, b3;
            ldsm4(b0, b1, b2, b3,
                  KsU + (uint32_t)((nt * 16 + kb_row) * KV_STRIDE + kt * 16 + kb_col8) * 2);
            mma_f16(scr[nt * 2],     qa[kt][0], qa[kt][1], qa[kt][2], qa[kt][3], b0, b1);
            mma_f16(scr[nt * 2 + 1], qa[kt][0], qa[kt][1], qa[kt][2], qa[kt][3], b2, b3);
        }
    }

    // (5) decay + causal mask (always diagonal) + intra rowsum + fp16 repack
    float rs0 = 0.0f, rs1 = 0.0f;
    uint32_t sa[4][4];
    #pragma unroll
    for (int t = 0; t < 8; t++) {
        const int jb = t * 8 + 2 * lc;
        float v0 = scr[t][0] * R0;
        float v1 = scr[t][1] * R0;
        float v2 = scr[t][2] * R1;
        float v3 = scr[t][3] * R1;
        if (jb     > il0) v0 = 0.0f;
        if (jb + 1 > il0) v1 = 0.0f;
        if (jb     > il1) v2 = 0.0f;
        if (jb + 1 > il1) v3 = 0.0f;
        rs0 += v0 + v1;
        rs1 += v2 + v3;
        const int u  = t >> 1;
        const int hi = (t & 1) * 2;
        sa[u][hi]     = h2bits(__floats2half2_rn(v0, v1));
        sa[u][hi + 1] = h2bits(__floats2half2_rn(v2, v3));
    }

    // (6) inter GEMM: ocI = Q · T  (k = dk = 128, n = 136 incl z col 128)
    float ocI[18][4];
    #pragma unroll
    for (int t = 0; t < 18; t++)
        #pragma unroll
        for (int e = 0; e < 4; e++) ocI[t][e] = 0.0f;
    #pragma unroll
    for (int ntb = 0; ntb < 9; ntb++) {
        #pragma unroll
        for (int kt = 0; kt < 8; kt++) {
            uint32_t b0, b1, b2, b3;
            ldsm4t(b0, b1, b2, b3,
                   TsU + (uint32_t)((kt * 16 + a_row) * TS_STRIDE + ntb * 16 + a_col8) * 2);
            mma_f16(ocI[ntb * 2],     qa[kt][0], qa[kt][1], qa[kt][2], qa[kt][3], b0, b1);
            mma_f16(ocI[ntb * 2 + 1], qa[kt][0], qa[kt][1], qa[kt][2], qa[kt][3], b2, b3);
        }
    }
    // scale inter by gamma^{iloc}
    #pragma unroll
    for (int t = 0; t < 18; t++) {
        ocI[t][0] *= R0; ocI[t][1] *= R0;
        ocI[t][2] *= R1; ocI[t][3] *= R1;
    }

    // (7) intra GEMM2 accumulates on top: O += S~ · V  (cols 0..127 only)
    #pragma unroll
    for (int kt2 = 0; kt2 < 4; kt2++) {
        #pragma unroll
        for (int dt = 0; dt < 8; dt++) {
            uint32_t b0, b1, b2, b3;
            ldsm4t(b0, b1, b2, b3,
                   VsU + (uint32_t)((kt2 * 16 + a_row) * KV_STRIDE + dt * 16 + a_col8) * 2);
            mma_f16(ocI[dt * 2],     sa[kt2][0], sa[kt2][1], sa[kt2][2], sa[kt2][3], b0, b1);
            mma_f16(ocI[dt * 2 + 1], sa[kt2][0], sa[kt2][1], sa[kt2][2], sa[kt2][3], b2, b3);
        }
    }

    // (8) denominator: rs += inter z term (col 128 -> frag nt=16, 2lc==0)
    if (lc == 0) { rs0 += ocI[16][0]; rs1 += ocI[16][2]; }
    rs0 += __shfl_xor_sync(0xffffffffu, rs0, 1);
    rs0 += __shfl_xor_sync(0xffffffffu, rs0, 2);
    rs1 += __shfl_xor_sync(0xffffffffu, rs1, 1);
    rs1 += __shfl_xor_sync(0xffffffffu, rs1, 2);
    const float dn0 = 1.0f / fmaxf(fabsf(rs0), 1.0f);
    const float dn1 = 1.0f / fmaxf(fabsf(rs1), 1.0f);

    // (9) normalize + RMS + write
    float ssq0 = 0.0f, ssq1 = 0.0f;
    #pragma unroll
    for (int t = 0; t < 16; t++) {
        ocI[t][0] *= dn0; ocI[t][1] *= dn0;
        ocI[t][2] *= dn1; ocI[t][3] *= dn1;
        ssq0 += ocI[t][0] * ocI[t][0] + ocI[t][1] * ocI[t][1];
        ssq1 += ocI[t][2] * ocI[t][2] + ocI[t][3] * ocI[t][3];
    }
    ssq0 += __shfl_xor_sync(0xffffffffu, ssq0, 1);
    ssq0 += __shfl_xor_sync(0xffffffffu, ssq0, 2);
    ssq1 += __shfl_xor_sync(0xffffffffu, ssq1, 1);
    ssq1 += __shfl_xor_sync(0xffffffffu, ssq1, 2);
    const float sc0 = rsqrtf(ssq0 * (1.0f / 128.0f) + 1e-6f);
    const float sc1 = rsqrtf(ssq1 * (1.0f / 128.0f) + 1e-6f);

    float* po0 = out + (((size_t)b * Lc + (i0 + il0)) * Hc + h) * DKc;
    float* po1 = out + (((size_t)b * Lc + (i0 + il1)) * Hc + h) * DKc;
    #pragma unroll
    for (int t = 0; t < 16; t++) {
        const int d = t * 8 + 2 * lc;
        float2 w0, w1;
        w0.x = ocI[t][0] * sc0; w0.y = ocI[t][1] * sc0;
        w1.x = ocI[t][2] * sc1; w1.y = ocI[t][3] * sc1;
        *(float2*)(po0 + d) = w0;
        *(float2*)(po1 + d) = w1;
    }
}

extern "C" void kernel_launch(void* const* d_in, const int* in_sizes, int n_in,
                              void* d_out, int out_size)
{
    const float* q = (const float*)d_in[0];
    const float* k = (const float*)d_in[1];
    const float* v = (const float*)d_in[2];
    float* out = (float*)d_out;

    // 0) prepass
    cvt_kv_kernel<<<(unsigned)(KV_ELEMS / 4 / 256), 256>>>(k, v);

    // 1) chunk partials
    {
        const int smem = (CH * KV_STRIDE + CH * TS_STRIDE) * 2;
        cudaFuncSetAttribute(chunk_partial_kernel,
                             cudaFuncAttributeMaxDynamicSharedMemorySize, smem);
        dim3 grid(NC, NBH);
        chunk_partial_kernel<<<grid, 128, smem>>>();
    }
    // 2) prefix scan
    {
        dim3 grid(17, NBH);
        scan_kernel<<<grid, 128>>>();
    }
    // 3) fused output
    {
        const int smem = (2 * CH * KV_STRIDE + DKc * TS_STRIDE) * 2;
        cudaFuncSetAttribute(retnet_out_kernel,
                             cudaFuncAttributeMaxDynamicSharedMemorySize, smem);
        dim3 grid(NC, NBH);
        retnet_out_kernel<<<grid, 128, smem>>>(q, out);
    }
}

// round 15
// speedup vs baseline: 4.9292x; 1.1554x over previous
#include <cuda_runtime.h>
#include <cuda_fp16.h>
#include <cstdint>

// RetNet retention via exact chunked linear-attention form (R15).
//   A: fused cvt + partial  P_c = K'^T [V | 1]   (P stored fp16)
//   B: prefix scan T_{c+1} = g^64 (T_c + P_c)    (fp32 acc, fp16 store, prefetch)
//   C: O = g^{iloc} Q T_c + intra-chunk          (denominator via z col of T)
// B=2, H=16, L=2048, DK=DV=128, chunk C=64.
namespace {
constexpr int Lc  = 2048;
constexpr int Hc  = 16;
constexpr int Bc  = 2;
constexpr int DKc = 128;
constexpr int CH  = 64;
constexpr int NC  = Lc / CH;            // 32
constexpr int NBH = Bc * Hc;            // 32
constexpr int PCOLS = 136;              // 128 dv + z col + 7 pad
constexpr int KV_STRIDE = 136;
constexpr int TS_STRIDE = 152;

constexpr size_t KV_ELEMS = (size_t)NBH * Lc * DKc;          // 8388608
constexpr size_t PT_ELEMS = (size_t)NBH * NC * DKc * PCOLS;  // 17825792
}

__device__ __half g_qh[KV_ELEMS];   // Q fp16
__device__ __half g_kh[KV_ELEMS];   // K * gamma^{-(j mod 64)} fp16
__device__ __half g_vh[KV_ELEMS];   // V fp16
__device__ __half g_P[PT_ELEMS];    // chunk partials fp16
__device__ __half g_T[PT_ELEMS];    // prefix states fp16

__device__ __forceinline__ void ldsm4(uint32_t& r0, uint32_t& r1, uint32_t& r2, uint32_t& r3,
                                      uint32_t addr) {
    asm volatile("ldmatrix.sync.aligned.m8n8.x4.shared.b16 {%0,%1,%2,%3}, [%4];"
                 : "=r"(r0), "=r"(r1), "=r"(r2), "=r"(r3) : "r"(addr));
}
__device__ __forceinline__ void ldsm4t(uint32_t& r0, uint32_t& r1, uint32_t& r2, uint32_t& r3,
                                       uint32_t addr) {
    asm volatile("ldmatrix.sync.aligned.m8n8.x4.trans.shared.b16 {%0,%1,%2,%3}, [%4];"
                 : "=r"(r0), "=r"(r1), "=r"(r2), "=r"(r3) : "r"(addr));
}
__device__ __forceinline__ void mma_f16(float c[4],
                                        uint32_t a0, uint32_t a1, uint32_t a2, uint32_t a3,
                                        uint32_t b0, uint32_t b1) {
    asm volatile(
        "mma.sync.aligned.m16n8k16.row.col.f32.f16.f16.f32 "
        "{%0,%1,%2,%3}, {%4,%5,%6,%7}, {%8,%9}, {%0,%1,%2,%3};\n"
        : "+f"(c[0]), "+f"(c[1]), "+f"(c[2]), "+f"(c[3])
        : "r"(a0), "r"(a1), "r"(a2), "r"(a3), "r"(b0), "r"(b1));
}
__device__ __forceinline__ uint32_t h2bits(__half2 h) {
    return *reinterpret_cast<uint32_t*>(&h);
}

#define CP_ASYNC16(dst, src) \
    asm volatile("cp.async.cg.shared.global [%0], [%1], 16;" :: "r"(dst), "l"(src) : "memory")
#define CP_COMMIT() asm volatile("cp.async.commit_group;" ::: "memory")
#define CP_WAIT0()  asm volatile("cp.async.wait_group 0;"  ::: "memory")

__device__ __forceinline__ float head_lg2(int h) {
    return log1pf(-exp2f(-5.0f - (float)h)) * 1.4426950408889634f;
}

// ============ kernel A: fused cvt (Q/K/V fp32->fp16) + chunk partial P ============
// grid (NC, NBH), 128 threads.
__global__ __launch_bounds__(128)
void partial_kernel(const float* __restrict__ q,
                    const float* __restrict__ k,
                    const float* __restrict__ v)
{
    extern __shared__ __align__(16) char smraw[];
    __half* Ka = reinterpret_cast<__half*>(smraw);            // [64][136]
    __half* Va = Ka + CH * KV_STRIDE;                         // [64][152] augmented
    const uint32_t KaU = (uint32_t)__cvta_generic_to_shared(Ka);
    const uint32_t VaU = (uint32_t)__cvta_generic_to_shared(Va);

    const int tid  = threadIdx.x;
    const int lane = tid & 31;
    const int warp = tid >> 5;
    const int lr   = lane >> 2;
    const int lc   = lane & 3;
    const int l7 = lane & 7;
    const int g  = lane >> 3;
    const int a_row  = l7 + (g & 1) * 8;
    const int a_col8 = (g >> 1) * 8;

    const int c  = blockIdx.x;
    const int bh = blockIdx.y;
    const int h  = bh & 15;
    const int j0 = c * CH;
    const float lg2 = head_lg2(h);

    const size_t base = (size_t)bh * Lc * DKc + (size_t)j0 * DKc;
    const float* qs = q + base;
    const float* ks = k + base;
    const float* vs = v + base;
    __half* qo = g_qh + base;
    __half* ko = g_kh + base;
    __half* vo = g_vh + base;

    // convert: K (scaled) -> smem + gmem ; V -> smem + gmem ; Q -> gmem
    #pragma unroll
    for (int t = 0; t < 16; t++) {
        int idx = tid + t * 128;
        int r   = idx >> 5;       // 0..63
        int c4  = idx & 31;
        const float cj = exp2f(-lg2 * (float)r);
        float4 gk = *(const float4*)(ks + (size_t)r * DKc + c4 * 4);
        uint2 uk;
        uk.x = h2bits(__floats2half2_rn(gk.x * cj, gk.y * cj));
        uk.y = h2bits(__floats2half2_rn(gk.z * cj, gk.w * cj));
        *(uint2*)(Ka + r * KV_STRIDE + c4 * 4) = uk;
        *(uint2*)(ko + (size_t)r * DKc + c4 * 4) = uk;

        float4 gv = *(const float4*)(vs + (size_t)r * DKc + c4 * 4);
        uint2 uv;
        uv.x = h2bits(__floats2half2_rn(gv.x, gv.y));
        uv.y = h2bits(__floats2half2_rn(gv.z, gv.w));
        *(uint2*)(Va + r * TS_STRIDE + c4 * 4) = uv;
        *(uint2*)(vo + (size_t)r * DKc + c4 * 4) = uv;

        float4 gq = *(const float4*)(qs + (size_t)r * DKc + c4 * 4);
        uint2 uq;
        uq.x = h2bits(__floats2half2_rn(gq.x, gq.y));
        uq.y = h2bits(__floats2half2_rn(gq.z, gq.w));
        *(uint2*)(qo + (size_t)r * DKc + c4 * 4) = uq;
    }
    // augmentation: col 128 = 1.0, cols 129..151 = 0
    if (tid < 64) {
        __half* row = Va + tid * TS_STRIDE;
        row[128] = __float2half_rn(1.0f);
        #pragma unroll
        for (int cc = 129; cc < 152; cc++) row[cc] = __float2half_rn(0.0f);
    }
    __syncthreads();

    // A-fragments of K'^T via ldsm trans; mapping a0=r0, a1=r2, a2=r1, a3=r3.
    uint32_t afr[2][4][4];
    #pragma unroll
    for (int mt = 0; mt < 2; mt++)
        #pragma unroll
        for (int kt = 0; kt < 4; kt++) {
            uint32_t r0, r1, r2, r3;
            uint32_t addr = KaU + ((uint32_t)((kt * 16 + a_row) * KV_STRIDE
                                              + warp * 32 + mt * 16 + a_col8)) * 2;
            ldsm4t(r0, r1, r2, r3, addr);
            afr[mt][kt][0] = r0; afr[mt][kt][1] = r2;
            afr[mt][kt][2] = r1; afr[mt][kt][3] = r3;
        }

    __half* Pout = g_P + (size_t)(bh * NC + c) * DKc * PCOLS;

    #pragma unroll
    for (int ntb = 0; ntb < 9; ntb++) {
        uint32_t bfr[4][4];
        #pragma unroll
        for (int kt = 0; kt < 4; kt++) {
            ldsm4t(bfr[kt][0], bfr[kt][1], bfr[kt][2], bfr[kt][3],
                   VaU + ((uint32_t)((kt * 16 + a_row) * TS_STRIDE + ntb * 16 + a_col8)) * 2);
        }
        #pragma unroll
        for (int mt = 0; mt < 2; mt++) {
            #pragma unroll
            for (int nh = 0; nh < 2; nh++) {
                if (ntb == 8 && nh == 1) continue;   // cols >=136 discarded
                float acc[4] = {0.0f, 0.0f, 0.0f, 0.0f};
                #pragma unroll
                for (int kt = 0; kt < 4; kt++)
                    mma_f16(acc, afr[mt][kt][0], afr[mt][kt][1], afr[mt][kt][2], afr[mt][kt][3],
                            bfr[kt][nh * 2], bfr[kt][nh * 2 + 1]);
                const int dk0 = warp * 32 + mt * 16 + lr;
                const int col = ntb * 16 + nh * 8 + 2 * lc;
                *(__half2*)(Pout + (size_t)dk0 * PCOLS + col) =
                    __floats2half2_rn(acc[0], acc[1]);
                *(__half2*)(Pout + (size_t)(dk0 + 8) * PCOLS + col) =
                    __floats2half2_rn(acc[2], acc[3]);
            }
        }
    }
}

// ============ kernel B: prefix scan T_{c+1} = g^64 (T_c + P_c), prefetched ============
// grid (17 col-slabs of 8, NBH), 128 threads (thread = dk row).
__global__ __launch_bounds__(128)
void scan_kernel()
{
    const int s  = blockIdx.x;
    const int bh = blockIdx.y;
    const int t  = threadIdx.x;
    const float g64 = exp2f(head_lg2(bh & 15) * 64.0f);

    const __half* P = g_P + (size_t)bh * NC * DKc * PCOLS;
    __half*       T = g_T + (size_t)bh * NC * DKc * PCOLS;
    const size_t offs = (size_t)t * PCOLS + s * 8;
    const size_t cstride = (size_t)DKc * PCOLS;

    // T_0 = 0
    {
        uint4 z = make_uint4(0, 0, 0, 0);
        *(uint4*)(T + offs) = z;
    }

    float acc[8] = {0, 0, 0, 0, 0, 0, 0, 0};
    uint4 nxt = *(const uint4*)(P + offs);   // chunk 0
    #pragma unroll 4
    for (int c = 0; c < NC - 1; c++) {
        uint4 cur = nxt;
        if (c + 1 < NC - 1) nxt = *(const uint4*)(P + (c + 1) * cstride + offs);
        const __half2* ph = reinterpret_cast<const __half2*>(&cur);
        #pragma unroll
        for (int e = 0; e < 4; e++) {
            float2 p = __half22float2(ph[e]);
            acc[2 * e]     = g64 * (acc[2 * e]     + p.x);
            acc[2 * e + 1] = g64 * (acc[2 * e + 1] + p.y);
        }
        uint4 o;
        ((uint32_t*)&o)[0] = h2bits(__floats2half2_rn(acc[0], acc[1]));
        ((uint32_t*)&o)[1] = h2bits(__floats2half2_rn(acc[2], acc[3]));
        ((uint32_t*)&o)[2] = h2bits(__floats2half2_rn(acc[4], acc[5]));
        ((uint32_t*)&o)[3] = h2bits(__floats2half2_rn(acc[6], acc[7]));
        *(uint4*)(T + (c + 1) * cstride + offs) = o;
    }
}

// ============ kernel C: output = intra(chunk) + g^{iloc} Q T_c ; denom ; RMS ============
// grid (NC, NBH), 128 threads.
__global__ __launch_bounds__(128)
void retnet_out_kernel(float* __restrict__ out)
{
    extern __shared__ __align__(16) char smraw[];
    __half* Ks = reinterpret_cast<__half*>(smraw);            // [64][136] (Q staged here first)
    __half* Vs = Ks + CH * KV_STRIDE;                         // [64][136]
    __half* Ts = Vs + CH * KV_STRIDE;                         // [128][152]
    const uint32_t KsU = (uint32_t)__cvta_generic_to_shared(Ks);
    const uint32_t VsU = (uint32_t)__cvta_generic_to_shared(Vs);
    const uint32_t TsU = (uint32_t)__cvta_generic_to_shared(Ts);

    const int tid  = threadIdx.x;
    const int lane = tid & 31;
    const int warp = tid >> 5;
    const int lr   = lane >> 2;
    const int lc   = lane & 3;
    const int l7 = lane & 7;
    const int g  = lane >> 3;
    const int a_row  = l7 + (g & 1) * 8;
    const int a_col8 = (g >> 1) * 8;
    const int kb_row  = l7 + (g >> 1) * 8;
    const int kb_col8 = (g & 1) * 8;

    const int c  = blockIdx.x;
    const int bh = blockIdx.y;
    const int b  = bh >> 4;
    const int h  = bh & 15;
    const int i0 = c * CH;

    const size_t base = (size_t)bh * Lc * DKc + (size_t)i0 * DKc;
    const __half* qh = g_qh + base;
    const __half* kh = g_kh + base;
    const __half* vh = g_vh + base;
    const __half* th = g_T + (size_t)(bh * NC + c) * DKc * PCOLS;

    const float lg2 = head_lg2(h);
    const int il0 = warp * 16 + lr;
    const int il1 = il0 + 8;
    const float R0 = exp2f(lg2 * (float)il0);
    const float R1 = exp2f(lg2 * (float)il1);

    // (1) stage Q (fp16) into Ks region, pull qa fragments
    #pragma unroll
    for (int t = 0; t < 8; t++) {
        int idx = tid + t * 128;
        int n   = idx >> 4;
        int ch  = idx & 15;
        CP_ASYNC16(KsU + (uint32_t)(n * KV_STRIDE + ch * 8) * 2, qh + n * DKc + ch * 8);
    }
    CP_COMMIT();
    CP_WAIT0();
    __syncthreads();
    uint32_t qa[8][4];
    #pragma unroll
    for (int kt = 0; kt < 8; kt++) {
        ldsm4(qa[kt][0], qa[kt][1], qa[kt][2], qa[kt][3],
              KsU + (uint32_t)((warp * 16 + a_row) * KV_STRIDE + kt * 16 + a_col8) * 2);
    }
    __syncthreads();

    // (2) stage K', V, T (one overlapped group)
    #pragma unroll
    for (int t = 0; t < 8; t++) {
        int idx = tid + t * 128;
        int n   = idx >> 4;
        int ch  = idx & 15;
        CP_ASYNC16(KsU + (uint32_t)(n * KV_STRIDE + ch * 8) * 2, kh + n * DKc + ch * 8);
        CP_ASYNC16(VsU + (uint32_t)(n * KV_STRIDE + ch * 8) * 2, vh + n * DKc + ch * 8);
    }
    #pragma unroll
    for (int t = 0; t < 17; t++) {
        int idx = tid + t * 128;
        int r   = idx / 17;
        int ch  = idx % 17;
        CP_ASYNC16(TsU + (uint32_t)(r * TS_STRIDE + ch * 8) * 2, th + (size_t)r * PCOLS + ch * 8);
    }
    CP_COMMIT();
    CP_WAIT0();
    __syncthreads();

    // (3) intra GEMM1: S = Q K'^T
    float scr[8][4];
    #pragma unroll
    for (int t = 0; t < 8; t++)
        #pragma unroll
        for (int e = 0; e < 4; e++) scr[t][e] = 0.0f;
    #pragma unroll
    for (int kt = 0; kt < 8; kt++) {
        #pragma unroll
        for (int nt = 0; nt < 4; nt++) {
            uint32_t b0, b1, b2, b3;
            ldsm4(b0, b1, b2, b3,
                  KsU + (uint32_t)((nt * 16 + kb_row) * KV_STRIDE + kt * 16 + kb_col8) * 2);
            mma_f16(scr[nt * 2],     qa[kt][0], qa[kt][1], qa[kt][2], qa[kt][3], b0, b1);
            mma_f16(scr[nt * 2 + 1], qa[kt][0], qa[kt][1], qa[kt][2], qa[kt][3], b2, b3);
        }
    }

    // (4) decay + causal mask + intra rowsum + fp16 repack
    float rs0 = 0.0f, rs1 = 0.0f;
    uint32_t sa[4][4];
    #pragma unroll
    for (int t = 0; t < 8; t++) {
        const int jb = t * 8 + 2 * lc;
        float v0 = scr[t][0] * R0;
        float v1 = scr[t][1] * R0;
        float v2 = scr[t][2] * R1;
        float v3 = scr[t][3] * R1;
        if (jb     > il0) v0 = 0.0f;
        if (jb + 1 > il0) v1 = 0.0f;
        if (jb     > il1) v2 = 0.0f;
        if (jb + 1 > il1) v3 = 0.0f;
        rs0 += v0 + v1;
        rs1 += v2 + v3;
        const int u  = t >> 1;
        const int hi = (t & 1) * 2;
        sa[u][hi]     = h2bits(__floats2half2_rn(v0, v1));
        sa[u][hi + 1] = h2bits(__floats2half2_rn(v2, v3));
    }

    // (5) inter GEMM: ocI = Q · T  (n = 136 incl z col 128)
    float ocI[18][4];
    #pragma unroll
    for (int t = 0; t < 18; t++)
        #pragma unroll
        for (int e = 0; e < 4; e++) ocI[t][e] = 0.0f;
    #pragma unroll
    for (int ntb = 0; ntb < 9; ntb++) {
        #pragma unroll
        for (int kt = 0; kt < 8; kt++) {
            uint32_t b0, b1, b2, b3;
            ldsm4t(b0, b1, b2, b3,
                   TsU + (uint32_t)((kt * 16 + a_row) * TS_STRIDE + ntb * 16 + a_col8) * 2);
            mma_f16(ocI[ntb * 2],     qa[kt][0], qa[kt][1], qa[kt][2], qa[kt][3], b0, b1);
            mma_f16(ocI[ntb * 2 + 1], qa[kt][0], qa[kt][1], qa[kt][2], qa[kt][3], b2, b3);
        }
    }
    #pragma unroll
    for (int t = 0; t < 18; t++) {
        ocI[t][0] *= R0; ocI[t][1] *= R0;
        ocI[t][2] *= R1; ocI[t][3] *= R1;
    }

    // (6) intra GEMM2 accumulates on top: O += S~ · V
    #pragma unroll
    for (int kt2 = 0; kt2 < 4; kt2++) {
        #pragma unroll
        for (int dt = 0; dt < 8; dt++) {
            uint32_t b0, b1, b2, b3;
            ldsm4t(b0, b1, b2, b3,
                   VsU + (uint32_t)((kt2 * 16 + a_row) * KV_STRIDE + dt * 16 + a_col8) * 2);
            mma_f16(ocI[dt * 2],     sa[kt2][0], sa[kt2][1], sa[kt2][2], sa[kt2][3], b0, b1);
            mma_f16(ocI[dt * 2 + 1], sa[kt2][0], sa[kt2][1], sa[kt2][2], sa[kt2][3], b2, b3);
        }
    }

    // (7) denominator (z col 128 lives in frag ntb=8 low half at 2lc==0)
    if (lc == 0) { rs0 += ocI[16][0]; rs1 += ocI[16][2]; }
    rs0 += __shfl_xor_sync(0xffffffffu, rs0, 1);
    rs0 += __shfl_xor_sync(0xffffffffu, rs0, 2);
    rs1 += __shfl_xor_sync(0xffffffffu, rs1, 1);
    rs1 += __shfl_xor_sync(0xffffffffu, rs1, 2);
    const float dn0 = 1.0f / fmaxf(fabsf(rs0), 1.0f);
    const float dn1 = 1.0f / fmaxf(fabsf(rs1), 1.0f);

    // (8) normalize + RMS + write
    float ssq0 = 0.0f, ssq1 = 0.0f;
    #pragma unroll
    for (int t = 0; t < 16; t++) {
        ocI[t][0] *= dn0; ocI[t][1] *= dn0;
        ocI[t][2] *= dn1; ocI[t][3] *= dn1;
        ssq0 += ocI[t][0] * ocI[t][0] + ocI[t][1] * ocI[t][1];
        ssq1 += ocI[t][2] * ocI[t][2] + ocI[t][3] * ocI[t][3];
    }
    ssq0 += __shfl_xor_sync(0xffffffffu, ssq0, 1);
    ssq0 += __shfl_xor_sync(0xffffffffu, ssq0, 2);
    ssq1 += __shfl_xor_sync(0xffffffffu, ssq1, 1);
    ssq1 += __shfl_xor_sync(0xffffffffu, ssq1, 2);
    const float sc0 = rsqrtf(ssq0 * (1.0f / 128.0f) + 1e-6f);
    const float sc1 = rsqrtf(ssq1 * (1.0f / 128.0f) + 1e-6f);

    float* po0 = out + (((size_t)b * Lc + (i0 + il0)) * Hc + h) * DKc;
    float* po1 = out + (((size_t)b * Lc + (i0 + il1)) * Hc + h) * DKc;
    #pragma unroll
    for (int t = 0; t < 16; t++) {
        const int d = t * 8 + 2 * lc;
        float2 w0, w1;
        w0.x = ocI[t][0] * sc0; w0.y = ocI[t][1] * sc0;
        w1.x = ocI[t][2] * sc1; w1.y = ocI[t][3] * sc1;
        *(float2*)(po0 + d) = w0;
        *(float2*)(po1 + d) = w1;
    }
}

extern "C" void kernel_launch(void* const* d_in, const int* in_sizes, int n_in,
                              void* d_out, int out_size)
{
    const float* q = (const float*)d_in[0];
    const float* k = (const float*)d_in[1];
    const float* v = (const float*)d_in[2];
    float* out = (float*)d_out;

    // A) fused cvt + chunk partials
    {
        const int smem = (CH * KV_STRIDE + CH * TS_STRIDE) * 2;
        cudaFuncSetAttribute(partial_kernel,
                             cudaFuncAttributeMaxDynamicSharedMemorySize, smem);
        dim3 grid(NC, NBH);
        partial_kernel<<<grid, 128, smem>>>(q, k, v);
    }
    // B) prefix scan
    {
        dim3 grid(17, NBH);
        scan_kernel<<<grid, 128>>>();
    }
    // C) fused output
    {
        const int smem = (2 * CH * KV_STRIDE + DKc * TS_STRIDE) * 2;
        cudaFuncSetAttribute(retnet_out_kernel,
                             cudaFuncAttributeMaxDynamicSharedMemorySize, smem);
        dim3 grid(NC, NBH);
        retnet_out_kernel<<<grid, 128, smem>>>(out);
    }
}

// round 16
// speedup vs baseline: 4.9898x; 1.0123x over previous
#include <cuda_runtime.h>
#include <cuda_fp16.h>
#include <cstdint>

// RetNet retention via exact chunked linear-attention form (R16).
//   A: fused cvt (K/V only) + partial  P_c = K'^T [V | 1]  (P fp16)
//   B: prefix scan T_{c+1} = g^64 (T_c + P_c)              (fp32 acc, fp16 store)
//   C: O = g^{iloc} Q T_c + intra-chunk  (Q read fp32 directly; denom via z col)
// B=2, H=16, L=2048, DK=DV=128, chunk C=64.
namespace {
constexpr int Lc  = 2048;
constexpr int Hc  = 16;
constexpr int Bc  = 2;
constexpr int DKc = 128;
constexpr int CH  = 64;
constexpr int NC  = Lc / CH;            // 32
constexpr int NBH = Bc * Hc;            // 32
constexpr int PCOLS = 136;              // 128 dv + z col + 7 pad
constexpr int KV_STRIDE = 136;
constexpr int TS_STRIDE = 152;

constexpr size_t KV_ELEMS = (size_t)NBH * Lc * DKc;          // 8388608
constexpr size_t PT_ELEMS = (size_t)NBH * NC * DKc * PCOLS;  // 17825792
}

__device__ __half g_kh[KV_ELEMS];   // K * gamma^{-(j mod 64)} fp16
__device__ __half g_vh[KV_ELEMS];   // V fp16
__device__ __half g_P[PT_ELEMS];    // chunk partials fp16
__device__ __half g_T[PT_ELEMS];    // prefix states fp16

__device__ __forceinline__ void ldsm4(uint32_t& r0, uint32_t& r1, uint32_t& r2, uint32_t& r3,
                                      uint32_t addr) {
    asm volatile("ldmatrix.sync.aligned.m8n8.x4.shared.b16 {%0,%1,%2,%3}, [%4];"
                 : "=r"(r0), "=r"(r1), "=r"(r2), "=r"(r3) : "r"(addr));
}
__device__ __forceinline__ void ldsm4t(uint32_t& r0, uint32_t& r1, uint32_t& r2, uint32_t& r3,
                                       uint32_t addr) {
    asm volatile("ldmatrix.sync.aligned.m8n8.x4.trans.shared.b16 {%0,%1,%2,%3}, [%4];"
                 : "=r"(r0), "=r"(r1), "=r"(r2), "=r"(r3) : "r"(addr));
}
__device__ __forceinline__ void mma_f16(float c[4],
                                        uint32_t a0, uint32_t a1, uint32_t a2, uint32_t a3,
                                        uint32_t b0, uint32_t b1) {
    asm volatile(
        "mma.sync.aligned.m16n8k16.row.col.f32.f16.f16.f32 "
        "{%0,%1,%2,%3}, {%4,%5,%6,%7}, {%8,%9}, {%0,%1,%2,%3};\n"
        : "+f"(c[0]), "+f"(c[1]), "+f"(c[2]), "+f"(c[3])
        : "r"(a0), "r"(a1), "r"(a2), "r"(a3), "r"(b0), "r"(b1));
}
__device__ __forceinline__ uint32_t h2bits(__half2 h) {
    return *reinterpret_cast<uint32_t*>(&h);
}

#define CP_ASYNC16(dst, src) \
    asm volatile("cp.async.cg.shared.global [%0], [%1], 16;" :: "r"(dst), "l"(src) : "memory")
#define CP_COMMIT() asm volatile("cp.async.commit_group;" ::: "memory")
#define CP_WAIT0()  asm volatile("cp.async.wait_group 0;"  ::: "memory")

__device__ __forceinline__ float head_lg2(int h) {
    return log1pf(-exp2f(-5.0f - (float)h)) * 1.4426950408889634f;
}

// ============ kernel A: fused cvt (K/V fp32->fp16) + chunk partial P ============
// grid (NC, NBH), 128 threads.
__global__ __launch_bounds__(128, 5)
void partial_kernel(const float* __restrict__ k,
                    const float* __restrict__ v)
{
    extern __shared__ __align__(16) char smraw[];
    __half* Ka = reinterpret_cast<__half*>(smraw);            // [64][136]
    __half* Va = Ka + CH * KV_STRIDE;                         // [64][152] augmented
    const uint32_t KaU = (uint32_t)__cvta_generic_to_shared(Ka);
    const uint32_t VaU = (uint32_t)__cvta_generic_to_shared(Va);

    const int tid  = threadIdx.x;
    const int lane = tid & 31;
    const int warp = tid >> 5;
    const int lr   = lane >> 2;
    const int lc   = lane & 3;
    const int l7 = lane & 7;
    const int g  = lane >> 3;
    const int a_row  = l7 + (g & 1) * 8;
    const int a_col8 = (g >> 1) * 8;

    const int c  = blockIdx.x;
    const int bh = blockIdx.y;
    const int h  = bh & 15;
    const int j0 = c * CH;
    const float lg2 = head_lg2(h);

    const size_t base = (size_t)bh * Lc * DKc + (size_t)j0 * DKc;
    const float* ks = k + base;
    const float* vs = v + base;
    __half* ko = g_kh + base;
    __half* vo = g_vh + base;

    // convert: K (scaled) -> smem + gmem ; V -> smem + gmem
    #pragma unroll
    for (int t = 0; t < 16; t++) {
        int idx = tid + t * 128;
        int r   = idx >> 5;       // 0..63
        int c4  = idx & 31;
        const float cj = exp2f(-lg2 * (float)r);
        float4 gk = *(const float4*)(ks + (size_t)r * DKc + c4 * 4);
        uint2 uk;
        uk.x = h2bits(__floats2half2_rn(gk.x * cj, gk.y * cj));
        uk.y = h2bits(__floats2half2_rn(gk.z * cj, gk.w * cj));
        *(uint2*)(Ka + r * KV_STRIDE + c4 * 4) = uk;
        *(uint2*)(ko + (size_t)r * DKc + c4 * 4) = uk;

        float4 gv = *(const float4*)(vs + (size_t)r * DKc + c4 * 4);
        uint2 uv;
        uv.x = h2bits(__floats2half2_rn(gv.x, gv.y));
        uv.y = h2bits(__floats2half2_rn(gv.z, gv.w));
        *(uint2*)(Va + r * TS_STRIDE + c4 * 4) = uv;
        *(uint2*)(vo + (size_t)r * DKc + c4 * 4) = uv;
    }
    // augmentation: col 128 = 1.0, cols 129..151 = 0
    if (tid < 64) {
        __half* row = Va + tid * TS_STRIDE;
        row[128] = __float2half_rn(1.0f);
        #pragma unroll
        for (int cc = 129; cc < 152; cc++) row[cc] = __float2half_rn(0.0f);
    }
    __syncthreads();

    // A-fragments of K'^T via ldsm trans; mapping a0=r0, a1=r2, a2=r1, a3=r3.
    uint32_t afr[2][4][4];
    #pragma unroll
    for (int mt = 0; mt < 2; mt++)
        #pragma unroll
        for (int kt = 0; kt < 4; kt++) {
            uint32_t r0, r1, r2, r3;
            uint32_t addr = KaU + ((uint32_t)((kt * 16 + a_row) * KV_STRIDE
                                              + warp * 32 + mt * 16 + a_col8)) * 2;
            ldsm4t(r0, r1, r2, r3, addr);
            afr[mt][kt][0] = r0; afr[mt][kt][1] = r2;
            afr[mt][kt][2] = r1; afr[mt][kt][3] = r3;
        }

    __half* Pout = g_P + (size_t)(bh * NC + c) * DKc * PCOLS;

    #pragma unroll
    for (int ntb = 0; ntb < 9; ntb++) {
        uint32_t bfr[4][4];
        #pragma unroll
        for (int kt = 0; kt < 4; kt++) {
            ldsm4t(bfr[kt][0], bfr[kt][1], bfr[kt][2], bfr[kt][3],
                   VaU + ((uint32_t)((kt * 16 + a_row) * TS_STRIDE + ntb * 16 + a_col8)) * 2);
        }
        #pragma unroll
        for (int mt = 0; mt < 2; mt++) {
            #pragma unroll
            for (int nh = 0; nh < 2; nh++) {
                if (ntb == 8 && nh == 1) continue;   // cols >=136 discarded
                float acc[4] = {0.0f, 0.0f, 0.0f, 0.0f};
                #pragma unroll
                for (int kt = 0; kt < 4; kt++)
                    mma_f16(acc, afr[mt][kt][0], afr[mt][kt][1], afr[mt][kt][2], afr[mt][kt][3],
                            bfr[kt][nh * 2], bfr[kt][nh * 2 + 1]);
                const int dk0 = warp * 32 + mt * 16 + lr;
                const int col = ntb * 16 + nh * 8 + 2 * lc;
                *(__half2*)(Pout + (size_t)dk0 * PCOLS + col) =
                    __floats2half2_rn(acc[0], acc[1]);
                *(__half2*)(Pout + (size_t)(dk0 + 8) * PCOLS + col) =
                    __floats2half2_rn(acc[2], acc[3]);
            }
        }
    }
}

// ============ kernel B: prefix scan T_{c+1} = g^64 (T_c + P_c), prefetched ============
// grid (17 col-slabs of 8, NBH), 128 threads (thread = dk row).
__global__ __launch_bounds__(128)
void scan_kernel()
{
    const int s  = blockIdx.x;
    const int bh = blockIdx.y;
    const int t  = threadIdx.x;
    const float g64 = exp2f(head_lg2(bh & 15) * 64.0f);

    const __half* P = g_P + (size_t)bh * NC * DKc * PCOLS;
    __half*       T = g_T + (size_t)bh * NC * DKc * PCOLS;
    const size_t offs = (size_t)t * PCOLS + s * 8;
    const size_t cstride = (size_t)DKc * PCOLS;

    // T_0 = 0
    {
        uint4 z = make_uint4(0, 0, 0, 0);
        *(uint4*)(T + offs) = z;
    }

    float acc[8] = {0, 0, 0, 0, 0, 0, 0, 0};
    uint4 nxt = *(const uint4*)(P + offs);   // chunk 0
    #pragma unroll 4
    for (int c = 0; c < NC - 1; c++) {
        uint4 cur = nxt;
        if (c + 1 < NC - 1) nxt = *(const uint4*)(P + (c + 1) * cstride + offs);
        const __half2* ph = reinterpret_cast<const __half2*>(&cur);
        #pragma unroll
        for (int e = 0; e < 4; e++) {
            float2 p = __half22float2(ph[e]);
            acc[2 * e]     = g64 * (acc[2 * e]     + p.x);
            acc[2 * e + 1] = g64 * (acc[2 * e + 1] + p.y);
        }
        uint4 o;
        ((uint32_t*)&o)[0] = h2bits(__floats2half2_rn(acc[0], acc[1]));
        ((uint32_t*)&o)[1] = h2bits(__floats2half2_rn(acc[2], acc[3]));
        ((uint32_t*)&o)[2] = h2bits(__floats2half2_rn(acc[4], acc[5]));
        ((uint32_t*)&o)[3] = h2bits(__floats2half2_rn(acc[6], acc[7]));
        *(uint4*)(T + (c + 1) * cstride + offs) = o;
    }
}

// ============ kernel C: output = intra(chunk) + g^{iloc} Q T_c ; denom ; RMS ============
// grid (NC, NBH), 128 threads, 3 CTAs/SM.
__global__ __launch_bounds__(128, 3)
void retnet_out_kernel(const float* __restrict__ q, float* __restrict__ out)
{
    extern __shared__ __align__(16) char smraw[];
    __half* Ks = reinterpret_cast<__half*>(smraw);            // [64][136]
    __half* Vs = Ks + CH * KV_STRIDE;                         // [64][136]
    __half* Ts = Vs + CH * KV_STRIDE;                         // [128][152] (Q staged here first)
    const uint32_t KsU = (uint32_t)__cvta_generic_to_shared(Ks);
    const uint32_t VsU = (uint32_t)__cvta_generic_to_shared(Vs);
    const uint32_t TsU = (uint32_t)__cvta_generic_to_shared(Ts);

    const int tid  = threadIdx.x;
    const int lane = tid & 31;
    const int warp = tid >> 5;
    const int lr   = lane >> 2;
    const int lc   = lane & 3;
    const int l7 = lane & 7;
    const int g  = lane >> 3;
    const int a_row  = l7 + (g & 1) * 8;
    const int a_col8 = (g >> 1) * 8;
    const int kb_row  = l7 + (g >> 1) * 8;
    const int kb_col8 = (g & 1) * 8;

    const int c  = blockIdx.x;
    const int bh = blockIdx.y;
    const int b  = bh >> 4;
    const int h  = bh & 15;
    const int i0 = c * CH;

    const size_t base = (size_t)bh * Lc * DKc + (size_t)i0 * DKc;
    const float*  qb = q    + base;
    const __half* kh = g_kh + base;
    const __half* vh = g_vh + base;
    const __half* th = g_T + (size_t)(bh * NC + c) * DKc * PCOLS;

    const float lg2 = head_lg2(h);
    const int il0 = warp * 16 + lr;
    const int il1 = il0 + 8;
    const float R0 = exp2f(lg2 * (float)il0);
    const float R1 = exp2f(lg2 * (float)il1);

    // (1) start async K'/V loads immediately
    #pragma unroll
    for (int t = 0; t < 8; t++) {
        int idx = tid + t * 128;
        int n   = idx >> 4;
        int ch  = idx & 15;
        CP_ASYNC16(KsU + (uint32_t)(n * KV_STRIDE + ch * 8) * 2, kh + n * DKc + ch * 8);
        CP_ASYNC16(VsU + (uint32_t)(n * KV_STRIDE + ch * 8) * 2, vh + n * DKc + ch * 8);
    }
    CP_COMMIT();

    // (2) stage Q fp32->fp16 into Ts region, pull qa fragments
    #pragma unroll
    for (int t = 0; t < 16; t++) {
        int idx = tid + t * 128;
        int r   = idx >> 5;       // 0..63
        int c4  = idx & 31;
        float4 gld = *(const float4*)(qb + (size_t)r * DKc + c4 * 4);
        uint2 u;
        u.x = h2bits(__floats2half2_rn(gld.x, gld.y));
        u.y = h2bits(__floats2half2_rn(gld.z, gld.w));
        *(uint2*)(Ts + r * TS_STRIDE + c4 * 4) = u;
    }
    __syncthreads();
    uint32_t qa[8][4];
    #pragma unroll
    for (int kt = 0; kt < 8; kt++) {
        ldsm4(qa[kt][0], qa[kt][1], qa[kt][2], qa[kt][3],
              TsU + (uint32_t)((warp * 16 + a_row) * TS_STRIDE + kt * 16 + a_col8) * 2);
    }
    __syncthreads();

    // (3) stage T (overwrites Q staging region)
    #pragma unroll
    for (int t = 0; t < 17; t++) {
        int idx = tid + t * 128;
        int r   = idx / 17;
        int ch  = idx % 17;
        CP_ASYNC16(TsU + (uint32_t)(r * TS_STRIDE + ch * 8) * 2, th + (size_t)r * PCOLS + ch * 8);
    }
    CP_COMMIT();
    CP_WAIT0();
    __syncthreads();

    // (4) intra GEMM1: S = Q K'^T
    float scr[8][4];
    #pragma unroll
    for (int t = 0; t < 8; t++)
        #pragma unroll
        for (int e = 0; e < 4; e++) scr[t][e] = 0.0f;
    #pragma unroll
    for (int kt = 0; kt < 8; kt++) {
        #pragma unroll
        for (int nt = 0; nt < 4; nt++) {
            uint32_t b0, b1, b2, b3;
            ldsm4(b0, b1, b2, b3,
                  KsU + (uint32_t)((nt * 16 + kb_row) * KV_STRIDE + kt * 16 + kb_col8) * 2);
            mma_f16(scr[nt * 2],     qa[kt][0], qa[kt][1], qa[kt][2], qa[kt][3], b0, b1);
            mma_f16(scr[nt * 2 + 1], qa[kt][0], qa[kt][1], qa[kt][2], qa[kt][3], b2, b3);
        }
    }

    // (5) decay + causal mask + intra rowsum + fp16 repack
    float rs0 = 0.0f, rs1 = 0.0f;
    uint32_t sa[4][4];
    #pragma unroll
    for (int t = 0; t < 8; t++) {
        const int jb = t * 8 + 2 * lc;
        float v0 = scr[t][0] * R0;
        float v1 = scr[t][1] * R0;
        float v2 = scr[t][2] * R1;
        float v3 = scr[t][3] * R1;
        if (jb     > il0) v0 = 0.0f;
        if (jb + 1 > il0) v1 = 0.0f;
        if (jb     > il1) v2 = 0.0f;
        if (jb + 1 > il1) v3 = 0.0f;
        rs0 += v0 + v1;
        rs1 += v2 + v3;
        const int u  = t >> 1;
        const int hi = (t & 1) * 2;
        sa[u][hi]     = h2bits(__floats2half2_rn(v0, v1));
        sa[u][hi + 1] = h2bits(__floats2half2_rn(v2, v3));
    }

    // (6) inter GEMM: ocI = Q · T  (n = 136 incl z col 128)
    float ocI[18][4];
    #pragma unroll
    for (int t = 0; t < 18; t++)
        #pragma unroll
        for (int e = 0; e < 4; e++) ocI[t][e] = 0.0f;
    #pragma unroll
    for (int ntb = 0; ntb < 9; ntb++) {
        #pragma unroll
        for (int kt = 0; kt < 8; kt++) {
            uint32_t b0, b1, b2, b3;
            ldsm4t(b0, b1, b2, b3,
                   TsU + (uint32_t)((kt * 16 + a_row) * TS_STRIDE + ntb * 16 + a_col8) * 2);
            mma_f16(ocI[ntb * 2],     qa[kt][0], qa[kt][1], qa[kt][2], qa[kt][3], b0, b1);
            mma_f16(ocI[ntb * 2 + 1], qa[kt][0], qa[kt][1], qa[kt][2], qa[kt][3], b2, b3);
        }
    }
    #pragma unroll
    for (int t = 0; t < 18; t++) {
        ocI[t][0] *= R0; ocI[t][1] *= R0;
        ocI[t][2] *= R1; ocI[t][3] *= R1;
    }

    // (7) intra GEMM2 accumulates on top: O += S~ · V
    #pragma unroll
    for (int kt2 = 0; kt2 < 4; kt2++) {
        #pragma unroll
        for (int dt = 0; dt < 8; dt++) {
            uint32_t b0, b1, b2, b3;
            ldsm4t(b0, b1, b2, b3,
                   VsU + (uint32_t)((kt2 * 16 + a_row) * KV_STRIDE + dt * 16 + a_col8) * 2);
            mma_f16(ocI[dt * 2],     sa[kt2][0], sa[kt2][1], sa[kt2][2], sa[kt2][3], b0, b1);
            mma_f16(ocI[dt * 2 + 1], sa[kt2][0], sa[kt2][1], sa[kt2][2], sa[kt2][3], b2, b3);
        }
    }

    // (8) denominator (z col 128 lives in frag ntb=8 low half at 2lc==0)
    if (lc == 0) { rs0 += ocI[16][0]; rs1 += ocI[16][2]; }
    rs0 += __shfl_xor_sync(0xffffffffu, rs0, 1);
    rs0 += __shfl_xor_sync(0xffffffffu, rs0, 2);
    rs1 += __shfl_xor_sync(0xffffffffu, rs1, 1);
    rs1 += __shfl_xor_sync(0xffffffffu, rs1, 2);
    const float dn0 = 1.0f / fmaxf(fabsf(rs0), 1.0f);
    const float dn1 = 1.0f / fmaxf(fabsf(rs1), 1.0f);

    // (9) normalize + RMS + write
    float ssq0 = 0.0f, ssq1 = 0.0f;
    #pragma unroll
    for (int t = 0; t < 16; t++) {
        ocI[t][0] *= dn0; ocI[t][1] *= dn0;
        ocI[t][2] *= dn1; ocI[t][3] *= dn1;
        ssq0 += ocI[t][0] * ocI[t][0] + ocI[t][1] * ocI[t][1];
        ssq1 += ocI[t][2] * ocI[t][2] + ocI[t][3] * ocI[t][3];
    }
    ssq0 += __shfl_xor_sync(0xffffffffu, ssq0, 1);
    ssq0 += __shfl_xor_sync(0xffffffffu, ssq0, 2);
    ssq1 += __shfl_xor_sync(0xffffffffu, ssq1, 1);
    ssq1 += __shfl_xor_sync(0xffffffffu, ssq1, 2);
    const float sc0 = rsqrtf(ssq0 * (1.0f / 128.0f) + 1e-6f);
    const float sc1 = rsqrtf(ssq1 * (1.0f / 128.0f) + 1e-6f);

    float* po0 = out + (((size_t)b * Lc + (i0 + il0)) * Hc + h) * DKc;
    float* po1 = out + (((size_t)b * Lc + (i0 + il1)) * Hc + h) * DKc;
    #pragma unroll
    for (int t = 0; t < 16; t++) {
        const int d = t * 8 + 2 * lc;
        float2 w0, w1;
        w0.x = ocI[t][0] * sc0; w0.y = ocI[t][1] * sc0;
        w1.x = ocI[t][2] * sc1; w1.y = ocI[t][3] * sc1;
        *(float2*)(po0 + d) = w0;
        *(float2*)(po1 + d) = w1;
    }
}

extern "C" void kernel_launch(void* const* d_in, const int* in_sizes, int n_in,
                              void* d_out, int out_size)
{
    const float* q = (const float*)d_in[0];
    const float* k = (const float*)d_in[1];
    const float* v = (const float*)d_in[2];
    float* out = (float*)d_out;

    // A) fused cvt + chunk partials
    {
        const int smem = (CH * KV_STRIDE + CH * TS_STRIDE) * 2;
        cudaFuncSetAttribute(partial_kernel,
                             cudaFuncAttributeMaxDynamicSharedMemorySize, smem);
        dim3 grid(NC, NBH);
        partial_kernel<<<grid, 128, smem>>>(k, v);
    }
    // B) prefix scan
    {
        dim3 grid(17, NBH);
        scan_kernel<<<grid, 128>>>();
    }
    // C) fused output
    {
        const int smem = (2 * CH * KV_STRIDE + DKc * TS_STRIDE) * 2;
        cudaFuncSetAttribute(retnet_out_kernel,
                             cudaFuncAttributeMaxDynamicSharedMemorySize, smem);
        dim3 grid(NC, NBH);
        retnet_out_kernel<<<grid, 128, smem>>>(q, out);
    }
}